// round 6
// baseline (speedup 1.0000x reference)
#include <cuda_runtime.h>
#include <cuda_bf16.h>
#include <cuda_fp16.h>
#include <math.h>
#include <stdint.h>

// Problem constants
#define Bb_ 2
#define Ss_ 2048
#define Dd_ 2048
#define Hh_ 16
#define HKV_ 2
#define HD_ 128
#define MROWS (Bb_ * Ss_)          // 4096
#define NKV (HKV_ * HD_)           // 256

// Scratch (allocation-free: __device__ globals)
__device__ float g_Q[(size_t)MROWS * Dd_];
__device__ float g_K[(size_t)MROWS * NKV];
__device__ float g_V[(size_t)MROWS * NKV];
__device__ float g_O[(size_t)MROWS * Dd_];
// bf16 split buffers for GEMM
__device__ __nv_bfloat16 g_Ah[(size_t)MROWS * Dd_];
__device__ __nv_bfloat16 g_Al[(size_t)MROWS * Dd_];
__device__ __nv_bfloat16 g_Bh[(size_t)Dd_ * Dd_];
__device__ __nv_bfloat16 g_Bl[(size_t)Dd_ * Dd_];
// fp16 buffers for attention
__device__ __half g_Qh[(size_t)MROWS * Dd_];
__device__ __half g_Kh[(size_t)MROWS * NKV];
__device__ __half g_Vh[(size_t)MROWS * NKV];

// ---------------------------------------------------------------------------
// Helpers
// ---------------------------------------------------------------------------
static __device__ __forceinline__ uint32_t smem_u32(const void* p) {
    uint32_t r;
    asm("{ .reg .u64 t; cvta.to.shared.u64 t, %1; cvt.u32.u64 %0, t; }"
        : "=r"(r) : "l"(p));
    return r;
}

static __device__ __forceinline__ void mma16816(float* c, const uint32_t* a,
                                                const uint32_t* b) {
    asm volatile(
        "mma.sync.aligned.m16n8k16.row.col.f32.bf16.bf16.f32 "
        "{%0,%1,%2,%3}, {%4,%5,%6,%7}, {%8,%9}, {%0,%1,%2,%3};"
        : "+f"(c[0]), "+f"(c[1]), "+f"(c[2]), "+f"(c[3])
        : "r"(a[0]), "r"(a[1]), "r"(a[2]), "r"(a[3]), "r"(b[0]), "r"(b[1]));
}

static __device__ __forceinline__ void mma16816h(float* c, const uint32_t* a,
                                                 const uint32_t* b) {
    asm volatile(
        "mma.sync.aligned.m16n8k16.row.col.f32.f16.f16.f32 "
        "{%0,%1,%2,%3}, {%4,%5,%6,%7}, {%8,%9}, {%0,%1,%2,%3};"
        : "+f"(c[0]), "+f"(c[1]), "+f"(c[2]), "+f"(c[3])
        : "r"(a[0]), "r"(a[1]), "r"(a[2]), "r"(a[3]), "r"(b[0]), "r"(b[1]));
}

static __device__ __forceinline__ void ldsm_x4(uint32_t* r, uint32_t addr) {
    asm volatile("ldmatrix.sync.aligned.m8n8.x4.shared.b16 {%0,%1,%2,%3}, [%4];"
                 : "=r"(r[0]), "=r"(r[1]), "=r"(r[2]), "=r"(r[3]) : "r"(addr));
}

static __device__ __forceinline__ void ldsm_x4_t(uint32_t* r, uint32_t addr) {
    asm volatile("ldmatrix.sync.aligned.m8n8.x4.trans.shared.b16 {%0,%1,%2,%3}, [%4];"
                 : "=r"(r[0]), "=r"(r[1]), "=r"(r[2]), "=r"(r[3]) : "r"(addr));
}

static __device__ __forceinline__ void ldsm_x2_t(uint32_t* r, uint32_t addr) {
    asm volatile("ldmatrix.sync.aligned.m8n8.x2.trans.shared.b16 {%0,%1}, [%2];"
                 : "=r"(r[0]), "=r"(r[1]) : "r"(addr));
}

static __device__ __forceinline__ float ex2f(float x) {
    float y;
    asm("ex2.approx.f32 %0, %1;" : "=f"(y) : "f"(x));
    return y;
}

static __device__ __forceinline__ uint32_t packh2(float a, float b) {
    __half2 h = __floats2half2_rn(a, b);
    return *reinterpret_cast<uint32_t*>(&h);
}

// Split a pair of floats into packed bf16x2 hi + lo residual
static __device__ __forceinline__ void split2(float a, float b,
                                              uint32_t& hi, uint32_t& lo) {
    __nv_bfloat162 h = __floats2bfloat162_rn(a, b);
    float ra = a - __bfloat162float(h.x);
    float rb = b - __bfloat162float(h.y);
    __nv_bfloat162 l = __floats2bfloat162_rn(ra, rb);
    hi = *reinterpret_cast<uint32_t*>(&h);
    lo = *reinterpret_cast<uint32_t*>(&l);
}

// fp32 -> bf16 hi/lo split
__global__ void convert_split_k(const float* __restrict__ in,
                                __nv_bfloat16* __restrict__ hi,
                                __nv_bfloat16* __restrict__ lo, int n)
{
    int i = (blockIdx.x * blockDim.x + threadIdx.x) * 4;
    if (i >= n) return;
    float4 v = *(const float4*)(in + i);
    uint32_t h0, l0, h1, l1;
    split2(v.x, v.y, h0, l0);
    split2(v.z, v.w, h1, l1);
    *(uint2*)(hi + i) = make_uint2(h0, h1);
    *(uint2*)(lo + i) = make_uint2(l0, l1);
}

// fp32 -> fp16 with multiplier
__global__ void convert_half_k(const float* __restrict__ in,
                               __half* __restrict__ out, int n, float mult)
{
    int i = (blockIdx.x * blockDim.x + threadIdx.x) * 8;
    if (i >= n) return;
    float4 a = *(const float4*)(in + i);
    float4 b = *(const float4*)(in + i + 4);
    uint4 o;
    o.x = packh2(a.x * mult, a.y * mult);
    o.y = packh2(a.z * mult, a.w * mult);
    o.z = packh2(b.x * mult, b.y * mult);
    o.w = packh2(b.z * mult, b.w * mult);
    *(uint4*)(out + i) = o;
}

// ---------------------------------------------------------------------------
// bf16x3 tensor-core GEMM (validated R4)
// ---------------------------------------------------------------------------
#define SA_STRIDE 72
#define SB_STRIDE 136
#define SA_SZ (128 * SA_STRIDE)
#define SB_SZ (64 * SB_STRIDE)
#define GEMM_SMEM_BYTES ((2 * SA_SZ + 2 * SB_SZ) * 2)

__global__ __launch_bounds__(256, 2) void gemm_tc(const __nv_bfloat16* __restrict__ Ah,
                                                  const __nv_bfloat16* __restrict__ Al,
                                                  const __nv_bfloat16* __restrict__ Bh,
                                                  const __nv_bfloat16* __restrict__ Bl,
                                                  float* __restrict__ C,
                                                  int M, int N, int K)
{
    extern __shared__ __nv_bfloat16 smb[];
    __nv_bfloat16* sAh = smb;
    __nv_bfloat16* sAl = sAh + SA_SZ;
    __nv_bfloat16* sBh = sAl + SA_SZ;
    __nv_bfloat16* sBl = sBh + SB_SZ;

    const int t    = threadIdx.x;
    const int lane = t & 31;
    const int wid  = t >> 5;
    const int wm   = wid & 1;
    const int wn   = wid >> 1;
    const int n0   = blockIdx.x * 128;
    const int m0   = blockIdx.y * 128;

    float acc[4][4][4];
#pragma unroll
    for (int i = 0; i < 4; ++i)
#pragma unroll
        for (int j = 0; j < 4; ++j)
#pragma unroll
            for (int k = 0; k < 4; ++k) acc[i][j][k] = 0.0f;

    const uint32_t A_LO = SA_SZ * 2;
    const uint32_t B_LO = SB_SZ * 2;
    const uint32_t a_addr = smem_u32(sAh) +
        (uint32_t)(((lane & 7) + ((lane >> 3) & 1) * 8 + wm * 64) * (SA_STRIDE * 2)) +
        (uint32_t)(((lane >> 4) & 1) * 16);
    const uint32_t b_addr = smem_u32(sBh) +
        (uint32_t)(((lane & 7) + ((lane >> 3) & 1) * 8) * (SB_STRIDE * 2)) +
        (uint32_t)(wn * 64);

    const int nch = K >> 6;
    for (int c = 0; c < nch; ++c) {
        const int k0 = c << 6;
        __syncthreads();
        {
            const int r  = t >> 4;
            const int c4 = (t & 15) * 4;
            const size_t gA = (size_t)(m0 + r) * K + k0 + c4;
#pragma unroll
            for (int p = 0; p < 8; ++p) {
                const size_t g = gA + (size_t)(16 * p) * K;
                const int s = (r + 16 * p) * SA_STRIDE + c4;
                *(uint2*)&sAh[s] = *(const uint2*)(Ah + g);
                *(uint2*)&sAl[s] = *(const uint2*)(Al + g);
            }
        }
        {
            const int kr = t >> 4;
            const int c8 = (t & 15) * 8;
#pragma unroll
            for (int i = 0; i < 4; ++i) {
                const size_t g = (size_t)(k0 + kr + 16 * i) * N + n0 + c8;
                const int s = (kr + 16 * i) * SB_STRIDE + c8;
                *(uint4*)&sBh[s] = *(const uint4*)(Bh + g);
                *(uint4*)&sBl[s] = *(const uint4*)(Bl + g);
            }
        }
        __syncthreads();

#pragma unroll
        for (int k16 = 0; k16 < 4; ++k16) {
            uint32_t bh[4][2], bl[4][2], af[4][4];
            const uint32_t bko = (uint32_t)(k16 * 16 * SB_STRIDE * 2);
#pragma unroll
            for (int nt = 0; nt < 4; ++nt) {
                ldsm_x2_t(bh[nt], b_addr + nt * 16 + bko);
                ldsm_x2_t(bl[nt], b_addr + B_LO + nt * 16 + bko);
            }
            const uint32_t ako = (uint32_t)(k16 * 32);
#pragma unroll
            for (int mt = 0; mt < 4; ++mt)
                ldsm_x4(af[mt], a_addr + mt * (16 * SA_STRIDE * 2) + ako);
#pragma unroll
            for (int mt = 0; mt < 4; ++mt)
#pragma unroll
                for (int nt = 0; nt < 4; ++nt) {
                    mma16816(acc[mt][nt], af[mt], bh[nt]);
                    mma16816(acc[mt][nt], af[mt], bl[nt]);
                }
#pragma unroll
            for (int mt = 0; mt < 4; ++mt)
                ldsm_x4(af[mt], a_addr + A_LO + mt * (16 * SA_STRIDE * 2) + ako);
#pragma unroll
            for (int mt = 0; mt < 4; ++mt)
#pragma unroll
                for (int nt = 0; nt < 4; ++nt)
                    mma16816(acc[mt][nt], af[mt], bh[nt]);
        }
    }

    const int g   = lane >> 2;
    const int tid = lane & 3;
#pragma unroll
    for (int mt = 0; mt < 4; ++mt) {
        const int row = m0 + wm * 64 + mt * 16 + g;
#pragma unroll
        for (int nt = 0; nt < 4; ++nt) {
            const int col = n0 + wn * 32 + nt * 8 + tid * 2;
            *(float2*)(C + (size_t)row * N + col) =
                make_float2(acc[mt][nt][0], acc[mt][nt][1]);
            *(float2*)(C + (size_t)(row + 8) * N + col) =
                make_float2(acc[mt][nt][2], acc[mt][nt][3]);
        }
    }
}

// ---------------------------------------------------------------------------
// RoPE (unchanged, validated)
// ---------------------------------------------------------------------------
__global__ void rope_kernel(float* __restrict__ buf, int nh, int total)
{
    int idx = blockIdx.x * blockDim.x + threadIdx.x;
    if (idx >= total) return;
    int i    = idx & 63;
    int hh   = (idx >> 6) % nh;
    int srow = idx / (64 * nh);
    int pos  = srow & (Ss_ - 1);

    float inv = (float)exp(-(double)i * (log(10000.0) / 64.0));
    float ang = (float)pos * inv;
    float sn, cs;
    sincosf(ang, &sn, &cs);

    size_t base = (size_t)srow * (nh * HD_) + (size_t)hh * HD_ + i;
    float x1 = buf[base];
    float x2 = buf[base + 64];
    buf[base]      = x1 * cs - x2 * sn;
    buf[base + 64] = x2 * cs + x1 * sn;
}

// ---------------------------------------------------------------------------
// Tensor-core causal flash attention (fp16 mma, fp32 accum, exp2 softmax).
// Grid (S/128, H, B), 256 threads = 8 warps x 16 q-rows. BK=64.
// SMEM (half, stride 136): Qs[128], Ks[64], Vs[64]  -> conflict-free ldmatrix.
// Q is pre-scaled by (1/sqrt(128))*log2(e); softmax in base-2 domain.
// ---------------------------------------------------------------------------
#define FA_BQ 128
#define FA_BK 64
#define FA_STR 136
#define FA_SMEM ((FA_BQ + 2 * FA_BK) * FA_STR * 2)

__global__ __launch_bounds__(256) void flash_tc(const __half* __restrict__ Qh,
                                                const __half* __restrict__ Kh,
                                                const __half* __restrict__ Vh,
                                                float* __restrict__ O)
{
    extern __shared__ __half sh[];
    __half* Qs = sh;                         // [128][136]
    __half* Ks = Qs + FA_BQ * FA_STR;        // [64][136]
    __half* Vs = Ks + FA_BK * FA_STR;        // [64][136]

    const int qb = blockIdx.x, h = blockIdx.y, b = blockIdx.z;
    const int kvh = h % HKV_;
    const int t = threadIdx.x, lane = t & 31, w = t >> 5;
    const int q0 = qb * FA_BQ;
    const int wq0 = w * 16;

    // Load Q tile once
    {
#pragma unroll
        for (int i = 0; i < 8; ++i) {
            int linear = t + 256 * i;
            int row = linear >> 4;
            int c8 = (linear & 15) * 8;
            *(uint4*)&Qs[row * FA_STR + c8] =
                *(const uint4*)(Qh + (size_t)(b * Ss_ + q0 + row) * Dd_ + h * HD_ + c8);
        }
    }

    float oacc[16][4];
#pragma unroll
    for (int i = 0; i < 16; ++i)
#pragma unroll
        for (int j = 0; j < 4; ++j) oacc[i][j] = 0.0f;
    float mrow[2] = {-INFINITY, -INFINITY};
    float lrow[2] = {0.0f, 0.0f};

    const uint32_t qa = smem_u32(Qs) +
        (uint32_t)((wq0 + (lane & 15)) * (FA_STR * 2)) +
        (uint32_t)(((lane >> 4) & 1) * 16);
    // K (B operand, col-major natural): rows = kv pos, non-trans
    const uint32_t ka = smem_u32(Ks) +
        (uint32_t)(((lane & 7) + ((lane >> 4) & 1) * 8) * (FA_STR * 2)) +
        (uint32_t)(((lane >> 3) & 1) * 16);
    // V (B operand, row-major [kv][d]): trans
    const uint32_t va = smem_u32(Vs) +
        (uint32_t)(((lane & 7) + ((lane >> 3) & 1) * 8) * (FA_STR * 2)) +
        (uint32_t)(((lane >> 4) & 1) * 16);

    const int nkb = (q0 + FA_BQ) / FA_BK;
    for (int kb = 0; kb < nkb; ++kb) {
        const int k0 = kb * FA_BK;
        __syncthreads();
        // Load K and V tiles
        {
#pragma unroll
            for (int i = 0; i < 4; ++i) {
                int linear = t + 256 * i;
                int row = linear >> 4;
                int c8 = (linear & 15) * 8;
                size_t g = (size_t)(b * Ss_ + k0 + row) * NKV + kvh * HD_ + c8;
                *(uint4*)&Ks[row * FA_STR + c8] = *(const uint4*)(Kh + g);
                *(uint4*)&Vs[row * FA_STR + c8] = *(const uint4*)(Vh + g);
            }
        }
        __syncthreads();

        if (k0 <= q0 + wq0 + 15) {   // warp-uniform: skip fully-masked blocks
            float sacc[8][4];
#pragma unroll
            for (int i = 0; i < 8; ++i)
#pragma unroll
                for (int j = 0; j < 4; ++j) sacc[i][j] = 0.0f;

            // S = Q @ K^T over d=128 (8 k16 steps)
#pragma unroll
            for (int kk = 0; kk < 8; ++kk) {
                uint32_t af[4];
                ldsm_x4(af, qa + kk * 32);
#pragma unroll
                for (int np = 0; np < 4; ++np) {
                    uint32_t bf[4];
                    ldsm_x4(bf, ka + np * 16 * (FA_STR * 2) + kk * 32);
                    mma16816h(sacc[np * 2],     af, bf);
                    mma16816h(sacc[np * 2 + 1], af, bf + 2);
                }
            }

            // Causal mask (only near-diagonal blocks)
            if (k0 + FA_BK - 1 > q0 + wq0) {
                const int rbase = q0 + wq0 + (lane >> 2);
                const int cbase = k0 + (lane & 3) * 2;
#pragma unroll
                for (int nt = 0; nt < 8; ++nt)
#pragma unroll
                    for (int e = 0; e < 4; ++e) {
                        int col = cbase + nt * 8 + (e & 1);
                        int row = rbase + (e >> 1) * 8;
                        if (col > row) sacc[nt][e] = -INFINITY;
                    }
            }

            // Online softmax (base-2 domain)
#pragma unroll
            for (int r = 0; r < 2; ++r) {
                float mx = -INFINITY;
#pragma unroll
                for (int nt = 0; nt < 8; ++nt)
                    mx = fmaxf(mx, fmaxf(sacc[nt][2 * r], sacc[nt][2 * r + 1]));
                mx = fmaxf(mx, __shfl_xor_sync(0xffffffffu, mx, 1));
                mx = fmaxf(mx, __shfl_xor_sync(0xffffffffu, mx, 2));
                float mn = fmaxf(mrow[r], mx);
                float al = ex2f(mrow[r] - mn);
                mrow[r] = mn;
                float rs = 0.0f;
#pragma unroll
                for (int nt = 0; nt < 8; ++nt) {
                    float p0 = ex2f(sacc[nt][2 * r] - mn);
                    float p1 = ex2f(sacc[nt][2 * r + 1] - mn);
                    sacc[nt][2 * r] = p0;
                    sacc[nt][2 * r + 1] = p1;
                    rs += p0 + p1;
                }
                rs += __shfl_xor_sync(0xffffffffu, rs, 1);
                rs += __shfl_xor_sync(0xffffffffu, rs, 2);
                lrow[r] = lrow[r] * al + rs;
#pragma unroll
                for (int nt = 0; nt < 16; ++nt) {
                    oacc[nt][2 * r]     *= al;
                    oacc[nt][2 * r + 1] *= al;
                }
            }

            // O += P @ V  (4 k16 steps over kv, 16 d-tiles)
#pragma unroll
            for (int j = 0; j < 4; ++j) {
                uint32_t a[4];
                a[0] = packh2(sacc[2 * j][0],     sacc[2 * j][1]);
                a[1] = packh2(sacc[2 * j][2],     sacc[2 * j][3]);
                a[2] = packh2(sacc[2 * j + 1][0], sacc[2 * j + 1][1]);
                a[3] = packh2(sacc[2 * j + 1][2], sacc[2 * j + 1][3]);
#pragma unroll
                for (int dp = 0; dp < 8; ++dp) {
                    uint32_t bf[4];
                    ldsm_x4_t(bf, va + j * 16 * (FA_STR * 2) + dp * 32);
                    mma16816h(oacc[dp * 2],     a, bf);
                    mma16816h(oacc[dp * 2 + 1], a, bf + 2);
                }
            }
        }
    }

    // Epilogue: normalize and write fp32 O
#pragma unroll
    for (int r = 0; r < 2; ++r) {
        float inv = 1.0f / lrow[r];
        int row = q0 + wq0 + (lane >> 2) + r * 8;
        float* Og = O + (size_t)(b * Ss_ + row) * Dd_ + h * HD_;
#pragma unroll
        for (int nt = 0; nt < 16; ++nt) {
            int col = nt * 8 + (lane & 3) * 2;
            *(float2*)(Og + col) =
                make_float2(oacc[nt][2 * r] * inv, oacc[nt][2 * r + 1] * inv);
        }
    }
}

// ---------------------------------------------------------------------------
// Launch
// ---------------------------------------------------------------------------
extern "C" void kernel_launch(void* const* d_in, const int* in_sizes, int n_in,
                              void* d_out, int out_size)
{
    const float* x  = (const float*)d_in[0];
    const float* Wq = (const float*)d_in[2];
    const float* Wk = (const float*)d_in[3];
    const float* Wv = (const float*)d_in[4];
    const float* Wo = (const float*)d_in[5];
    float* out = (float*)d_out;

    float *Qp, *Kp, *Vp, *Op;
    __nv_bfloat16 *Ahp, *Alp, *Bhp, *Blp;
    __half *Qhp, *Khp, *Vhp;
    cudaGetSymbolAddress((void**)&Qp, g_Q);
    cudaGetSymbolAddress((void**)&Kp, g_K);
    cudaGetSymbolAddress((void**)&Vp, g_V);
    cudaGetSymbolAddress((void**)&Op, g_O);
    cudaGetSymbolAddress((void**)&Ahp, g_Ah);
    cudaGetSymbolAddress((void**)&Alp, g_Al);
    cudaGetSymbolAddress((void**)&Bhp, g_Bh);
    cudaGetSymbolAddress((void**)&Blp, g_Bl);
    cudaGetSymbolAddress((void**)&Qhp, g_Qh);
    cudaGetSymbolAddress((void**)&Khp, g_Kh);
    cudaGetSymbolAddress((void**)&Vhp, g_Vh);

    cudaFuncSetAttribute(gemm_tc, cudaFuncAttributeMaxDynamicSharedMemorySize,
                         GEMM_SMEM_BYTES);
    cudaFuncSetAttribute(flash_tc, cudaFuncAttributeMaxDynamicSharedMemorySize,
                         FA_SMEM);

    const int nX  = MROWS * Dd_;
    const int nWq = Dd_ * Dd_;
    const int nWk = Dd_ * NKV;
    const int nKV = MROWS * NKV;

    // x -> bf16 hi/lo (A side)
    convert_split_k<<<nX / 1024, 256>>>(x, Ahp, Alp, nX);

    // Q = x @ Wq
    convert_split_k<<<nWq / 1024, 256>>>(Wq, Bhp, Blp, nWq);
    gemm_tc<<<dim3(Dd_ / 128, MROWS / 128), 256, GEMM_SMEM_BYTES>>>(
        Ahp, Alp, Bhp, Blp, Qp, MROWS, Dd_, Dd_);

    // K = x @ Wk
    convert_split_k<<<nWk / 1024, 256>>>(Wk, Bhp, Blp, nWk);
    gemm_tc<<<dim3(NKV / 128, MROWS / 128), 256, GEMM_SMEM_BYTES>>>(
        Ahp, Alp, Bhp, Blp, Kp, MROWS, NKV, Dd_);

    // V = x @ Wv
    convert_split_k<<<nWk / 1024, 256>>>(Wv, Bhp, Blp, nWk);
    gemm_tc<<<dim3(NKV / 128, MROWS / 128), 256, GEMM_SMEM_BYTES>>>(
        Ahp, Alp, Bhp, Blp, Vp, MROWS, NKV, Dd_);

    // RoPE
    {
        int totq = MROWS * Hh_ * 64;
        rope_kernel<<<(totq + 255) / 256, 256>>>(Qp, Hh_, totq);
        int totk = MROWS * HKV_ * 64;
        rope_kernel<<<(totk + 255) / 256, 256>>>(Kp, HKV_, totk);
    }

    // fp32 -> fp16 for attention (scale*log2e folded into Q)
    const float qmult = 1.4426950408889634f / sqrtf((float)HD_);
    convert_half_k<<<nX / 2048, 256>>>(Qp, Qhp, nX, qmult);
    convert_half_k<<<nKV / 2048, 256>>>(Kp, Khp, nKV, 1.0f);
    convert_half_k<<<nKV / 2048, 256>>>(Vp, Vhp, nKV, 1.0f);

    // Flash attention (tensor cores)
    flash_tc<<<dim3(Ss_ / FA_BQ, Hh_, Bb_), 256, FA_SMEM>>>(Qhp, Khp, Vhp, Op);

    // out = O @ Wo
    convert_split_k<<<nX / 1024, 256>>>(Op, Ahp, Alp, nX);
    convert_split_k<<<nWq / 1024, 256>>>(Wo, Bhp, Blp, nWq);
    gemm_tc<<<dim3(Dd_ / 128, MROWS / 128), 256, GEMM_SMEM_BYTES>>>(
        Ahp, Alp, Bhp, Blp, out, MROWS, Dd_, Dd_);
}

// round 7
// speedup vs baseline: 1.0072x; 1.0072x over previous
#include <cuda_runtime.h>
#include <cuda_bf16.h>
#include <cuda_fp16.h>
#include <math.h>
#include <stdint.h>

// Problem constants
#define Bb_ 2
#define Ss_ 2048
#define Dd_ 2048
#define Hh_ 16
#define HKV_ 2
#define HD_ 128
#define MROWS (Bb_ * Ss_)          // 4096
#define NKV (HKV_ * HD_)           // 256

// Scratch (allocation-free: __device__ globals)
__device__ float g_Q[(size_t)MROWS * Dd_];
__device__ float g_K[(size_t)MROWS * NKV];
__device__ float g_V[(size_t)MROWS * NKV];
__device__ float g_O[(size_t)MROWS * Dd_];
// bf16 split buffers for GEMM
__device__ __nv_bfloat16 g_Ah[(size_t)MROWS * Dd_];
__device__ __nv_bfloat16 g_Al[(size_t)MROWS * Dd_];
__device__ __nv_bfloat16 g_Bh[(size_t)Dd_ * Dd_];
__device__ __nv_bfloat16 g_Bl[(size_t)Dd_ * Dd_];
// fp16 buffers for attention
__device__ __half g_Qh[(size_t)MROWS * Dd_];
__device__ __half g_Kh[(size_t)MROWS * NKV];
__device__ __half g_Vh[(size_t)MROWS * NKV];

// ---------------------------------------------------------------------------
// Helpers
// ---------------------------------------------------------------------------
static __device__ __forceinline__ uint32_t smem_u32(const void* p) {
    uint32_t r;
    asm("{ .reg .u64 t; cvta.to.shared.u64 t, %1; cvt.u32.u64 %0, t; }"
        : "=r"(r) : "l"(p));
    return r;
}

static __device__ __forceinline__ void mma16816(float* c, const uint32_t* a,
                                                const uint32_t* b) {
    asm volatile(
        "mma.sync.aligned.m16n8k16.row.col.f32.bf16.bf16.f32 "
        "{%0,%1,%2,%3}, {%4,%5,%6,%7}, {%8,%9}, {%0,%1,%2,%3};"
        : "+f"(c[0]), "+f"(c[1]), "+f"(c[2]), "+f"(c[3])
        : "r"(a[0]), "r"(a[1]), "r"(a[2]), "r"(a[3]), "r"(b[0]), "r"(b[1]));
}

static __device__ __forceinline__ void mma16816h(float* c, const uint32_t* a,
                                                 const uint32_t* b) {
    asm volatile(
        "mma.sync.aligned.m16n8k16.row.col.f32.f16.f16.f32 "
        "{%0,%1,%2,%3}, {%4,%5,%6,%7}, {%8,%9}, {%0,%1,%2,%3};"
        : "+f"(c[0]), "+f"(c[1]), "+f"(c[2]), "+f"(c[3])
        : "r"(a[0]), "r"(a[1]), "r"(a[2]), "r"(a[3]), "r"(b[0]), "r"(b[1]));
}

static __device__ __forceinline__ void ldsm_x4(uint32_t* r, uint32_t addr) {
    asm volatile("ldmatrix.sync.aligned.m8n8.x4.shared.b16 {%0,%1,%2,%3}, [%4];"
                 : "=r"(r[0]), "=r"(r[1]), "=r"(r[2]), "=r"(r[3]) : "r"(addr));
}

static __device__ __forceinline__ void ldsm_x4_t(uint32_t* r, uint32_t addr) {
    asm volatile("ldmatrix.sync.aligned.m8n8.x4.trans.shared.b16 {%0,%1,%2,%3}, [%4];"
                 : "=r"(r[0]), "=r"(r[1]), "=r"(r[2]), "=r"(r[3]) : "r"(addr));
}

static __device__ __forceinline__ void ldsm_x2_t(uint32_t* r, uint32_t addr) {
    asm volatile("ldmatrix.sync.aligned.m8n8.x2.trans.shared.b16 {%0,%1}, [%2];"
                 : "=r"(r[0]), "=r"(r[1]) : "r"(addr));
}

static __device__ __forceinline__ float ex2f(float x) {
    float y;
    asm("ex2.approx.f32 %0, %1;" : "=f"(y) : "f"(x));
    return y;
}

static __device__ __forceinline__ uint32_t packh2(float a, float b) {
    __half2 h = __floats2half2_rn(a, b);
    return *reinterpret_cast<uint32_t*>(&h);
}

// Split a pair of floats into packed bf16x2 hi + lo residual
static __device__ __forceinline__ void split2(float a, float b,
                                              uint32_t& hi, uint32_t& lo) {
    __nv_bfloat162 h = __floats2bfloat162_rn(a, b);
    float ra = a - __bfloat162float(h.x);
    float rb = b - __bfloat162float(h.y);
    __nv_bfloat162 l = __floats2bfloat162_rn(ra, rb);
    hi = *reinterpret_cast<uint32_t*>(&h);
    lo = *reinterpret_cast<uint32_t*>(&l);
}

// fp32 -> bf16 hi/lo split
__global__ void convert_split_k(const float* __restrict__ in,
                                __nv_bfloat16* __restrict__ hi,
                                __nv_bfloat16* __restrict__ lo, int n)
{
    int i = (blockIdx.x * blockDim.x + threadIdx.x) * 4;
    if (i >= n) return;
    float4 v = *(const float4*)(in + i);
    uint32_t h0, l0, h1, l1;
    split2(v.x, v.y, h0, l0);
    split2(v.z, v.w, h1, l1);
    *(uint2*)(hi + i) = make_uint2(h0, h1);
    *(uint2*)(lo + i) = make_uint2(l0, l1);
}

// fp32 -> fp16 with multiplier
__global__ void convert_half_k(const float* __restrict__ in,
                               __half* __restrict__ out, int n, float mult)
{
    int i = (blockIdx.x * blockDim.x + threadIdx.x) * 8;
    if (i >= n) return;
    float4 a = *(const float4*)(in + i);
    float4 b = *(const float4*)(in + i + 4);
    uint4 o;
    o.x = packh2(a.x * mult, a.y * mult);
    o.y = packh2(a.z * mult, a.w * mult);
    o.z = packh2(b.x * mult, b.y * mult);
    o.w = packh2(b.z * mult, b.w * mult);
    *(uint4*)(out + i) = o;
}

// ---------------------------------------------------------------------------
// bf16x3 tensor-core GEMM (validated R4)
// ---------------------------------------------------------------------------
#define SA_STRIDE 72
#define SB_STRIDE 136
#define SA_SZ (128 * SA_STRIDE)
#define SB_SZ (64 * SB_STRIDE)
#define GEMM_SMEM_BYTES ((2 * SA_SZ + 2 * SB_SZ) * 2)

__global__ __launch_bounds__(256, 2) void gemm_tc(const __nv_bfloat16* __restrict__ Ah,
                                                  const __nv_bfloat16* __restrict__ Al,
                                                  const __nv_bfloat16* __restrict__ Bh,
                                                  const __nv_bfloat16* __restrict__ Bl,
                                                  float* __restrict__ C,
                                                  int M, int N, int K)
{
    extern __shared__ __nv_bfloat16 smb[];
    __nv_bfloat16* sAh = smb;
    __nv_bfloat16* sAl = sAh + SA_SZ;
    __nv_bfloat16* sBh = sAl + SA_SZ;
    __nv_bfloat16* sBl = sBh + SB_SZ;

    const int t    = threadIdx.x;
    const int lane = t & 31;
    const int wid  = t >> 5;
    const int wm   = wid & 1;
    const int wn   = wid >> 1;
    const int n0   = blockIdx.x * 128;
    const int m0   = blockIdx.y * 128;

    float acc[4][4][4];
#pragma unroll
    for (int i = 0; i < 4; ++i)
#pragma unroll
        for (int j = 0; j < 4; ++j)
#pragma unroll
            for (int k = 0; k < 4; ++k) acc[i][j][k] = 0.0f;

    const uint32_t A_LO = SA_SZ * 2;
    const uint32_t B_LO = SB_SZ * 2;
    const uint32_t a_addr = smem_u32(sAh) +
        (uint32_t)(((lane & 7) + ((lane >> 3) & 1) * 8 + wm * 64) * (SA_STRIDE * 2)) +
        (uint32_t)(((lane >> 4) & 1) * 16);
    const uint32_t b_addr = smem_u32(sBh) +
        (uint32_t)(((lane & 7) + ((lane >> 3) & 1) * 8) * (SB_STRIDE * 2)) +
        (uint32_t)(wn * 64);

    const int nch = K >> 6;
    for (int c = 0; c < nch; ++c) {
        const int k0 = c << 6;
        __syncthreads();
        {
            const int r  = t >> 4;
            const int c4 = (t & 15) * 4;
            const size_t gA = (size_t)(m0 + r) * K + k0 + c4;
#pragma unroll
            for (int p = 0; p < 8; ++p) {
                const size_t g = gA + (size_t)(16 * p) * K;
                const int s = (r + 16 * p) * SA_STRIDE + c4;
                *(uint2*)&sAh[s] = *(const uint2*)(Ah + g);
                *(uint2*)&sAl[s] = *(const uint2*)(Al + g);
            }
        }
        {
            const int kr = t >> 4;
            const int c8 = (t & 15) * 8;
#pragma unroll
            for (int i = 0; i < 4; ++i) {
                const size_t g = (size_t)(k0 + kr + 16 * i) * N + n0 + c8;
                const int s = (kr + 16 * i) * SB_STRIDE + c8;
                *(uint4*)&sBh[s] = *(const uint4*)(Bh + g);
                *(uint4*)&sBl[s] = *(const uint4*)(Bl + g);
            }
        }
        __syncthreads();

#pragma unroll
        for (int k16 = 0; k16 < 4; ++k16) {
            uint32_t bh[4][2], bl[4][2], af[4][4];
            const uint32_t bko = (uint32_t)(k16 * 16 * SB_STRIDE * 2);
#pragma unroll
            for (int nt = 0; nt < 4; ++nt) {
                ldsm_x2_t(bh[nt], b_addr + nt * 16 + bko);
                ldsm_x2_t(bl[nt], b_addr + B_LO + nt * 16 + bko);
            }
            const uint32_t ako = (uint32_t)(k16 * 32);
#pragma unroll
            for (int mt = 0; mt < 4; ++mt)
                ldsm_x4(af[mt], a_addr + mt * (16 * SA_STRIDE * 2) + ako);
#pragma unroll
            for (int mt = 0; mt < 4; ++mt)
#pragma unroll
                for (int nt = 0; nt < 4; ++nt) {
                    mma16816(acc[mt][nt], af[mt], bh[nt]);
                    mma16816(acc[mt][nt], af[mt], bl[nt]);
                }
#pragma unroll
            for (int mt = 0; mt < 4; ++mt)
                ldsm_x4(af[mt], a_addr + A_LO + mt * (16 * SA_STRIDE * 2) + ako);
#pragma unroll
            for (int mt = 0; mt < 4; ++mt)
#pragma unroll
                for (int nt = 0; nt < 4; ++nt)
                    mma16816(acc[mt][nt], af[mt], bh[nt]);
        }
    }

    const int g   = lane >> 2;
    const int tid = lane & 3;
#pragma unroll
    for (int mt = 0; mt < 4; ++mt) {
        const int row = m0 + wm * 64 + mt * 16 + g;
#pragma unroll
        for (int nt = 0; nt < 4; ++nt) {
            const int col = n0 + wn * 32 + nt * 8 + tid * 2;
            *(float2*)(C + (size_t)row * N + col) =
                make_float2(acc[mt][nt][0], acc[mt][nt][1]);
            *(float2*)(C + (size_t)(row + 8) * N + col) =
                make_float2(acc[mt][nt][2], acc[mt][nt][3]);
        }
    }
}

// ---------------------------------------------------------------------------
// RoPE (unchanged, validated)
// ---------------------------------------------------------------------------
__global__ void rope_kernel(float* __restrict__ buf, int nh, int total)
{
    int idx = blockIdx.x * blockDim.x + threadIdx.x;
    if (idx >= total) return;
    int i    = idx & 63;
    int hh   = (idx >> 6) % nh;
    int srow = idx / (64 * nh);
    int pos  = srow & (Ss_ - 1);

    float inv = (float)exp(-(double)i * (log(10000.0) / 64.0));
    float ang = (float)pos * inv;
    float sn, cs;
    sincosf(ang, &sn, &cs);

    size_t base = (size_t)srow * (nh * HD_) + (size_t)hh * HD_ + i;
    float x1 = buf[base];
    float x2 = buf[base + 64];
    buf[base]      = x1 * cs - x2 * sn;
    buf[base + 64] = x2 * cs + x1 * sn;
}

// ---------------------------------------------------------------------------
// Tensor-core causal flash attention (fp16 mma, fp32 accum, exp2 softmax).
// Grid (S/128, H, B), 256 threads = 8 warps x 16 q-rows. BK=64.
// SMEM (half, stride 136): Qs[128], Ks[64], Vs[64]  -> conflict-free ldmatrix.
// Q is pre-scaled by (1/sqrt(128))*log2(e); softmax in base-2 domain.
// ---------------------------------------------------------------------------
#define FA_BQ 128
#define FA_BK 64
#define FA_STR 136
#define FA_SMEM ((FA_BQ + 2 * FA_BK) * FA_STR * 2)

__global__ __launch_bounds__(256) void flash_tc(const __half* __restrict__ Qh,
                                                const __half* __restrict__ Kh,
                                                const __half* __restrict__ Vh,
                                                float* __restrict__ O)
{
    extern __shared__ __half sh[];
    __half* Qs = sh;                         // [128][136]
    __half* Ks = Qs + FA_BQ * FA_STR;        // [64][136]
    __half* Vs = Ks + FA_BK * FA_STR;        // [64][136]

    const int qb = blockIdx.x, h = blockIdx.y, b = blockIdx.z;
    const int kvh = h % HKV_;
    const int t = threadIdx.x, lane = t & 31, w = t >> 5;
    const int q0 = qb * FA_BQ;
    const int wq0 = w * 16;

    // Load Q tile once
    {
#pragma unroll
        for (int i = 0; i < 8; ++i) {
            int linear = t + 256 * i;
            int row = linear >> 4;
            int c8 = (linear & 15) * 8;
            *(uint4*)&Qs[row * FA_STR + c8] =
                *(const uint4*)(Qh + (size_t)(b * Ss_ + q0 + row) * Dd_ + h * HD_ + c8);
        }
    }

    float oacc[16][4];
#pragma unroll
    for (int i = 0; i < 16; ++i)
#pragma unroll
        for (int j = 0; j < 4; ++j) oacc[i][j] = 0.0f;
    float mrow[2] = {-INFINITY, -INFINITY};
    float lrow[2] = {0.0f, 0.0f};

    const uint32_t qa = smem_u32(Qs) +
        (uint32_t)((wq0 + (lane & 15)) * (FA_STR * 2)) +
        (uint32_t)(((lane >> 4) & 1) * 16);
    // K (B operand, col-major natural): rows = kv pos, non-trans
    const uint32_t ka = smem_u32(Ks) +
        (uint32_t)(((lane & 7) + ((lane >> 4) & 1) * 8) * (FA_STR * 2)) +
        (uint32_t)(((lane >> 3) & 1) * 16);
    // V (B operand, row-major [kv][d]): trans
    const uint32_t va = smem_u32(Vs) +
        (uint32_t)(((lane & 7) + ((lane >> 3) & 1) * 8) * (FA_STR * 2)) +
        (uint32_t)(((lane >> 4) & 1) * 16);

    const int nkb = (q0 + FA_BQ) / FA_BK;
    for (int kb = 0; kb < nkb; ++kb) {
        const int k0 = kb * FA_BK;
        __syncthreads();
        // Load K and V tiles
        {
#pragma unroll
            for (int i = 0; i < 4; ++i) {
                int linear = t + 256 * i;
                int row = linear >> 4;
                int c8 = (linear & 15) * 8;
                size_t g = (size_t)(b * Ss_ + k0 + row) * NKV + kvh * HD_ + c8;
                *(uint4*)&Ks[row * FA_STR + c8] = *(const uint4*)(Kh + g);
                *(uint4*)&Vs[row * FA_STR + c8] = *(const uint4*)(Vh + g);
            }
        }
        __syncthreads();

        if (k0 <= q0 + wq0 + 15) {   // warp-uniform: skip fully-masked blocks
            float sacc[8][4];
#pragma unroll
            for (int i = 0; i < 8; ++i)
#pragma unroll
                for (int j = 0; j < 4; ++j) sacc[i][j] = 0.0f;

            // S = Q @ K^T over d=128 (8 k16 steps)
#pragma unroll
            for (int kk = 0; kk < 8; ++kk) {
                uint32_t af[4];
                ldsm_x4(af, qa + kk * 32);
#pragma unroll
                for (int np = 0; np < 4; ++np) {
                    uint32_t bf[4];
                    ldsm_x4(bf, ka + np * 16 * (FA_STR * 2) + kk * 32);
                    mma16816h(sacc[np * 2],     af, bf);
                    mma16816h(sacc[np * 2 + 1], af, bf + 2);
                }
            }

            // Causal mask (only near-diagonal blocks)
            if (k0 + FA_BK - 1 > q0 + wq0) {
                const int rbase = q0 + wq0 + (lane >> 2);
                const int cbase = k0 + (lane & 3) * 2;
#pragma unroll
                for (int nt = 0; nt < 8; ++nt)
#pragma unroll
                    for (int e = 0; e < 4; ++e) {
                        int col = cbase + nt * 8 + (e & 1);
                        int row = rbase + (e >> 1) * 8;
                        if (col > row) sacc[nt][e] = -INFINITY;
                    }
            }

            // Online softmax (base-2 domain)
#pragma unroll
            for (int r = 0; r < 2; ++r) {
                float mx = -INFINITY;
#pragma unroll
                for (int nt = 0; nt < 8; ++nt)
                    mx = fmaxf(mx, fmaxf(sacc[nt][2 * r], sacc[nt][2 * r + 1]));
                mx = fmaxf(mx, __shfl_xor_sync(0xffffffffu, mx, 1));
                mx = fmaxf(mx, __shfl_xor_sync(0xffffffffu, mx, 2));
                float mn = fmaxf(mrow[r], mx);
                float al = ex2f(mrow[r] - mn);
                mrow[r] = mn;
                float rs = 0.0f;
#pragma unroll
                for (int nt = 0; nt < 8; ++nt) {
                    float p0 = ex2f(sacc[nt][2 * r] - mn);
                    float p1 = ex2f(sacc[nt][2 * r + 1] - mn);
                    sacc[nt][2 * r] = p0;
                    sacc[nt][2 * r + 1] = p1;
                    rs += p0 + p1;
                }
                rs += __shfl_xor_sync(0xffffffffu, rs, 1);
                rs += __shfl_xor_sync(0xffffffffu, rs, 2);
                lrow[r] = lrow[r] * al + rs;
#pragma unroll
                for (int nt = 0; nt < 16; ++nt) {
                    oacc[nt][2 * r]     *= al;
                    oacc[nt][2 * r + 1] *= al;
                }
            }

            // O += P @ V  (4 k16 steps over kv, 16 d-tiles)
#pragma unroll
            for (int j = 0; j < 4; ++j) {
                uint32_t a[4];
                a[0] = packh2(sacc[2 * j][0],     sacc[2 * j][1]);
                a[1] = packh2(sacc[2 * j][2],     sacc[2 * j][3]);
                a[2] = packh2(sacc[2 * j + 1][0], sacc[2 * j + 1][1]);
                a[3] = packh2(sacc[2 * j + 1][2], sacc[2 * j + 1][3]);
#pragma unroll
                for (int dp = 0; dp < 8; ++dp) {
                    uint32_t bf[4];
                    ldsm_x4_t(bf, va + j * 16 * (FA_STR * 2) + dp * 32);
                    mma16816h(oacc[dp * 2],     a, bf);
                    mma16816h(oacc[dp * 2 + 1], a, bf + 2);
                }
            }
        }
    }

    // Epilogue: normalize and write fp32 O
#pragma unroll
    for (int r = 0; r < 2; ++r) {
        float inv = 1.0f / lrow[r];
        int row = q0 + wq0 + (lane >> 2) + r * 8;
        float* Og = O + (size_t)(b * Ss_ + row) * Dd_ + h * HD_;
#pragma unroll
        for (int nt = 0; nt < 16; ++nt) {
            int col = nt * 8 + (lane & 3) * 2;
            *(float2*)(Og + col) =
                make_float2(oacc[nt][2 * r] * inv, oacc[nt][2 * r + 1] * inv);
        }
    }
}

// ---------------------------------------------------------------------------
// Launch
// ---------------------------------------------------------------------------
extern "C" void kernel_launch(void* const* d_in, const int* in_sizes, int n_in,
                              void* d_out, int out_size)
{
    const float* x  = (const float*)d_in[0];
    const float* Wq = (const float*)d_in[2];
    const float* Wk = (const float*)d_in[3];
    const float* Wv = (const float*)d_in[4];
    const float* Wo = (const float*)d_in[5];
    float* out = (float*)d_out;

    float *Qp, *Kp, *Vp, *Op;
    __nv_bfloat16 *Ahp, *Alp, *Bhp, *Blp;
    __half *Qhp, *Khp, *Vhp;
    cudaGetSymbolAddress((void**)&Qp, g_Q);
    cudaGetSymbolAddress((void**)&Kp, g_K);
    cudaGetSymbolAddress((void**)&Vp, g_V);
    cudaGetSymbolAddress((void**)&Op, g_O);
    cudaGetSymbolAddress((void**)&Ahp, g_Ah);
    cudaGetSymbolAddress((void**)&Alp, g_Al);
    cudaGetSymbolAddress((void**)&Bhp, g_Bh);
    cudaGetSymbolAddress((void**)&Blp, g_Bl);
    cudaGetSymbolAddress((void**)&Qhp, g_Qh);
    cudaGetSymbolAddress((void**)&Khp, g_Kh);
    cudaGetSymbolAddress((void**)&Vhp, g_Vh);

    cudaFuncSetAttribute(gemm_tc, cudaFuncAttributeMaxDynamicSharedMemorySize,
                         GEMM_SMEM_BYTES);
    cudaFuncSetAttribute(flash_tc, cudaFuncAttributeMaxDynamicSharedMemorySize,
                         FA_SMEM);

    const int nX  = MROWS * Dd_;
    const int nWq = Dd_ * Dd_;
    const int nWk = Dd_ * NKV;
    const int nKV = MROWS * NKV;

    // x -> bf16 hi/lo (A side)
    convert_split_k<<<nX / 1024, 256>>>(x, Ahp, Alp, nX);

    // Q = x @ Wq
    convert_split_k<<<nWq / 1024, 256>>>(Wq, Bhp, Blp, nWq);
    gemm_tc<<<dim3(Dd_ / 128, MROWS / 128), 256, GEMM_SMEM_BYTES>>>(
        Ahp, Alp, Bhp, Blp, Qp, MROWS, Dd_, Dd_);

    // K = x @ Wk
    convert_split_k<<<nWk / 1024, 256>>>(Wk, Bhp, Blp, nWk);
    gemm_tc<<<dim3(NKV / 128, MROWS / 128), 256, GEMM_SMEM_BYTES>>>(
        Ahp, Alp, Bhp, Blp, Kp, MROWS, NKV, Dd_);

    // V = x @ Wv
    convert_split_k<<<nWk / 1024, 256>>>(Wv, Bhp, Blp, nWk);
    gemm_tc<<<dim3(NKV / 128, MROWS / 128), 256, GEMM_SMEM_BYTES>>>(
        Ahp, Alp, Bhp, Blp, Vp, MROWS, NKV, Dd_);

    // RoPE
    {
        int totq = MROWS * Hh_ * 64;
        rope_kernel<<<(totq + 255) / 256, 256>>>(Qp, Hh_, totq);
        int totk = MROWS * HKV_ * 64;
        rope_kernel<<<(totk + 255) / 256, 256>>>(Kp, HKV_, totk);
    }

    // fp32 -> fp16 for attention (scale*log2e folded into Q)
    const float qmult = 1.4426950408889634f / sqrtf((float)HD_);
    convert_half_k<<<nX / 2048, 256>>>(Qp, Qhp, nX, qmult);
    convert_half_k<<<nKV / 2048, 256>>>(Kp, Khp, nKV, 1.0f);
    convert_half_k<<<nKV / 2048, 256>>>(Vp, Vhp, nKV, 1.0f);

    // Flash attention (tensor cores)
    flash_tc<<<dim3(Ss_ / FA_BQ, Hh_, Bb_), 256, FA_SMEM>>>(Qhp, Khp, Vhp, Op);

    // out = O @ Wo
    convert_split_k<<<nX / 1024, 256>>>(Op, Ahp, Alp, nX);
    convert_split_k<<<nWq / 1024, 256>>>(Wo, Bhp, Blp, nWq);
    gemm_tc<<<dim3(Dd_ / 128, MROWS / 128), 256, GEMM_SMEM_BYTES>>>(
        Ahp, Alp, Bhp, Blp, out, MROWS, Dd_, Dd_);
}

// round 8
// speedup vs baseline: 1.0603x; 1.0528x over previous
#include <cuda_runtime.h>
#include <cuda_bf16.h>
#include <cuda_fp16.h>
#include <math.h>
#include <stdint.h>

// Problem constants
#define Bb_ 2
#define Ss_ 2048
#define Dd_ 2048
#define Hh_ 16
#define HKV_ 2
#define HD_ 128
#define MROWS (Bb_ * Ss_)          // 4096
#define NKV (HKV_ * HD_)           // 256
#define NKV2 512                   // combined K|V projection width

// Scratch (allocation-free: __device__ globals)
__device__ float g_Q[(size_t)MROWS * Dd_];
__device__ float g_KV[(size_t)MROWS * NKV2];   // cols 0-255 = K, 256-511 = V
__device__ float g_O[(size_t)MROWS * Dd_];
// bf16 split buffers for GEMM
__device__ __nv_bfloat16 g_Ah[(size_t)MROWS * Dd_];
__device__ __nv_bfloat16 g_Al[(size_t)MROWS * Dd_];
__device__ __nv_bfloat16 g_Bh[(size_t)Dd_ * Dd_];
__device__ __nv_bfloat16 g_Bl[(size_t)Dd_ * Dd_];
// fp16 buffers for attention
__device__ __half g_Qh[(size_t)MROWS * Dd_];
__device__ __half g_Kh[(size_t)MROWS * NKV];
__device__ __half g_Vh[(size_t)MROWS * NKV];

// ---------------------------------------------------------------------------
// Helpers
// ---------------------------------------------------------------------------
static __device__ __forceinline__ uint32_t smem_u32(const void* p) {
    uint32_t r;
    asm("{ .reg .u64 t; cvta.to.shared.u64 t, %1; cvt.u32.u64 %0, t; }"
        : "=r"(r) : "l"(p));
    return r;
}

static __device__ __forceinline__ void mma16816(float* c, const uint32_t* a,
                                                const uint32_t* b) {
    asm volatile(
        "mma.sync.aligned.m16n8k16.row.col.f32.bf16.bf16.f32 "
        "{%0,%1,%2,%3}, {%4,%5,%6,%7}, {%8,%9}, {%0,%1,%2,%3};"
        : "+f"(c[0]), "+f"(c[1]), "+f"(c[2]), "+f"(c[3])
        : "r"(a[0]), "r"(a[1]), "r"(a[2]), "r"(a[3]), "r"(b[0]), "r"(b[1]));
}

static __device__ __forceinline__ void mma16816h(float* c, const uint32_t* a,
                                                 const uint32_t* b) {
    asm volatile(
        "mma.sync.aligned.m16n8k16.row.col.f32.f16.f16.f32 "
        "{%0,%1,%2,%3}, {%4,%5,%6,%7}, {%8,%9}, {%0,%1,%2,%3};"
        : "+f"(c[0]), "+f"(c[1]), "+f"(c[2]), "+f"(c[3])
        : "r"(a[0]), "r"(a[1]), "r"(a[2]), "r"(a[3]), "r"(b[0]), "r"(b[1]));
}

static __device__ __forceinline__ void ldsm_x4(uint32_t* r, uint32_t addr) {
    asm volatile("ldmatrix.sync.aligned.m8n8.x4.shared.b16 {%0,%1,%2,%3}, [%4];"
                 : "=r"(r[0]), "=r"(r[1]), "=r"(r[2]), "=r"(r[3]) : "r"(addr));
}

static __device__ __forceinline__ void ldsm_x4_t(uint32_t* r, uint32_t addr) {
    asm volatile("ldmatrix.sync.aligned.m8n8.x4.trans.shared.b16 {%0,%1,%2,%3}, [%4];"
                 : "=r"(r[0]), "=r"(r[1]), "=r"(r[2]), "=r"(r[3]) : "r"(addr));
}

static __device__ __forceinline__ void ldsm_x2_t(uint32_t* r, uint32_t addr) {
    asm volatile("ldmatrix.sync.aligned.m8n8.x2.trans.shared.b16 {%0,%1}, [%2];"
                 : "=r"(r[0]), "=r"(r[1]) : "r"(addr));
}

static __device__ __forceinline__ float ex2f(float x) {
    float y;
    asm("ex2.approx.f32 %0, %1;" : "=f"(y) : "f"(x));
    return y;
}

static __device__ __forceinline__ uint32_t packh2(float a, float b) {
    __half2 h = __floats2half2_rn(a, b);
    return *reinterpret_cast<uint32_t*>(&h);
}

#define CPA16(dst, src) \
    asm volatile("cp.async.cg.shared.global [%0], [%1], 16;" :: "r"(dst), "l"(src))
#define CP_COMMIT() asm volatile("cp.async.commit_group;" ::: "memory")
#define CP_WAIT1() asm volatile("cp.async.wait_group 1;" ::: "memory")
#define CP_WAIT0() asm volatile("cp.async.wait_group 0;" ::: "memory")

// Split a pair of floats into packed bf16x2 hi + lo residual
static __device__ __forceinline__ void split2(float a, float b,
                                              uint32_t& hi, uint32_t& lo) {
    __nv_bfloat162 h = __floats2bfloat162_rn(a, b);
    float ra = a - __bfloat162float(h.x);
    float rb = b - __bfloat162float(h.y);
    __nv_bfloat162 l = __floats2bfloat162_rn(ra, rb);
    hi = *reinterpret_cast<uint32_t*>(&h);
    lo = *reinterpret_cast<uint32_t*>(&l);
}

// fp32 -> bf16 hi/lo split (contiguous)
__global__ void convert_split_k(const float* __restrict__ in,
                                __nv_bfloat16* __restrict__ hi,
                                __nv_bfloat16* __restrict__ lo, int n)
{
    int i = (blockIdx.x * blockDim.x + threadIdx.x) * 4;
    if (i >= n) return;
    float4 v = *(const float4*)(in + i);
    uint32_t h0, l0, h1, l1;
    split2(v.x, v.y, h0, l0);
    split2(v.z, v.w, h1, l1);
    *(uint2*)(hi + i) = make_uint2(h0, h1);
    *(uint2*)(lo + i) = make_uint2(l0, l1);
}

// fp32 [r][cols] -> bf16 hi/lo placed at [r][coloff + c] with row stride ldout
__global__ void convert_split_strided(const float* __restrict__ in,
                                      __nv_bfloat16* __restrict__ hi,
                                      __nv_bfloat16* __restrict__ lo,
                                      int cols, int ldout, int coloff, int n)
{
    int i = (blockIdx.x * blockDim.x + threadIdx.x) * 4;
    if (i >= n) return;
    int r = i / cols, c = i % cols;
    float4 v = *(const float4*)(in + i);
    uint32_t h0, l0, h1, l1;
    split2(v.x, v.y, h0, l0);
    split2(v.z, v.w, h1, l1);
    size_t off = (size_t)r * ldout + coloff + c;
    *(uint2*)(hi + off) = make_uint2(h0, h1);
    *(uint2*)(lo + off) = make_uint2(l0, l1);
}

// RoPE + scale + fp16 convert, separate in/out buffers with strides
__global__ void rope_half_k(const float* __restrict__ in, __half* __restrict__ out,
                            int nh, int ld_in, int ld_out, float mult, int total)
{
    int idx = blockIdx.x * blockDim.x + threadIdx.x;
    if (idx >= total) return;
    int i    = idx & 63;
    int hh   = (idx >> 6) % nh;
    int srow = idx / (64 * nh);
    int pos  = srow & (Ss_ - 1);

    float inv = (float)exp(-(double)i * (log(10000.0) / 64.0));
    float ang = (float)pos * inv;
    float sn, cs;
    sincosf(ang, &sn, &cs);

    size_t bi = (size_t)srow * ld_in + (size_t)hh * HD_ + i;
    size_t bo = (size_t)srow * ld_out + (size_t)hh * HD_ + i;
    float x1 = in[bi];
    float x2 = in[bi + 64];
    out[bo]      = __float2half((x1 * cs - x2 * sn) * mult);
    out[bo + 64] = __float2half((x2 * cs + x1 * sn) * mult);
}

// fp32 strided [r][ld_in] (cols window) -> fp16 dense [r][cols]
__global__ void convert_half_strided(const float* __restrict__ in,
                                     __half* __restrict__ out,
                                     int cols, int ld_in, int n)
{
    int i = (blockIdx.x * blockDim.x + threadIdx.x) * 8;
    if (i >= n) return;
    int r = i / cols, c = i % cols;
    const float* src = in + (size_t)r * ld_in + c;
    float4 a = *(const float4*)src;
    float4 b = *(const float4*)(src + 4);
    uint4 o;
    o.x = packh2(a.x, a.y);
    o.y = packh2(a.z, a.w);
    o.z = packh2(b.x, b.y);
    o.w = packh2(b.z, b.w);
    *(uint4*)(out + (size_t)r * cols + c) = o;
}

// ---------------------------------------------------------------------------
// bf16x3 tensor-core GEMM, cp.async 2-stage pipelined.
// CTA 128x128, BK=64, 8 warps (2m x 4n, 64x32 each).
// ---------------------------------------------------------------------------
#define SA_STRIDE 72
#define SB_STRIDE 136
#define SA_SZ (128 * SA_STRIDE)               // 9216 halves
#define SB_SZ (64 * SB_STRIDE)                // 8704 halves
#define STG_BYTES ((2 * SA_SZ + 2 * SB_SZ) * 2)   // 71680
#define GEMM_SMEM_BYTES (2 * STG_BYTES)           // 143360

__global__ __launch_bounds__(256, 1) void gemm_tc(const __nv_bfloat16* __restrict__ Ah,
                                                  const __nv_bfloat16* __restrict__ Al,
                                                  const __nv_bfloat16* __restrict__ Bh,
                                                  const __nv_bfloat16* __restrict__ Bl,
                                                  float* __restrict__ C,
                                                  int M, int N, int K)
{
    extern __shared__ __nv_bfloat16 smb[];
    const uint32_t sbase = smem_u32(smb);

    const int t    = threadIdx.x;
    const int lane = t & 31;
    const int wid  = t >> 5;
    const int wm   = wid & 1;
    const int wn   = wid >> 1;
    const int n0   = blockIdx.x * 128;
    const int m0   = blockIdx.y * 128;

    float acc[4][4][4];
#pragma unroll
    for (int i = 0; i < 4; ++i)
#pragma unroll
        for (int j = 0; j < 4; ++j)
#pragma unroll
            for (int k = 0; k < 4; ++k) acc[i][j][k] = 0.0f;

    auto load_stage = [&](int c, int buf) {
        const int k0 = c << 6;
        const uint32_t sb = sbase + (uint32_t)buf * STG_BYTES;
#pragma unroll
        for (int i = 0; i < 4; ++i) {                 // A hi+lo: 1024 vec16 each
            int li = t + 256 * i;
            int row = li >> 3, v = li & 7;
            const size_t g = (size_t)(m0 + row) * K + k0 + v * 8;
            uint32_t s = sb + (uint32_t)(row * SA_STRIDE + v * 8) * 2;
            CPA16(s, Ah + g);
            CPA16(s + SA_SZ * 2, Al + g);
        }
#pragma unroll
        for (int i = 0; i < 4; ++i) {                 // B hi+lo: 1024 vec16 each
            int li = t + 256 * i;
            int row = li >> 4, v = li & 15;
            const size_t g = (size_t)(k0 + row) * N + n0 + v * 8;
            uint32_t s = sb + (uint32_t)(2 * SA_SZ + row * SB_STRIDE + v * 8) * 2;
            CPA16(s, Bh + g);
            CPA16(s + SB_SZ * 2, Bl + g);
        }
    };

    // lane-relative fragment offsets (bytes, rel. to stage base)
    const uint32_t a_rel =
        (uint32_t)(((lane & 7) + ((lane >> 3) & 1) * 8 + wm * 64) * (SA_STRIDE * 2)) +
        (uint32_t)(((lane >> 4) & 1) * 16);
    const uint32_t b_rel = (uint32_t)(2 * SA_SZ * 2) +
        (uint32_t)(((lane & 7) + ((lane >> 3) & 1) * 8) * (SB_STRIDE * 2)) +
        (uint32_t)(wn * 64);
    const uint32_t A_LO = SA_SZ * 2;
    const uint32_t B_LO = SB_SZ * 2;

    const int nch = K >> 6;
    load_stage(0, 0);
    CP_COMMIT();

    for (int c = 0; c < nch; ++c) {
        const int buf = c & 1;
        if (c + 1 < nch) {
            load_stage(c + 1, (c + 1) & 1);
            CP_COMMIT();
            CP_WAIT1();
        } else {
            CP_WAIT0();
        }
        __syncthreads();

        const uint32_t stg = sbase + (uint32_t)buf * STG_BYTES;
        const uint32_t a_addr = stg + a_rel;
        const uint32_t b_addr = stg + b_rel;

#pragma unroll
        for (int k16 = 0; k16 < 4; ++k16) {
            uint32_t bh[4][2], bl[4][2], af[4][4];
            const uint32_t bko = (uint32_t)(k16 * 16 * SB_STRIDE * 2);
#pragma unroll
            for (int nt = 0; nt < 4; ++nt) {
                ldsm_x2_t(bh[nt], b_addr + nt * 16 + bko);
                ldsm_x2_t(bl[nt], b_addr + B_LO + nt * 16 + bko);
            }
            const uint32_t ako = (uint32_t)(k16 * 32);
#pragma unroll
            for (int mt = 0; mt < 4; ++mt)
                ldsm_x4(af[mt], a_addr + mt * (16 * SA_STRIDE * 2) + ako);
#pragma unroll
            for (int mt = 0; mt < 4; ++mt)
#pragma unroll
                for (int nt = 0; nt < 4; ++nt) {
                    mma16816(acc[mt][nt], af[mt], bh[nt]);
                    mma16816(acc[mt][nt], af[mt], bl[nt]);
                }
#pragma unroll
            for (int mt = 0; mt < 4; ++mt)
                ldsm_x4(af[mt], a_addr + A_LO + mt * (16 * SA_STRIDE * 2) + ako);
#pragma unroll
            for (int mt = 0; mt < 4; ++mt)
#pragma unroll
                for (int nt = 0; nt < 4; ++nt)
                    mma16816(acc[mt][nt], af[mt], bh[nt]);
        }
        __syncthreads();
    }

    const int g   = lane >> 2;
    const int tid = lane & 3;
#pragma unroll
    for (int mt = 0; mt < 4; ++mt) {
        const int row = m0 + wm * 64 + mt * 16 + g;
#pragma unroll
        for (int nt = 0; nt < 4; ++nt) {
            const int col = n0 + wn * 32 + nt * 8 + tid * 2;
            *(float2*)(C + (size_t)row * N + col) =
                make_float2(acc[mt][nt][0], acc[mt][nt][1]);
            *(float2*)(C + (size_t)(row + 8) * N + col) =
                make_float2(acc[mt][nt][2], acc[mt][nt][3]);
        }
    }
}

// ---------------------------------------------------------------------------
// Tensor-core causal flash attention (validated R7, unchanged)
// ---------------------------------------------------------------------------
#define FA_BQ 128
#define FA_BK 64
#define FA_STR 136
#define FA_SMEM ((FA_BQ + 2 * FA_BK) * FA_STR * 2)

__global__ __launch_bounds__(256) void flash_tc(const __half* __restrict__ Qh,
                                                const __half* __restrict__ Kh,
                                                const __half* __restrict__ Vh,
                                                float* __restrict__ O)
{
    extern __shared__ __half sh[];
    __half* Qs = sh;
    __half* Ks = Qs + FA_BQ * FA_STR;
    __half* Vs = Ks + FA_BK * FA_STR;

    const int qb = blockIdx.x, h = blockIdx.y, b = blockIdx.z;
    const int kvh = h % HKV_;
    const int t = threadIdx.x, lane = t & 31, w = t >> 5;
    const int q0 = qb * FA_BQ;
    const int wq0 = w * 16;

    {
#pragma unroll
        for (int i = 0; i < 8; ++i) {
            int linear = t + 256 * i;
            int row = linear >> 4;
            int c8 = (linear & 15) * 8;
            *(uint4*)&Qs[row * FA_STR + c8] =
                *(const uint4*)(Qh + (size_t)(b * Ss_ + q0 + row) * Dd_ + h * HD_ + c8);
        }
    }

    float oacc[16][4];
#pragma unroll
    for (int i = 0; i < 16; ++i)
#pragma unroll
        for (int j = 0; j < 4; ++j) oacc[i][j] = 0.0f;
    float mrow[2] = {-INFINITY, -INFINITY};
    float lrow[2] = {0.0f, 0.0f};

    const uint32_t qa = smem_u32(Qs) +
        (uint32_t)((wq0 + (lane & 15)) * (FA_STR * 2)) +
        (uint32_t)(((lane >> 4) & 1) * 16);
    const uint32_t ka = smem_u32(Ks) +
        (uint32_t)(((lane & 7) + ((lane >> 4) & 1) * 8) * (FA_STR * 2)) +
        (uint32_t)(((lane >> 3) & 1) * 16);
    const uint32_t va = smem_u32(Vs) +
        (uint32_t)(((lane & 7) + ((lane >> 3) & 1) * 8) * (FA_STR * 2)) +
        (uint32_t)(((lane >> 4) & 1) * 16);

    const int nkb = (q0 + FA_BQ) / FA_BK;
    for (int kb = 0; kb < nkb; ++kb) {
        const int k0 = kb * FA_BK;
        __syncthreads();
        {
#pragma unroll
            for (int i = 0; i < 4; ++i) {
                int linear = t + 256 * i;
                int row = linear >> 4;
                int c8 = (linear & 15) * 8;
                size_t g = (size_t)(b * Ss_ + k0 + row) * NKV + kvh * HD_ + c8;
                *(uint4*)&Ks[row * FA_STR + c8] = *(const uint4*)(Kh + g);
                *(uint4*)&Vs[row * FA_STR + c8] = *(const uint4*)(Vh + g);
            }
        }
        __syncthreads();

        if (k0 <= q0 + wq0 + 15) {
            float sacc[8][4];
#pragma unroll
            for (int i = 0; i < 8; ++i)
#pragma unroll
                for (int j = 0; j < 4; ++j) sacc[i][j] = 0.0f;

#pragma unroll
            for (int kk = 0; kk < 8; ++kk) {
                uint32_t af[4];
                ldsm_x4(af, qa + kk * 32);
#pragma unroll
                for (int np = 0; np < 4; ++np) {
                    uint32_t bf[4];
                    ldsm_x4(bf, ka + np * 16 * (FA_STR * 2) + kk * 32);
                    mma16816h(sacc[np * 2],     af, bf);
                    mma16816h(sacc[np * 2 + 1], af, bf + 2);
                }
            }

            if (k0 + FA_BK - 1 > q0 + wq0) {
                const int rbase = q0 + wq0 + (lane >> 2);
                const int cbase = k0 + (lane & 3) * 2;
#pragma unroll
                for (int nt = 0; nt < 8; ++nt)
#pragma unroll
                    for (int e = 0; e < 4; ++e) {
                        int col = cbase + nt * 8 + (e & 1);
                        int row = rbase + (e >> 1) * 8;
                        if (col > row) sacc[nt][e] = -INFINITY;
                    }
            }

#pragma unroll
            for (int r = 0; r < 2; ++r) {
                float mx = -INFINITY;
#pragma unroll
                for (int nt = 0; nt < 8; ++nt)
                    mx = fmaxf(mx, fmaxf(sacc[nt][2 * r], sacc[nt][2 * r + 1]));
                mx = fmaxf(mx, __shfl_xor_sync(0xffffffffu, mx, 1));
                mx = fmaxf(mx, __shfl_xor_sync(0xffffffffu, mx, 2));
                float mn = fmaxf(mrow[r], mx);
                float al = ex2f(mrow[r] - mn);
                mrow[r] = mn;
                float rs = 0.0f;
#pragma unroll
                for (int nt = 0; nt < 8; ++nt) {
                    float p0 = ex2f(sacc[nt][2 * r] - mn);
                    float p1 = ex2f(sacc[nt][2 * r + 1] - mn);
                    sacc[nt][2 * r] = p0;
                    sacc[nt][2 * r + 1] = p1;
                    rs += p0 + p1;
                }
                rs += __shfl_xor_sync(0xffffffffu, rs, 1);
                rs += __shfl_xor_sync(0xffffffffu, rs, 2);
                lrow[r] = lrow[r] * al + rs;
#pragma unroll
                for (int nt = 0; nt < 16; ++nt) {
                    oacc[nt][2 * r]     *= al;
                    oacc[nt][2 * r + 1] *= al;
                }
            }

#pragma unroll
            for (int j = 0; j < 4; ++j) {
                uint32_t a[4];
                a[0] = packh2(sacc[2 * j][0],     sacc[2 * j][1]);
                a[1] = packh2(sacc[2 * j][2],     sacc[2 * j][3]);
                a[2] = packh2(sacc[2 * j + 1][0], sacc[2 * j + 1][1]);
                a[3] = packh2(sacc[2 * j + 1][2], sacc[2 * j + 1][3]);
#pragma unroll
                for (int dp = 0; dp < 8; ++dp) {
                    uint32_t bf[4];
                    ldsm_x4_t(bf, va + j * 16 * (FA_STR * 2) + dp * 32);
                    mma16816h(oacc[dp * 2],     a, bf);
                    mma16816h(oacc[dp * 2 + 1], a, bf + 2);
                }
            }
        }
    }

#pragma unroll
    for (int r = 0; r < 2; ++r) {
        float inv = 1.0f / lrow[r];
        int row = q0 + wq0 + (lane >> 2) + r * 8;
        float* Og = O + (size_t)(b * Ss_ + row) * Dd_ + h * HD_;
#pragma unroll
        for (int nt = 0; nt < 16; ++nt) {
            int col = nt * 8 + (lane & 3) * 2;
            *(float2*)(Og + col) =
                make_float2(oacc[nt][2 * r] * inv, oacc[nt][2 * r + 1] * inv);
        }
    }
}

// ---------------------------------------------------------------------------
// Launch
// ---------------------------------------------------------------------------
extern "C" void kernel_launch(void* const* d_in, const int* in_sizes, int n_in,
                              void* d_out, int out_size)
{
    const float* x  = (const float*)d_in[0];
    const float* Wq = (const float*)d_in[2];
    const float* Wk = (const float*)d_in[3];
    const float* Wv = (const float*)d_in[4];
    const float* Wo = (const float*)d_in[5];
    float* out = (float*)d_out;

    float *Qp, *KVp, *Op;
    __nv_bfloat16 *Ahp, *Alp, *Bhp, *Blp;
    __half *Qhp, *Khp, *Vhp;
    cudaGetSymbolAddress((void**)&Qp, g_Q);
    cudaGetSymbolAddress((void**)&KVp, g_KV);
    cudaGetSymbolAddress((void**)&Op, g_O);
    cudaGetSymbolAddress((void**)&Ahp, g_Ah);
    cudaGetSymbolAddress((void**)&Alp, g_Al);
    cudaGetSymbolAddress((void**)&Bhp, g_Bh);
    cudaGetSymbolAddress((void**)&Blp, g_Bl);
    cudaGetSymbolAddress((void**)&Qhp, g_Qh);
    cudaGetSymbolAddress((void**)&Khp, g_Kh);
    cudaGetSymbolAddress((void**)&Vhp, g_Vh);

    cudaFuncSetAttribute(gemm_tc, cudaFuncAttributeMaxDynamicSharedMemorySize,
                         GEMM_SMEM_BYTES);
    cudaFuncSetAttribute(flash_tc, cudaFuncAttributeMaxDynamicSharedMemorySize,
                         FA_SMEM);

    const int nX  = MROWS * Dd_;       // 8.4M
    const int nWq = Dd_ * Dd_;         // 4.2M
    const int nWk = Dd_ * NKV;         // 0.5M

    // x -> bf16 hi/lo (A side)
    convert_split_k<<<nX / 1024, 256>>>(x, Ahp, Alp, nX);

    // Q = x @ Wq
    convert_split_k<<<nWq / 1024, 256>>>(Wq, Bhp, Blp, nWq);
    gemm_tc<<<dim3(Dd_ / 128, MROWS / 128), 256, GEMM_SMEM_BYTES>>>(
        Ahp, Alp, Bhp, Blp, Qp, MROWS, Dd_, Dd_);

    // KV = x @ [Wk | Wv]  (combined N=512 GEMM)
    convert_split_strided<<<nWk / 1024, 256>>>(Wk, Bhp, Blp, NKV, NKV2, 0, nWk);
    convert_split_strided<<<nWk / 1024, 256>>>(Wv, Bhp, Blp, NKV, NKV2, NKV, nWk);
    gemm_tc<<<dim3(NKV2 / 128, MROWS / 128), 256, GEMM_SMEM_BYTES>>>(
        Ahp, Alp, Bhp, Blp, KVp, MROWS, NKV2, Dd_);

    // RoPE + fp16 convert (fused); V straight convert
    const float qmult = 1.4426950408889634f / sqrtf((float)HD_);
    {
        int totq = MROWS * Hh_ * 64;
        rope_half_k<<<(totq + 255) / 256, 256>>>(Qp, Qhp, Hh_, Dd_, Dd_, qmult, totq);
        int totk = MROWS * HKV_ * 64;
        rope_half_k<<<(totk + 255) / 256, 256>>>(KVp, Khp, HKV_, NKV2, NKV, 1.0f, totk);
        int nV = MROWS * NKV;
        convert_half_strided<<<nV / 2048, 256>>>(KVp + NKV, Vhp, NKV, NKV2, nV);
    }

    // Flash attention (tensor cores)
    flash_tc<<<dim3(Ss_ / FA_BQ, Hh_, Bb_), 256, FA_SMEM>>>(Qhp, Khp, Vhp, Op);

    // out = O @ Wo
    convert_split_k<<<nX / 1024, 256>>>(Op, Ahp, Alp, nX);
    convert_split_k<<<nWq / 1024, 256>>>(Wo, Bhp, Blp, nWq);
    gemm_tc<<<dim3(Dd_ / 128, MROWS / 128), 256, GEMM_SMEM_BYTES>>>(
        Ahp, Alp, Bhp, Blp, out, MROWS, Dd_, Dd_);
}

// round 9
// speedup vs baseline: 1.4940x; 1.4090x over previous
#include <cuda_runtime.h>
#include <cuda_fp16.h>
#include <math.h>
#include <stdint.h>

// Problem constants
#define Bb_ 2
#define Ss_ 2048
#define Dd_ 2048
#define Hh_ 16
#define HKV_ 2
#define HD_ 128
#define MROWS (Bb_ * Ss_)          // 4096
#define NKV (HKV_ * HD_)           // 256
#define NKV2 512                   // combined K|V projection width

// Scratch (allocation-free: __device__ globals)
__device__ float g_Q[(size_t)MROWS * Dd_];
__device__ float g_KV[(size_t)MROWS * NKV2];     // cols 0-255 = K, 256-511 = V
__device__ __half g_Xh[(size_t)MROWS * Dd_];     // x as fp16 (A side)
__device__ __half g_Oh[(size_t)MROWS * Dd_];     // attn out as fp16 (A side)
__device__ __half g_WBh[(size_t)Dd_ * Dd_];      // weight hi (B side)
__device__ __half g_WBl[(size_t)Dd_ * Dd_];      // weight lo (B side)
__device__ __half g_Qh[(size_t)MROWS * Dd_];
__device__ __half g_Kh[(size_t)MROWS * NKV];
__device__ __half g_Vh[(size_t)MROWS * NKV];

// ---------------------------------------------------------------------------
// Helpers
// ---------------------------------------------------------------------------
static __device__ __forceinline__ uint32_t smem_u32(const void* p) {
    uint32_t r;
    asm("{ .reg .u64 t; cvta.to.shared.u64 t, %1; cvt.u32.u64 %0, t; }"
        : "=r"(r) : "l"(p));
    return r;
}

static __device__ __forceinline__ void mma16816h(float* c, const uint32_t* a,
                                                 const uint32_t* b) {
    asm volatile(
        "mma.sync.aligned.m16n8k16.row.col.f32.f16.f16.f32 "
        "{%0,%1,%2,%3}, {%4,%5,%6,%7}, {%8,%9}, {%0,%1,%2,%3};"
        : "+f"(c[0]), "+f"(c[1]), "+f"(c[2]), "+f"(c[3])
        : "r"(a[0]), "r"(a[1]), "r"(a[2]), "r"(a[3]), "r"(b[0]), "r"(b[1]));
}

static __device__ __forceinline__ void ldsm_x4(uint32_t* r, uint32_t addr) {
    asm volatile("ldmatrix.sync.aligned.m8n8.x4.shared.b16 {%0,%1,%2,%3}, [%4];"
                 : "=r"(r[0]), "=r"(r[1]), "=r"(r[2]), "=r"(r[3]) : "r"(addr));
}

static __device__ __forceinline__ void ldsm_x4_t(uint32_t* r, uint32_t addr) {
    asm volatile("ldmatrix.sync.aligned.m8n8.x4.trans.shared.b16 {%0,%1,%2,%3}, [%4];"
                 : "=r"(r[0]), "=r"(r[1]), "=r"(r[2]), "=r"(r[3]) : "r"(addr));
}

static __device__ __forceinline__ void ldsm_x2_t(uint32_t* r, uint32_t addr) {
    asm volatile("ldmatrix.sync.aligned.m8n8.x2.trans.shared.b16 {%0,%1}, [%2];"
                 : "=r"(r[0]), "=r"(r[1]) : "r"(addr));
}

static __device__ __forceinline__ float ex2f(float x) {
    float y;
    asm("ex2.approx.f32 %0, %1;" : "=f"(y) : "f"(x));
    return y;
}

static __device__ __forceinline__ uint32_t packh2(float a, float b) {
    __half2 h = __floats2half2_rn(a, b);
    return *reinterpret_cast<uint32_t*>(&h);
}

#define CPA16(dst, src) \
    asm volatile("cp.async.cg.shared.global [%0], [%1], 16;" :: "r"(dst), "l"(src))
#define CP_COMMIT() asm volatile("cp.async.commit_group;" ::: "memory")
#define CP_WAIT1() asm volatile("cp.async.wait_group 1;" ::: "memory")
#define CP_WAIT0() asm volatile("cp.async.wait_group 0;" ::: "memory")

// Split a pair of floats into packed fp16x2 hi + lo residual
static __device__ __forceinline__ void split2h(float a, float b,
                                               uint32_t& hi, uint32_t& lo) {
    __half2 h = __floats2half2_rn(a, b);
    float ra = a - __half2float(h.x);
    float rb = b - __half2float(h.y);
    __half2 l = __floats2half2_rn(ra, rb);
    hi = *reinterpret_cast<uint32_t*>(&h);
    lo = *reinterpret_cast<uint32_t*>(&l);
}

// fp32 -> fp16 hi/lo split (contiguous)
__global__ void convert_splitH_k(const float* __restrict__ in,
                                 __half* __restrict__ hi,
                                 __half* __restrict__ lo, int n)
{
    int i = (blockIdx.x * blockDim.x + threadIdx.x) * 4;
    if (i >= n) return;
    float4 v = *(const float4*)(in + i);
    uint32_t h0, l0, h1, l1;
    split2h(v.x, v.y, h0, l0);
    split2h(v.z, v.w, h1, l1);
    *(uint2*)(hi + i) = make_uint2(h0, h1);
    *(uint2*)(lo + i) = make_uint2(l0, l1);
}

// fp32 [r][cols] -> fp16 hi/lo placed at [r][coloff + c] with row stride ldout
__global__ void convert_splitH_strided(const float* __restrict__ in,
                                       __half* __restrict__ hi,
                                       __half* __restrict__ lo,
                                       int cols, int ldout, int coloff, int n)
{
    int i = (blockIdx.x * blockDim.x + threadIdx.x) * 4;
    if (i >= n) return;
    int r = i / cols, c = i % cols;
    float4 v = *(const float4*)(in + i);
    uint32_t h0, l0, h1, l1;
    split2h(v.x, v.y, h0, l0);
    split2h(v.z, v.w, h1, l1);
    size_t off = (size_t)r * ldout + coloff + c;
    *(uint2*)(hi + off) = make_uint2(h0, h1);
    *(uint2*)(lo + off) = make_uint2(l0, l1);
}

// fp32 -> fp16 (contiguous, optional multiplier)
__global__ void convert_half_k(const float* __restrict__ in,
                               __half* __restrict__ out, int n, float mult)
{
    int i = (blockIdx.x * blockDim.x + threadIdx.x) * 8;
    if (i >= n) return;
    float4 a = *(const float4*)(in + i);
    float4 b = *(const float4*)(in + i + 4);
    uint4 o;
    o.x = packh2(a.x * mult, a.y * mult);
    o.y = packh2(a.z * mult, a.w * mult);
    o.z = packh2(b.x * mult, b.y * mult);
    o.w = packh2(b.z * mult, b.w * mult);
    *(uint4*)(out + i) = o;
}

// RoPE + scale + fp16 convert, separate in/out buffers with strides
__global__ void rope_half_k(const float* __restrict__ in, __half* __restrict__ out,
                            int nh, int ld_in, int ld_out, float mult, int total)
{
    int idx = blockIdx.x * blockDim.x + threadIdx.x;
    if (idx >= total) return;
    int i    = idx & 63;
    int hh   = (idx >> 6) % nh;
    int srow = idx / (64 * nh);
    int pos  = srow & (Ss_ - 1);

    float inv = (float)exp(-(double)i * (log(10000.0) / 64.0));
    float ang = (float)pos * inv;
    float sn, cs;
    sincosf(ang, &sn, &cs);

    size_t bi = (size_t)srow * ld_in + (size_t)hh * HD_ + i;
    size_t bo = (size_t)srow * ld_out + (size_t)hh * HD_ + i;
    float x1 = in[bi];
    float x2 = in[bi + 64];
    out[bo]      = __float2half((x1 * cs - x2 * sn) * mult);
    out[bo + 64] = __float2half((x2 * cs + x1 * sn) * mult);
}

// fp32 strided [r][ld_in] (cols window) -> fp16 dense [r][cols]
__global__ void convert_half_strided(const float* __restrict__ in,
                                     __half* __restrict__ out,
                                     int cols, int ld_in, int n)
{
    int i = (blockIdx.x * blockDim.x + threadIdx.x) * 8;
    if (i >= n) return;
    int r = i / cols, c = i % cols;
    const float* src = in + (size_t)r * ld_in + c;
    float4 a = *(const float4*)src;
    float4 b = *(const float4*)(src + 4);
    uint4 o;
    o.x = packh2(a.x, a.y);
    o.y = packh2(a.z, a.w);
    o.z = packh2(b.x, b.y);
    o.w = packh2(b.z, b.w);
    *(uint4*)(out + (size_t)r * cols + c) = o;
}

// ---------------------------------------------------------------------------
// fp16x2 tensor-core GEMM: C = Ah @ (Bh + Bl), fp32 accumulate.
// A fp16 (single), B fp16 hi/lo. CTA 128x128, BK=64, 8 warps (2m x 4n).
// cp.async 2-stage pipeline; 2 CTAs/SM (52KB/stage).
// ---------------------------------------------------------------------------
#define SA_STRIDE 72
#define SB_STRIDE 136
#define SA_SZ (128 * SA_STRIDE)               // 9216 halves
#define SB_SZ (64 * SB_STRIDE)                // 8704 halves
#define STG_BYTES ((SA_SZ + 2 * SB_SZ) * 2)   // 53248
#define GEMM_SMEM_BYTES (2 * STG_BYTES)       // 106496

__global__ __launch_bounds__(256, 2) void gemm_f16x2(const __half* __restrict__ Ah,
                                                     const __half* __restrict__ Bh,
                                                     const __half* __restrict__ Bl,
                                                     float* __restrict__ C,
                                                     int M, int N, int K)
{
    extern __shared__ __half smh[];
    const uint32_t sbase = smem_u32(smh);

    const int t    = threadIdx.x;
    const int lane = t & 31;
    const int wid  = t >> 5;
    const int wm   = wid & 1;
    const int wn   = wid >> 1;
    const int n0   = blockIdx.x * 128;
    const int m0   = blockIdx.y * 128;

    float acc[4][4][4];
#pragma unroll
    for (int i = 0; i < 4; ++i)
#pragma unroll
        for (int j = 0; j < 4; ++j)
#pragma unroll
            for (int k = 0; k < 4; ++k) acc[i][j][k] = 0.0f;

    auto load_stage = [&](int c, int buf) {
        const int k0 = c << 6;
        const uint32_t sb = sbase + (uint32_t)buf * STG_BYTES;
#pragma unroll
        for (int i = 0; i < 4; ++i) {                 // A: 1024 vec16
            int li = t + 256 * i;
            int row = li >> 3, v = li & 7;
            const size_t g = (size_t)(m0 + row) * K + k0 + v * 8;
            uint32_t s = sb + (uint32_t)(row * SA_STRIDE + v * 8) * 2;
            CPA16(s, Ah + g);
        }
#pragma unroll
        for (int i = 0; i < 4; ++i) {                 // B hi+lo: 1024 vec16 each
            int li = t + 256 * i;
            int row = li >> 4, v = li & 15;
            const size_t g = (size_t)(k0 + row) * N + n0 + v * 8;
            uint32_t s = sb + (uint32_t)(SA_SZ + row * SB_STRIDE + v * 8) * 2;
            CPA16(s, Bh + g);
            CPA16(s + SB_SZ * 2, Bl + g);
        }
    };

    const uint32_t a_rel =
        (uint32_t)(((lane & 7) + ((lane >> 3) & 1) * 8 + wm * 64) * (SA_STRIDE * 2)) +
        (uint32_t)(((lane >> 4) & 1) * 16);
    const uint32_t b_rel = (uint32_t)(SA_SZ * 2) +
        (uint32_t)(((lane & 7) + ((lane >> 3) & 1) * 8) * (SB_STRIDE * 2)) +
        (uint32_t)(wn * 64);
    const uint32_t B_LO = SB_SZ * 2;

    const int nch = K >> 6;
    load_stage(0, 0);
    CP_COMMIT();

    for (int c = 0; c < nch; ++c) {
        const int buf = c & 1;
        if (c + 1 < nch) {
            load_stage(c + 1, (c + 1) & 1);
            CP_COMMIT();
            CP_WAIT1();
        } else {
            CP_WAIT0();
        }
        __syncthreads();

        const uint32_t stg = sbase + (uint32_t)buf * STG_BYTES;
        const uint32_t a_addr = stg + a_rel;
        const uint32_t b_addr = stg + b_rel;

#pragma unroll
        for (int k16 = 0; k16 < 4; ++k16) {
            uint32_t bh[4][2], bl[4][2], af[4][4];
            const uint32_t bko = (uint32_t)(k16 * 16 * SB_STRIDE * 2);
#pragma unroll
            for (int nt = 0; nt < 4; ++nt) {
                ldsm_x2_t(bh[nt], b_addr + nt * 16 + bko);
                ldsm_x2_t(bl[nt], b_addr + B_LO + nt * 16 + bko);
            }
            const uint32_t ako = (uint32_t)(k16 * 32);
#pragma unroll
            for (int mt = 0; mt < 4; ++mt)
                ldsm_x4(af[mt], a_addr + mt * (16 * SA_STRIDE * 2) + ako);
#pragma unroll
            for (int mt = 0; mt < 4; ++mt)
#pragma unroll
                for (int nt = 0; nt < 4; ++nt) {
                    mma16816h(acc[mt][nt], af[mt], bh[nt]);
                    mma16816h(acc[mt][nt], af[mt], bl[nt]);
                }
        }
        __syncthreads();
    }

    const int g   = lane >> 2;
    const int tid = lane & 3;
#pragma unroll
    for (int mt = 0; mt < 4; ++mt) {
        const int row = m0 + wm * 64 + mt * 16 + g;
#pragma unroll
        for (int nt = 0; nt < 4; ++nt) {
            const int col = n0 + wn * 32 + nt * 8 + tid * 2;
            *(float2*)(C + (size_t)row * N + col) =
                make_float2(acc[mt][nt][0], acc[mt][nt][1]);
            *(float2*)(C + (size_t)(row + 8) * N + col) =
                make_float2(acc[mt][nt][2], acc[mt][nt][3]);
        }
    }
}

// ---------------------------------------------------------------------------
// Tensor-core causal flash attention (validated R7); epilogue now writes fp16.
// ---------------------------------------------------------------------------
#define FA_BQ 128
#define FA_BK 64
#define FA_STR 136
#define FA_SMEM ((FA_BQ + 2 * FA_BK) * FA_STR * 2)

__global__ __launch_bounds__(256) void flash_tc(const __half* __restrict__ Qh,
                                                const __half* __restrict__ Kh,
                                                const __half* __restrict__ Vh,
                                                __half* __restrict__ Oh)
{
    extern __shared__ __half sh[];
    __half* Qs = sh;
    __half* Ks = Qs + FA_BQ * FA_STR;
    __half* Vs = Ks + FA_BK * FA_STR;

    const int qb = blockIdx.x, h = blockIdx.y, b = blockIdx.z;
    const int kvh = h % HKV_;
    const int t = threadIdx.x, lane = t & 31, w = t >> 5;
    const int q0 = qb * FA_BQ;
    const int wq0 = w * 16;

    {
#pragma unroll
        for (int i = 0; i < 8; ++i) {
            int linear = t + 256 * i;
            int row = linear >> 4;
            int c8 = (linear & 15) * 8;
            *(uint4*)&Qs[row * FA_STR + c8] =
                *(const uint4*)(Qh + (size_t)(b * Ss_ + q0 + row) * Dd_ + h * HD_ + c8);
        }
    }

    float oacc[16][4];
#pragma unroll
    for (int i = 0; i < 16; ++i)
#pragma unroll
        for (int j = 0; j < 4; ++j) oacc[i][j] = 0.0f;
    float mrow[2] = {-INFINITY, -INFINITY};
    float lrow[2] = {0.0f, 0.0f};

    const uint32_t qa = smem_u32(Qs) +
        (uint32_t)((wq0 + (lane & 15)) * (FA_STR * 2)) +
        (uint32_t)(((lane >> 4) & 1) * 16);
    const uint32_t ka = smem_u32(Ks) +
        (uint32_t)(((lane & 7) + ((lane >> 4) & 1) * 8) * (FA_STR * 2)) +
        (uint32_t)(((lane >> 3) & 1) * 16);
    const uint32_t va = smem_u32(Vs) +
        (uint32_t)(((lane & 7) + ((lane >> 3) & 1) * 8) * (FA_STR * 2)) +
        (uint32_t)(((lane >> 4) & 1) * 16);

    const int nkb = (q0 + FA_BQ) / FA_BK;
    for (int kb = 0; kb < nkb; ++kb) {
        const int k0 = kb * FA_BK;
        __syncthreads();
        {
#pragma unroll
            for (int i = 0; i < 4; ++i) {
                int linear = t + 256 * i;
                int row = linear >> 4;
                int c8 = (linear & 15) * 8;
                size_t g = (size_t)(b * Ss_ + k0 + row) * NKV + kvh * HD_ + c8;
                *(uint4*)&Ks[row * FA_STR + c8] = *(const uint4*)(Kh + g);
                *(uint4*)&Vs[row * FA_STR + c8] = *(const uint4*)(Vh + g);
            }
        }
        __syncthreads();

        if (k0 <= q0 + wq0 + 15) {
            float sacc[8][4];
#pragma unroll
            for (int i = 0; i < 8; ++i)
#pragma unroll
                for (int j = 0; j < 4; ++j) sacc[i][j] = 0.0f;

#pragma unroll
            for (int kk = 0; kk < 8; ++kk) {
                uint32_t af[4];
                ldsm_x4(af, qa + kk * 32);
#pragma unroll
                for (int np = 0; np < 4; ++np) {
                    uint32_t bf[4];
                    ldsm_x4(bf, ka + np * 16 * (FA_STR * 2) + kk * 32);
                    mma16816h(sacc[np * 2],     af, bf);
                    mma16816h(sacc[np * 2 + 1], af, bf + 2);
                }
            }

            if (k0 + FA_BK - 1 > q0 + wq0) {
                const int rbase = q0 + wq0 + (lane >> 2);
                const int cbase = k0 + (lane & 3) * 2;
#pragma unroll
                for (int nt = 0; nt < 8; ++nt)
#pragma unroll
                    for (int e = 0; e < 4; ++e) {
                        int col = cbase + nt * 8 + (e & 1);
                        int row = rbase + (e >> 1) * 8;
                        if (col > row) sacc[nt][e] = -INFINITY;
                    }
            }

#pragma unroll
            for (int r = 0; r < 2; ++r) {
                float mx = -INFINITY;
#pragma unroll
                for (int nt = 0; nt < 8; ++nt)
                    mx = fmaxf(mx, fmaxf(sacc[nt][2 * r], sacc[nt][2 * r + 1]));
                mx = fmaxf(mx, __shfl_xor_sync(0xffffffffu, mx, 1));
                mx = fmaxf(mx, __shfl_xor_sync(0xffffffffu, mx, 2));
                float mn = fmaxf(mrow[r], mx);
                float al = ex2f(mrow[r] - mn);
                mrow[r] = mn;
                float rs = 0.0f;
#pragma unroll
                for (int nt = 0; nt < 8; ++nt) {
                    float p0 = ex2f(sacc[nt][2 * r] - mn);
                    float p1 = ex2f(sacc[nt][2 * r + 1] - mn);
                    sacc[nt][2 * r] = p0;
                    sacc[nt][2 * r + 1] = p1;
                    rs += p0 + p1;
                }
                rs += __shfl_xor_sync(0xffffffffu, rs, 1);
                rs += __shfl_xor_sync(0xffffffffu, rs, 2);
                lrow[r] = lrow[r] * al + rs;
#pragma unroll
                for (int nt = 0; nt < 16; ++nt) {
                    oacc[nt][2 * r]     *= al;
                    oacc[nt][2 * r + 1] *= al;
                }
            }

#pragma unroll
            for (int j = 0; j < 4; ++j) {
                uint32_t a[4];
                a[0] = packh2(sacc[2 * j][0],     sacc[2 * j][1]);
                a[1] = packh2(sacc[2 * j][2],     sacc[2 * j][3]);
                a[2] = packh2(sacc[2 * j + 1][0], sacc[2 * j + 1][1]);
                a[3] = packh2(sacc[2 * j + 1][2], sacc[2 * j + 1][3]);
#pragma unroll
                for (int dp = 0; dp < 8; ++dp) {
                    uint32_t bf[4];
                    ldsm_x4_t(bf, va + j * 16 * (FA_STR * 2) + dp * 32);
                    mma16816h(oacc[dp * 2],     a, bf);
                    mma16816h(oacc[dp * 2 + 1], a, bf + 2);
                }
            }
        }
    }

    // Epilogue: normalize, write fp16 (A operand of the Wo GEMM)
#pragma unroll
    for (int r = 0; r < 2; ++r) {
        float inv = 1.0f / lrow[r];
        int row = q0 + wq0 + (lane >> 2) + r * 8;
        __half* Og = Oh + (size_t)(b * Ss_ + row) * Dd_ + h * HD_;
#pragma unroll
        for (int nt = 0; nt < 16; ++nt) {
            int col = nt * 8 + (lane & 3) * 2;
            *(uint32_t*)(Og + col) =
                packh2(oacc[nt][2 * r] * inv, oacc[nt][2 * r + 1] * inv);
        }
    }
}

// ---------------------------------------------------------------------------
// Launch
// ---------------------------------------------------------------------------
extern "C" void kernel_launch(void* const* d_in, const int* in_sizes, int n_in,
                              void* d_out, int out_size)
{
    const float* x  = (const float*)d_in[0];
    const float* Wq = (const float*)d_in[2];
    const float* Wk = (const float*)d_in[3];
    const float* Wv = (const float*)d_in[4];
    const float* Wo = (const float*)d_in[5];
    float* out = (float*)d_out;

    float *Qp, *KVp;
    __half *Xhp, *Ohp, *WBhp, *WBlp, *Qhp, *Khp, *Vhp;
    cudaGetSymbolAddress((void**)&Qp, g_Q);
    cudaGetSymbolAddress((void**)&KVp, g_KV);
    cudaGetSymbolAddress((void**)&Xhp, g_Xh);
    cudaGetSymbolAddress((void**)&Ohp, g_Oh);
    cudaGetSymbolAddress((void**)&WBhp, g_WBh);
    cudaGetSymbolAddress((void**)&WBlp, g_WBl);
    cudaGetSymbolAddress((void**)&Qhp, g_Qh);
    cudaGetSymbolAddress((void**)&Khp, g_Kh);
    cudaGetSymbolAddress((void**)&Vhp, g_Vh);

    cudaFuncSetAttribute(gemm_f16x2, cudaFuncAttributeMaxDynamicSharedMemorySize,
                         GEMM_SMEM_BYTES);
    cudaFuncSetAttribute(flash_tc, cudaFuncAttributeMaxDynamicSharedMemorySize,
                         FA_SMEM);

    const int nX  = MROWS * Dd_;       // 8.4M
    const int nWq = Dd_ * Dd_;         // 4.2M
    const int nWk = Dd_ * NKV;         // 0.5M

    // x -> fp16 (A side, single precision pass)
    convert_half_k<<<nX / 2048, 256>>>(x, Xhp, nX, 1.0f);

    // Q = x @ Wq
    convert_splitH_k<<<nWq / 1024, 256>>>(Wq, WBhp, WBlp, nWq);
    gemm_f16x2<<<dim3(Dd_ / 128, MROWS / 128), 256, GEMM_SMEM_BYTES>>>(
        Xhp, WBhp, WBlp, Qp, MROWS, Dd_, Dd_);

    // KV = x @ [Wk | Wv]  (combined N=512 GEMM)
    convert_splitH_strided<<<nWk / 1024, 256>>>(Wk, WBhp, WBlp, NKV, NKV2, 0, nWk);
    convert_splitH_strided<<<nWk / 1024, 256>>>(Wv, WBhp, WBlp, NKV, NKV2, NKV, nWk);
    gemm_f16x2<<<dim3(NKV2 / 128, MROWS / 128), 256, GEMM_SMEM_BYTES>>>(
        Xhp, WBhp, WBlp, KVp, MROWS, NKV2, Dd_);

    // RoPE + fp16 convert (fused); V straight convert
    const float qmult = 1.4426950408889634f / sqrtf((float)HD_);
    {
        int totq = MROWS * Hh_ * 64;
        rope_half_k<<<(totq + 255) / 256, 256>>>(Qp, Qhp, Hh_, Dd_, Dd_, qmult, totq);
        int totk = MROWS * HKV_ * 64;
        rope_half_k<<<(totk + 255) / 256, 256>>>(KVp, Khp, HKV_, NKV2, NKV, 1.0f, totk);
        int nV = MROWS * NKV;
        convert_half_strided<<<nV / 2048, 256>>>(KVp + NKV, Vhp, NKV, NKV2, nV);
    }

    // Flash attention (tensor cores) -> fp16 O
    flash_tc<<<dim3(Ss_ / FA_BQ, Hh_, Bb_), 256, FA_SMEM>>>(Qhp, Khp, Vhp, Ohp);

    // out = O @ Wo
    convert_splitH_k<<<nWq / 1024, 256>>>(Wo, WBhp, WBlp, nWq);
    gemm_f16x2<<<dim3(Dd_ / 128, MROWS / 128), 256, GEMM_SMEM_BYTES>>>(
        Ohp, WBhp, WBlp, out, MROWS, Dd_, Dd_);
}

// round 10
// speedup vs baseline: 1.7852x; 1.1949x over previous
#include <cuda_runtime.h>
#include <cuda_fp16.h>
#include <math.h>
#include <stdint.h>

// Problem constants
#define Bb_ 2
#define Ss_ 2048
#define Dd_ 2048
#define Hh_ 16
#define HKV_ 2
#define HD_ 128
#define MROWS (Bb_ * Ss_)          // 4096
#define NKV (HKV_ * HD_)           // 256
#define NQKV 2560                  // Q(2048) | K(256) | V(256)
#define VOFF 2304                  // V column offset in QKV buffer

// Scratch (allocation-free: __device__ globals)
__device__ __half g_Xh[(size_t)MROWS * Dd_];        // x as fp16 (A side)
__device__ __half g_Wqkv[(size_t)Dd_ * NQKV];       // [Wq|Wk|Wv] fp16
__device__ __half g_QKV[(size_t)MROWS * NQKV];      // pre-rope QKV (fp16)
__device__ __half g_Qh[(size_t)MROWS * Dd_];        // post-rope Q
__device__ __half g_Kh[(size_t)MROWS * NKV];        // post-rope K
__device__ __half g_Oh[(size_t)MROWS * Dd_];        // attn out (A of Wo gemm)
__device__ __half g_WBh[(size_t)Dd_ * Dd_];         // Wo hi
__device__ __half g_WBl[(size_t)Dd_ * Dd_];         // Wo lo

// ---------------------------------------------------------------------------
// Helpers
// ---------------------------------------------------------------------------
static __device__ __forceinline__ uint32_t smem_u32(const void* p) {
    uint32_t r;
    asm("{ .reg .u64 t; cvta.to.shared.u64 t, %1; cvt.u32.u64 %0, t; }"
        : "=r"(r) : "l"(p));
    return r;
}

static __device__ __forceinline__ void mma16816h(float* c, const uint32_t* a,
                                                 const uint32_t* b) {
    asm volatile(
        "mma.sync.aligned.m16n8k16.row.col.f32.f16.f16.f32 "
        "{%0,%1,%2,%3}, {%4,%5,%6,%7}, {%8,%9}, {%0,%1,%2,%3};"
        : "+f"(c[0]), "+f"(c[1]), "+f"(c[2]), "+f"(c[3])
        : "r"(a[0]), "r"(a[1]), "r"(a[2]), "r"(a[3]), "r"(b[0]), "r"(b[1]));
}

static __device__ __forceinline__ void ldsm_x4(uint32_t* r, uint32_t addr) {
    asm volatile("ldmatrix.sync.aligned.m8n8.x4.shared.b16 {%0,%1,%2,%3}, [%4];"
                 : "=r"(r[0]), "=r"(r[1]), "=r"(r[2]), "=r"(r[3]) : "r"(addr));
}

static __device__ __forceinline__ void ldsm_x4_t(uint32_t* r, uint32_t addr) {
    asm volatile("ldmatrix.sync.aligned.m8n8.x4.trans.shared.b16 {%0,%1,%2,%3}, [%4];"
                 : "=r"(r[0]), "=r"(r[1]), "=r"(r[2]), "=r"(r[3]) : "r"(addr));
}

static __device__ __forceinline__ void ldsm_x2_t(uint32_t* r, uint32_t addr) {
    asm volatile("ldmatrix.sync.aligned.m8n8.x2.trans.shared.b16 {%0,%1}, [%2];"
                 : "=r"(r[0]), "=r"(r[1]) : "r"(addr));
}

static __device__ __forceinline__ float ex2f(float x) {
    float y;
    asm("ex2.approx.f32 %0, %1;" : "=f"(y) : "f"(x));
    return y;
}

static __device__ __forceinline__ uint32_t packh2(float a, float b) {
    __half2 h = __floats2half2_rn(a, b);
    return *reinterpret_cast<uint32_t*>(&h);
}

#define CPA16(dst, src) \
    asm volatile("cp.async.cg.shared.global [%0], [%1], 16;" :: "r"(dst), "l"(src))
#define CP_COMMIT() asm volatile("cp.async.commit_group;" ::: "memory")
#define CP_WAIT1() asm volatile("cp.async.wait_group 1;" ::: "memory")
#define CP_WAIT0() asm volatile("cp.async.wait_group 0;" ::: "memory")

static __device__ __forceinline__ void split2h(float a, float b,
                                               uint32_t& hi, uint32_t& lo) {
    __half2 h = __floats2half2_rn(a, b);
    float ra = a - __half2float(h.x);
    float rb = b - __half2float(h.y);
    __half2 l = __floats2half2_rn(ra, rb);
    hi = *reinterpret_cast<uint32_t*>(&h);
    lo = *reinterpret_cast<uint32_t*>(&l);
}

// fp32 -> fp16 hi/lo split (contiguous)
__global__ void convert_splitH_k(const float* __restrict__ in,
                                 __half* __restrict__ hi,
                                 __half* __restrict__ lo, int n)
{
    int i = (blockIdx.x * blockDim.x + threadIdx.x) * 4;
    if (i >= n) return;
    float4 v = *(const float4*)(in + i);
    uint32_t h0, l0, h1, l1;
    split2h(v.x, v.y, h0, l0);
    split2h(v.z, v.w, h1, l1);
    *(uint2*)(hi + i) = make_uint2(h0, h1);
    *(uint2*)(lo + i) = make_uint2(l0, l1);
}

// fp32 -> fp16 (contiguous)
__global__ void convert_half_k(const float* __restrict__ in,
                               __half* __restrict__ out, int n)
{
    int i = (blockIdx.x * blockDim.x + threadIdx.x) * 8;
    if (i >= n) return;
    float4 a = *(const float4*)(in + i);
    float4 b = *(const float4*)(in + i + 4);
    uint4 o;
    o.x = packh2(a.x, a.y);
    o.y = packh2(a.z, a.w);
    o.z = packh2(b.x, b.y);
    o.w = packh2(b.z, b.w);
    *(uint4*)(out + i) = o;
}

// fp32 dense [r][cols] -> fp16 at [r][coloff + c] with row stride ldout
__global__ void convert_half_to_strided(const float* __restrict__ in,
                                        __half* __restrict__ out,
                                        int cols, int ldout, int coloff, int n)
{
    int i = (blockIdx.x * blockDim.x + threadIdx.x) * 4;
    if (i >= n) return;
    int r = i / cols, c = i % cols;
    float4 v = *(const float4*)(in + i);
    uint2 o;
    o.x = packh2(v.x, v.y);
    o.y = packh2(v.z, v.w);
    *(uint2*)(out + (size_t)r * ldout + coloff + c) = o;
}

// RoPE fp16 -> fp16 (math in fp32), strided in/out
__global__ void rope_h2h(const __half* __restrict__ in, __half* __restrict__ out,
                         int nh, int ld_in, int ld_out, float mult, int total)
{
    int idx = blockIdx.x * blockDim.x + threadIdx.x;
    if (idx >= total) return;
    int i    = idx & 63;
    int hh   = (idx >> 6) % nh;
    int srow = idx / (64 * nh);
    int pos  = srow & (Ss_ - 1);

    float inv = (float)exp(-(double)i * (log(10000.0) / 64.0));
    float ang = (float)pos * inv;
    float sn, cs;
    sincosf(ang, &sn, &cs);

    size_t bi = (size_t)srow * ld_in + (size_t)hh * HD_ + i;
    size_t bo = (size_t)srow * ld_out + (size_t)hh * HD_ + i;
    float x1 = __half2float(in[bi]);
    float x2 = __half2float(in[bi + 64]);
    out[bo]      = __float2half((x1 * cs - x2 * sn) * mult);
    out[bo + 64] = __float2half((x2 * cs + x1 * sn) * mult);
}

// ---------------------------------------------------------------------------
// Shared GEMM geometry: CTA 128x128, BK=64, 8 warps (2m x 4n, 64x32 each)
// ---------------------------------------------------------------------------
#define SA_STRIDE 72
#define SB_STRIDE 136
#define SA_SZ (128 * SA_STRIDE)               // 9216 halves
#define SB_SZ (64 * SB_STRIDE)                // 8704 halves

// ---- single-pass fp16 GEMM, fp16 output (QKV projections) ----
#define STG1_BYTES ((SA_SZ + SB_SZ) * 2)      // 35840
#define G1_SMEM (2 * STG1_BYTES)              // 71680

__global__ __launch_bounds__(256, 2) void gemm_f16x1(const __half* __restrict__ Ah,
                                                     const __half* __restrict__ Bh,
                                                     __half* __restrict__ C,
                                                     int M, int N, int K)
{
    extern __shared__ __half smh[];
    const uint32_t sbase = smem_u32(smh);

    const int t    = threadIdx.x;
    const int lane = t & 31;
    const int wid  = t >> 5;
    const int wm   = wid & 1;
    const int wn   = wid >> 1;
    const int n0   = blockIdx.x * 128;
    const int m0   = blockIdx.y * 128;

    float acc[4][4][4];
#pragma unroll
    for (int i = 0; i < 4; ++i)
#pragma unroll
        for (int j = 0; j < 4; ++j)
#pragma unroll
            for (int k = 0; k < 4; ++k) acc[i][j][k] = 0.0f;

    auto load_stage = [&](int c, int buf) {
        const int k0 = c << 6;
        const uint32_t sb = sbase + (uint32_t)buf * STG1_BYTES;
#pragma unroll
        for (int i = 0; i < 4; ++i) {
            int li = t + 256 * i;
            int row = li >> 3, v = li & 7;
            const size_t g = (size_t)(m0 + row) * K + k0 + v * 8;
            CPA16(sb + (uint32_t)(row * SA_STRIDE + v * 8) * 2, Ah + g);
        }
#pragma unroll
        for (int i = 0; i < 4; ++i) {
            int li = t + 256 * i;
            int row = li >> 4, v = li & 15;
            const size_t g = (size_t)(k0 + row) * N + n0 + v * 8;
            CPA16(sb + (uint32_t)(SA_SZ + row * SB_STRIDE + v * 8) * 2, Bh + g);
        }
    };

    const uint32_t a_rel =
        (uint32_t)(((lane & 7) + ((lane >> 3) & 1) * 8 + wm * 64) * (SA_STRIDE * 2)) +
        (uint32_t)(((lane >> 4) & 1) * 16);
    const uint32_t b_rel = (uint32_t)(SA_SZ * 2) +
        (uint32_t)(((lane & 7) + ((lane >> 3) & 1) * 8) * (SB_STRIDE * 2)) +
        (uint32_t)(wn * 64);

    const int nch = K >> 6;
    load_stage(0, 0);
    CP_COMMIT();

    for (int c = 0; c < nch; ++c) {
        const int buf = c & 1;
        if (c + 1 < nch) {
            load_stage(c + 1, (c + 1) & 1);
            CP_COMMIT();
            CP_WAIT1();
        } else {
            CP_WAIT0();
        }
        __syncthreads();

        const uint32_t stg = sbase + (uint32_t)buf * STG1_BYTES;
        const uint32_t a_addr = stg + a_rel;
        const uint32_t b_addr = stg + b_rel;

#pragma unroll
        for (int k16 = 0; k16 < 4; ++k16) {
            uint32_t bh[4][2], af[4][4];
            const uint32_t bko = (uint32_t)(k16 * 16 * SB_STRIDE * 2);
#pragma unroll
            for (int nt = 0; nt < 4; ++nt)
                ldsm_x2_t(bh[nt], b_addr + nt * 16 + bko);
            const uint32_t ako = (uint32_t)(k16 * 32);
#pragma unroll
            for (int mt = 0; mt < 4; ++mt)
                ldsm_x4(af[mt], a_addr + mt * (16 * SA_STRIDE * 2) + ako);
#pragma unroll
            for (int mt = 0; mt < 4; ++mt)
#pragma unroll
                for (int nt = 0; nt < 4; ++nt)
                    mma16816h(acc[mt][nt], af[mt], bh[nt]);
        }
        __syncthreads();
    }

    const int g   = lane >> 2;
    const int tid = lane & 3;
#pragma unroll
    for (int mt = 0; mt < 4; ++mt) {
        const int row = m0 + wm * 64 + mt * 16 + g;
#pragma unroll
        for (int nt = 0; nt < 4; ++nt) {
            const int col = n0 + wn * 32 + nt * 8 + tid * 2;
            *(uint32_t*)(C + (size_t)row * N + col) =
                packh2(acc[mt][nt][0], acc[mt][nt][1]);
            *(uint32_t*)(C + (size_t)(row + 8) * N + col) =
                packh2(acc[mt][nt][2], acc[mt][nt][3]);
        }
    }
}

// ---- two-pass fp16 GEMM (B hi/lo), fp32 output (Wo projection) ----
#define STG2_BYTES ((SA_SZ + 2 * SB_SZ) * 2)   // 53248
#define G2_SMEM (2 * STG2_BYTES)               // 106496

__global__ __launch_bounds__(256, 2) void gemm_f16x2(const __half* __restrict__ Ah,
                                                     const __half* __restrict__ Bh,
                                                     const __half* __restrict__ Bl,
                                                     float* __restrict__ C,
                                                     int M, int N, int K)
{
    extern __shared__ __half smh[];
    const uint32_t sbase = smem_u32(smh);

    const int t    = threadIdx.x;
    const int lane = t & 31;
    const int wid  = t >> 5;
    const int wm   = wid & 1;
    const int wn   = wid >> 1;
    const int n0   = blockIdx.x * 128;
    const int m0   = blockIdx.y * 128;

    float acc[4][4][4];
#pragma unroll
    for (int i = 0; i < 4; ++i)
#pragma unroll
        for (int j = 0; j < 4; ++j)
#pragma unroll
            for (int k = 0; k < 4; ++k) acc[i][j][k] = 0.0f;

    auto load_stage = [&](int c, int buf) {
        const int k0 = c << 6;
        const uint32_t sb = sbase + (uint32_t)buf * STG2_BYTES;
#pragma unroll
        for (int i = 0; i < 4; ++i) {
            int li = t + 256 * i;
            int row = li >> 3, v = li & 7;
            const size_t g = (size_t)(m0 + row) * K + k0 + v * 8;
            CPA16(sb + (uint32_t)(row * SA_STRIDE + v * 8) * 2, Ah + g);
        }
#pragma unroll
        for (int i = 0; i < 4; ++i) {
            int li = t + 256 * i;
            int row = li >> 4, v = li & 15;
            const size_t g = (size_t)(k0 + row) * N + n0 + v * 8;
            uint32_t s = sb + (uint32_t)(SA_SZ + row * SB_STRIDE + v * 8) * 2;
            CPA16(s, Bh + g);
            CPA16(s + SB_SZ * 2, Bl + g);
        }
    };

    const uint32_t a_rel =
        (uint32_t)(((lane & 7) + ((lane >> 3) & 1) * 8 + wm * 64) * (SA_STRIDE * 2)) +
        (uint32_t)(((lane >> 4) & 1) * 16);
    const uint32_t b_rel = (uint32_t)(SA_SZ * 2) +
        (uint32_t)(((lane & 7) + ((lane >> 3) & 1) * 8) * (SB_STRIDE * 2)) +
        (uint32_t)(wn * 64);
    const uint32_t B_LO = SB_SZ * 2;

    const int nch = K >> 6;
    load_stage(0, 0);
    CP_COMMIT();

    for (int c = 0; c < nch; ++c) {
        const int buf = c & 1;
        if (c + 1 < nch) {
            load_stage(c + 1, (c + 1) & 1);
            CP_COMMIT();
            CP_WAIT1();
        } else {
            CP_WAIT0();
        }
        __syncthreads();

        const uint32_t stg = sbase + (uint32_t)buf * STG2_BYTES;
        const uint32_t a_addr = stg + a_rel;
        const uint32_t b_addr = stg + b_rel;

#pragma unroll
        for (int k16 = 0; k16 < 4; ++k16) {
            uint32_t bh[4][2], bl[4][2], af[4][4];
            const uint32_t bko = (uint32_t)(k16 * 16 * SB_STRIDE * 2);
#pragma unroll
            for (int nt = 0; nt < 4; ++nt) {
                ldsm_x2_t(bh[nt], b_addr + nt * 16 + bko);
                ldsm_x2_t(bl[nt], b_addr + B_LO + nt * 16 + bko);
            }
            const uint32_t ako = (uint32_t)(k16 * 32);
#pragma unroll
            for (int mt = 0; mt < 4; ++mt)
                ldsm_x4(af[mt], a_addr + mt * (16 * SA_STRIDE * 2) + ako);
#pragma unroll
            for (int mt = 0; mt < 4; ++mt)
#pragma unroll
                for (int nt = 0; nt < 4; ++nt) {
                    mma16816h(acc[mt][nt], af[mt], bh[nt]);
                    mma16816h(acc[mt][nt], af[mt], bl[nt]);
                }
        }
        __syncthreads();
    }

    const int g   = lane >> 2;
    const int tid = lane & 3;
#pragma unroll
    for (int mt = 0; mt < 4; ++mt) {
        const int row = m0 + wm * 64 + mt * 16 + g;
#pragma unroll
        for (int nt = 0; nt < 4; ++nt) {
            const int col = n0 + wn * 32 + nt * 8 + tid * 2;
            *(float2*)(C + (size_t)row * N + col) =
                make_float2(acc[mt][nt][0], acc[mt][nt][1]);
            *(float2*)(C + (size_t)(row + 8) * N + col) =
                make_float2(acc[mt][nt][2], acc[mt][nt][3]);
        }
    }
}

// ---------------------------------------------------------------------------
// Tensor-core causal flash attention (validated); V read strided from QKV buf.
// ---------------------------------------------------------------------------
#define FA_BQ 128
#define FA_BK 64
#define FA_STR 136
#define FA_SMEM ((FA_BQ + 2 * FA_BK) * FA_STR * 2)

__global__ __launch_bounds__(256) void flash_tc(const __half* __restrict__ Qh,
                                                const __half* __restrict__ Kh,
                                                const __half* __restrict__ Vsrc,
                                                int vld,
                                                __half* __restrict__ Oh)
{
    extern __shared__ __half sh[];
    __half* Qs = sh;
    __half* Ks = Qs + FA_BQ * FA_STR;
    __half* Vs = Ks + FA_BK * FA_STR;

    const int qb = blockIdx.x, h = blockIdx.y, b = blockIdx.z;
    const int kvh = h % HKV_;
    const int t = threadIdx.x, lane = t & 31, w = t >> 5;
    const int q0 = qb * FA_BQ;
    const int wq0 = w * 16;

    {
#pragma unroll
        for (int i = 0; i < 8; ++i) {
            int linear = t + 256 * i;
            int row = linear >> 4;
            int c8 = (linear & 15) * 8;
            *(uint4*)&Qs[row * FA_STR + c8] =
                *(const uint4*)(Qh + (size_t)(b * Ss_ + q0 + row) * Dd_ + h * HD_ + c8);
        }
    }

    float oacc[16][4];
#pragma unroll
    for (int i = 0; i < 16; ++i)
#pragma unroll
        for (int j = 0; j < 4; ++j) oacc[i][j] = 0.0f;
    float mrow[2] = {-INFINITY, -INFINITY};
    float lrow[2] = {0.0f, 0.0f};

    const uint32_t qa = smem_u32(Qs) +
        (uint32_t)((wq0 + (lane & 15)) * (FA_STR * 2)) +
        (uint32_t)(((lane >> 4) & 1) * 16);
    const uint32_t ka = smem_u32(Ks) +
        (uint32_t)(((lane & 7) + ((lane >> 4) & 1) * 8) * (FA_STR * 2)) +
        (uint32_t)(((lane >> 3) & 1) * 16);
    const uint32_t va = smem_u32(Vs) +
        (uint32_t)(((lane & 7) + ((lane >> 3) & 1) * 8) * (FA_STR * 2)) +
        (uint32_t)(((lane >> 4) & 1) * 16);

    const int nkb = (q0 + FA_BQ) / FA_BK;
    for (int kb = 0; kb < nkb; ++kb) {
        const int k0 = kb * FA_BK;
        __syncthreads();
        {
#pragma unroll
            for (int i = 0; i < 4; ++i) {
                int linear = t + 256 * i;
                int row = linear >> 4;
                int c8 = (linear & 15) * 8;
                *(uint4*)&Ks[row * FA_STR + c8] = *(const uint4*)(
                    Kh + (size_t)(b * Ss_ + k0 + row) * NKV + kvh * HD_ + c8);
                *(uint4*)&Vs[row * FA_STR + c8] = *(const uint4*)(
                    Vsrc + (size_t)(b * Ss_ + k0 + row) * vld + kvh * HD_ + c8);
            }
        }
        __syncthreads();

        if (k0 <= q0 + wq0 + 15) {
            float sacc[8][4];
#pragma unroll
            for (int i = 0; i < 8; ++i)
#pragma unroll
                for (int j = 0; j < 4; ++j) sacc[i][j] = 0.0f;

#pragma unroll
            for (int kk = 0; kk < 8; ++kk) {
                uint32_t af[4];
                ldsm_x4(af, qa + kk * 32);
#pragma unroll
                for (int np = 0; np < 4; ++np) {
                    uint32_t bf[4];
                    ldsm_x4(bf, ka + np * 16 * (FA_STR * 2) + kk * 32);
                    mma16816h(sacc[np * 2],     af, bf);
                    mma16816h(sacc[np * 2 + 1], af, bf + 2);
                }
            }

            if (k0 + FA_BK - 1 > q0 + wq0) {
                const int rbase = q0 + wq0 + (lane >> 2);
                const int cbase = k0 + (lane & 3) * 2;
#pragma unroll
                for (int nt = 0; nt < 8; ++nt)
#pragma unroll
                    for (int e = 0; e < 4; ++e) {
                        int col = cbase + nt * 8 + (e & 1);
                        int row = rbase + (e >> 1) * 8;
                        if (col > row) sacc[nt][e] = -INFINITY;
                    }
            }

#pragma unroll
            for (int r = 0; r < 2; ++r) {
                float mx = -INFINITY;
#pragma unroll
                for (int nt = 0; nt < 8; ++nt)
                    mx = fmaxf(mx, fmaxf(sacc[nt][2 * r], sacc[nt][2 * r + 1]));
                mx = fmaxf(mx, __shfl_xor_sync(0xffffffffu, mx, 1));
                mx = fmaxf(mx, __shfl_xor_sync(0xffffffffu, mx, 2));
                float mn = fmaxf(mrow[r], mx);
                float al = ex2f(mrow[r] - mn);
                mrow[r] = mn;
                float rs = 0.0f;
#pragma unroll
                for (int nt = 0; nt < 8; ++nt) {
                    float p0 = ex2f(sacc[nt][2 * r] - mn);
                    float p1 = ex2f(sacc[nt][2 * r + 1] - mn);
                    sacc[nt][2 * r] = p0;
                    sacc[nt][2 * r + 1] = p1;
                    rs += p0 + p1;
                }
                rs += __shfl_xor_sync(0xffffffffu, rs, 1);
                rs += __shfl_xor_sync(0xffffffffu, rs, 2);
                lrow[r] = lrow[r] * al + rs;
#pragma unroll
                for (int nt = 0; nt < 16; ++nt) {
                    oacc[nt][2 * r]     *= al;
                    oacc[nt][2 * r + 1] *= al;
                }
            }

#pragma unroll
            for (int j = 0; j < 4; ++j) {
                uint32_t a[4];
                a[0] = packh2(sacc[2 * j][0],     sacc[2 * j][1]);
                a[1] = packh2(sacc[2 * j][2],     sacc[2 * j][3]);
                a[2] = packh2(sacc[2 * j + 1][0], sacc[2 * j + 1][1]);
                a[3] = packh2(sacc[2 * j + 1][2], sacc[2 * j + 1][3]);
#pragma unroll
                for (int dp = 0; dp < 8; ++dp) {
                    uint32_t bf[4];
                    ldsm_x4_t(bf, va + j * 16 * (FA_STR * 2) + dp * 32);
                    mma16816h(oacc[dp * 2],     a, bf);
                    mma16816h(oacc[dp * 2 + 1], a, bf + 2);
                }
            }
        }
    }

#pragma unroll
    for (int r = 0; r < 2; ++r) {
        float inv = 1.0f / lrow[r];
        int row = q0 + wq0 + (lane >> 2) + r * 8;
        __half* Og = Oh + (size_t)(b * Ss_ + row) * Dd_ + h * HD_;
#pragma unroll
        for (int nt = 0; nt < 16; ++nt) {
            int col = nt * 8 + (lane & 3) * 2;
            *(uint32_t*)(Og + col) =
                packh2(oacc[nt][2 * r] * inv, oacc[nt][2 * r + 1] * inv);
        }
    }
}

// ---------------------------------------------------------------------------
// Launch
// ---------------------------------------------------------------------------
extern "C" void kernel_launch(void* const* d_in, const int* in_sizes, int n_in,
                              void* d_out, int out_size)
{
    const float* x  = (const float*)d_in[0];
    const float* Wq = (const float*)d_in[2];
    const float* Wk = (const float*)d_in[3];
    const float* Wv = (const float*)d_in[4];
    const float* Wo = (const float*)d_in[5];
    float* out = (float*)d_out;

    __half *Xhp, *Wqkvp, *QKVp, *Qhp, *Khp, *Ohp, *WBhp, *WBlp;
    cudaGetSymbolAddress((void**)&Xhp, g_Xh);
    cudaGetSymbolAddress((void**)&Wqkvp, g_Wqkv);
    cudaGetSymbolAddress((void**)&QKVp, g_QKV);
    cudaGetSymbolAddress((void**)&Qhp, g_Qh);
    cudaGetSymbolAddress((void**)&Khp, g_Kh);
    cudaGetSymbolAddress((void**)&Ohp, g_Oh);
    cudaGetSymbolAddress((void**)&WBhp, g_WBh);
    cudaGetSymbolAddress((void**)&WBlp, g_WBl);

    cudaFuncSetAttribute(gemm_f16x1, cudaFuncAttributeMaxDynamicSharedMemorySize,
                         G1_SMEM);
    cudaFuncSetAttribute(gemm_f16x2, cudaFuncAttributeMaxDynamicSharedMemorySize,
                         G2_SMEM);
    cudaFuncSetAttribute(flash_tc, cudaFuncAttributeMaxDynamicSharedMemorySize,
                         FA_SMEM);

    const int nX  = MROWS * Dd_;       // 8.4M
    const int nWq = Dd_ * Dd_;         // 4.2M
    const int nWk = Dd_ * NKV;         // 0.5M

    // A side: x -> fp16
    convert_half_k<<<nX / 2048, 256>>>(x, Xhp, nX);

    // B side: [Wq | Wk | Wv] -> fp16 combined
    convert_half_to_strided<<<nWq / 1024, 256>>>(Wq, Wqkvp, Dd_, NQKV, 0, nWq);
    convert_half_to_strided<<<nWk / 1024, 256>>>(Wk, Wqkvp, NKV, NQKV, Dd_, nWk);
    convert_half_to_strided<<<nWk / 1024, 256>>>(Wv, Wqkvp, NKV, NQKV, VOFF, nWk);

    // QKV = x @ [Wq|Wk|Wv]  (single-pass fp16, fp16 out)
    gemm_f16x1<<<dim3(NQKV / 128, MROWS / 128), 256, G1_SMEM>>>(
        Xhp, Wqkvp, QKVp, MROWS, NQKV, Dd_);

    // RoPE (fp16 -> fp16); V used in-place from QKV buffer
    const float qmult = 1.4426950408889634f / sqrtf((float)HD_);
    {
        int totq = MROWS * Hh_ * 64;
        rope_h2h<<<(totq + 255) / 256, 256>>>(QKVp, Qhp, Hh_, NQKV, Dd_, qmult, totq);
        int totk = MROWS * HKV_ * 64;
        rope_h2h<<<(totk + 255) / 256, 256>>>(QKVp + Dd_, Khp, HKV_, NQKV, NKV, 1.0f, totk);
    }

    // Flash attention (V strided from QKV buffer)
    flash_tc<<<dim3(Ss_ / FA_BQ, Hh_, Bb_), 256, FA_SMEM>>>(
        Qhp, Khp, QKVp + VOFF, NQKV, Ohp);

    // out = O @ Wo (two-pass, fp32 out)
    convert_splitH_k<<<nWq / 1024, 256>>>(Wo, WBhp, WBlp, nWq);
    gemm_f16x2<<<dim3(Dd_ / 128, MROWS / 128), 256, G2_SMEM>>>(
        Ohp, WBhp, WBlp, out, MROWS, Dd_, Dd_);
}

// round 11
// speedup vs baseline: 2.0756x; 1.1627x over previous
#include <cuda_runtime.h>
#include <cuda_fp16.h>
#include <math.h>
#include <stdint.h>

// Problem constants
#define Bb_ 2
#define Ss_ 2048
#define Dd_ 2048
#define Hh_ 16
#define HKV_ 2
#define HD_ 128
#define MROWS (Bb_ * Ss_)          // 4096
#define NKV (HKV_ * HD_)           // 256
#define NQKV 2560                  // Q(2048) | K(256) | V(256)
#define VOFF 2304                  // V column offset in QKV buffer

// Scratch (allocation-free: __device__ globals)
__device__ __half g_Xh[(size_t)MROWS * Dd_];        // x as fp16 (A side)
__device__ __half g_Wqkv[(size_t)Dd_ * NQKV];       // [Wq|Wk|Wv] fp16
__device__ __half g_QKV[(size_t)MROWS * NQKV];      // pre-rope QKV (fp16)
__device__ __half g_Qh[(size_t)MROWS * Dd_];        // post-rope Q
__device__ __half g_Kh[(size_t)MROWS * NKV];        // post-rope K
__device__ __half g_Oh[(size_t)MROWS * Dd_];        // attn out (A of Wo gemm)
__device__ __half g_Woh[(size_t)Dd_ * Dd_];         // Wo fp16

// ---------------------------------------------------------------------------
// Helpers
// ---------------------------------------------------------------------------
static __device__ __forceinline__ uint32_t smem_u32(const void* p) {
    uint32_t r;
    asm("{ .reg .u64 t; cvta.to.shared.u64 t, %1; cvt.u32.u64 %0, t; }"
        : "=r"(r) : "l"(p));
    return r;
}

static __device__ __forceinline__ void mma16816h(float* c, const uint32_t* a,
                                                 const uint32_t* b) {
    asm volatile(
        "mma.sync.aligned.m16n8k16.row.col.f32.f16.f16.f32 "
        "{%0,%1,%2,%3}, {%4,%5,%6,%7}, {%8,%9}, {%0,%1,%2,%3};"
        : "+f"(c[0]), "+f"(c[1]), "+f"(c[2]), "+f"(c[3])
        : "r"(a[0]), "r"(a[1]), "r"(a[2]), "r"(a[3]), "r"(b[0]), "r"(b[1]));
}

static __device__ __forceinline__ void ldsm_x4(uint32_t* r, uint32_t addr) {
    asm volatile("ldmatrix.sync.aligned.m8n8.x4.shared.b16 {%0,%1,%2,%3}, [%4];"
                 : "=r"(r[0]), "=r"(r[1]), "=r"(r[2]), "=r"(r[3]) : "r"(addr));
}

static __device__ __forceinline__ void ldsm_x4_t(uint32_t* r, uint32_t addr) {
    asm volatile("ldmatrix.sync.aligned.m8n8.x4.trans.shared.b16 {%0,%1,%2,%3}, [%4];"
                 : "=r"(r[0]), "=r"(r[1]), "=r"(r[2]), "=r"(r[3]) : "r"(addr));
}

static __device__ __forceinline__ void ldsm_x2_t(uint32_t* r, uint32_t addr) {
    asm volatile("ldmatrix.sync.aligned.m8n8.x2.trans.shared.b16 {%0,%1}, [%2];"
                 : "=r"(r[0]), "=r"(r[1]) : "r"(addr));
}

static __device__ __forceinline__ float ex2f(float x) {
    float y;
    asm("ex2.approx.f32 %0, %1;" : "=f"(y) : "f"(x));
    return y;
}

static __device__ __forceinline__ uint32_t packh2(float a, float b) {
    __half2 h = __floats2half2_rn(a, b);
    return *reinterpret_cast<uint32_t*>(&h);
}

#define CPA16(dst, src) \
    asm volatile("cp.async.cg.shared.global [%0], [%1], 16;" :: "r"(dst), "l"(src))
#define CP_COMMIT() asm volatile("cp.async.commit_group;" ::: "memory")
#define CP_WAIT1() asm volatile("cp.async.wait_group 1;" ::: "memory")
#define CP_WAIT0() asm volatile("cp.async.wait_group 0;" ::: "memory")

// fp32 -> fp16 (contiguous)
__global__ void convert_half_k(const float* __restrict__ in,
                               __half* __restrict__ out, int n)
{
    int i = (blockIdx.x * blockDim.x + threadIdx.x) * 8;
    if (i >= n) return;
    float4 a = *(const float4*)(in + i);
    float4 b = *(const float4*)(in + i + 4);
    uint4 o;
    o.x = packh2(a.x, a.y);
    o.y = packh2(a.z, a.w);
    o.z = packh2(b.x, b.y);
    o.w = packh2(b.z, b.w);
    *(uint4*)(out + i) = o;
}

// fp32 dense [r][cols] -> fp16 at [r][coloff + c] with row stride ldout
__global__ void convert_half_to_strided(const float* __restrict__ in,
                                        __half* __restrict__ out,
                                        int cols, int ldout, int coloff, int n)
{
    int i = (blockIdx.x * blockDim.x + threadIdx.x) * 4;
    if (i >= n) return;
    int r = i / cols, c = i % cols;
    float4 v = *(const float4*)(in + i);
    uint2 o;
    o.x = packh2(v.x, v.y);
    o.y = packh2(v.z, v.w);
    *(uint2*)(out + (size_t)r * ldout + coloff + c) = o;
}

// RoPE fp16 -> fp16 (math in fp32), strided in/out
__global__ void rope_h2h(const __half* __restrict__ in, __half* __restrict__ out,
                         int nh, int ld_in, int ld_out, float mult, int total)
{
    int idx = blockIdx.x * blockDim.x + threadIdx.x;
    if (idx >= total) return;
    int i    = idx & 63;
    int hh   = (idx >> 6) % nh;
    int srow = idx / (64 * nh);
    int pos  = srow & (Ss_ - 1);

    float inv = (float)exp(-(double)i * (log(10000.0) / 64.0));
    float ang = (float)pos * inv;
    float sn, cs;
    sincosf(ang, &sn, &cs);

    size_t bi = (size_t)srow * ld_in + (size_t)hh * HD_ + i;
    size_t bo = (size_t)srow * ld_out + (size_t)hh * HD_ + i;
    float x1 = __half2float(in[bi]);
    float x2 = __half2float(in[bi + 64]);
    out[bo]      = __float2half((x1 * cs - x2 * sn) * mult);
    out[bo + 64] = __float2half((x2 * cs + x1 * sn) * mult);
}

// ---------------------------------------------------------------------------
// Single-pass fp16 GEMM (templated output type), cp.async 2-stage.
// CTA 128x128, BK=64, 8 warps (2m x 4n, 64x32 each).
// ---------------------------------------------------------------------------
#define SA_STRIDE 72
#define SB_STRIDE 136
#define SA_SZ (128 * SA_STRIDE)               // 9216 halves
#define SB_SZ (64 * SB_STRIDE)                // 8704 halves
#define STG1_BYTES ((SA_SZ + SB_SZ) * 2)      // 35840
#define G1_SMEM (2 * STG1_BYTES)              // 71680

template <typename TO>
__global__ __launch_bounds__(256, 2) void gemm_f16x1(const __half* __restrict__ Ah,
                                                     const __half* __restrict__ Bh,
                                                     TO* __restrict__ C,
                                                     int M, int N, int K)
{
    extern __shared__ __half smh[];
    const uint32_t sbase = smem_u32(smh);

    const int t    = threadIdx.x;
    const int lane = t & 31;
    const int wid  = t >> 5;
    const int wm   = wid & 1;
    const int wn   = wid >> 1;
    const int n0   = blockIdx.x * 128;
    const int m0   = blockIdx.y * 128;

    float acc[4][4][4];
#pragma unroll
    for (int i = 0; i < 4; ++i)
#pragma unroll
        for (int j = 0; j < 4; ++j)
#pragma unroll
            for (int k = 0; k < 4; ++k) acc[i][j][k] = 0.0f;

    auto load_stage = [&](int c, int buf) {
        const int k0 = c << 6;
        const uint32_t sb = sbase + (uint32_t)buf * STG1_BYTES;
#pragma unroll
        for (int i = 0; i < 4; ++i) {
            int li = t + 256 * i;
            int row = li >> 3, v = li & 7;
            const size_t g = (size_t)(m0 + row) * K + k0 + v * 8;
            CPA16(sb + (uint32_t)(row * SA_STRIDE + v * 8) * 2, Ah + g);
        }
#pragma unroll
        for (int i = 0; i < 4; ++i) {
            int li = t + 256 * i;
            int row = li >> 4, v = li & 15;
            const size_t g = (size_t)(k0 + row) * N + n0 + v * 8;
            CPA16(sb + (uint32_t)(SA_SZ + row * SB_STRIDE + v * 8) * 2, Bh + g);
        }
    };

    const uint32_t a_rel =
        (uint32_t)(((lane & 7) + ((lane >> 3) & 1) * 8 + wm * 64) * (SA_STRIDE * 2)) +
        (uint32_t)(((lane >> 4) & 1) * 16);
    const uint32_t b_rel = (uint32_t)(SA_SZ * 2) +
        (uint32_t)(((lane & 7) + ((lane >> 3) & 1) * 8) * (SB_STRIDE * 2)) +
        (uint32_t)(wn * 64);

    const int nch = K >> 6;
    load_stage(0, 0);
    CP_COMMIT();

    for (int c = 0; c < nch; ++c) {
        const int buf = c & 1;
        if (c + 1 < nch) {
            load_stage(c + 1, (c + 1) & 1);
            CP_COMMIT();
            CP_WAIT1();
        } else {
            CP_WAIT0();
        }
        __syncthreads();

        const uint32_t stg = sbase + (uint32_t)buf * STG1_BYTES;
        const uint32_t a_addr = stg + a_rel;
        const uint32_t b_addr = stg + b_rel;

#pragma unroll
        for (int k16 = 0; k16 < 4; ++k16) {
            uint32_t bh[4][2], af[4][4];
            const uint32_t bko = (uint32_t)(k16 * 16 * SB_STRIDE * 2);
#pragma unroll
            for (int nt = 0; nt < 4; ++nt)
                ldsm_x2_t(bh[nt], b_addr + nt * 16 + bko);
            const uint32_t ako = (uint32_t)(k16 * 32);
#pragma unroll
            for (int mt = 0; mt < 4; ++mt)
                ldsm_x4(af[mt], a_addr + mt * (16 * SA_STRIDE * 2) + ako);
#pragma unroll
            for (int mt = 0; mt < 4; ++mt)
#pragma unroll
                for (int nt = 0; nt < 4; ++nt)
                    mma16816h(acc[mt][nt], af[mt], bh[nt]);
        }
        __syncthreads();
    }

    const int g   = lane >> 2;
    const int tid = lane & 3;
#pragma unroll
    for (int mt = 0; mt < 4; ++mt) {
        const int row = m0 + wm * 64 + mt * 16 + g;
#pragma unroll
        for (int nt = 0; nt < 4; ++nt) {
            const int col = n0 + wn * 32 + nt * 8 + tid * 2;
            if (sizeof(TO) == 4) {
                *(float2*)((float*)C + (size_t)row * N + col) =
                    make_float2(acc[mt][nt][0], acc[mt][nt][1]);
                *(float2*)((float*)C + (size_t)(row + 8) * N + col) =
                    make_float2(acc[mt][nt][2], acc[mt][nt][3]);
            } else {
                *(uint32_t*)((__half*)C + (size_t)row * N + col) =
                    packh2(acc[mt][nt][0], acc[mt][nt][1]);
                *(uint32_t*)((__half*)C + (size_t)(row + 8) * N + col) =
                    packh2(acc[mt][nt][2], acc[mt][nt][3]);
            }
        }
    }
}

// ---------------------------------------------------------------------------
// Tensor-core causal flash attention; cp.async double-buffered K/V tiles.
// Grid x reversed: long (late-qb) CTAs launch first.
// ---------------------------------------------------------------------------
#define FA_BQ 128
#define FA_BK 64
#define FA_STR 136
#define FA_QS (FA_BQ * FA_STR)                  // halves
#define FA_KV1 (FA_BK * FA_STR)                 // one K or V tile, halves
#define FA_STAGE (2 * FA_KV1)                   // K+V per stage, halves
#define FA_SMEM ((FA_QS + 2 * FA_STAGE) * 2)    // 104448 bytes

__global__ __launch_bounds__(256) void flash_tc(const __half* __restrict__ Qh,
                                                const __half* __restrict__ Kh,
                                                const __half* __restrict__ Vsrc,
                                                int vld,
                                                __half* __restrict__ Oh)
{
    extern __shared__ __half sh[];
    __half* Qs = sh;

    const int qb = gridDim.x - 1 - blockIdx.x;   // long CTAs first
    const int h = blockIdx.y, b = blockIdx.z;
    const int kvh = h % HKV_;
    const int t = threadIdx.x, lane = t & 31, w = t >> 5;
    const int q0 = qb * FA_BQ;
    const int wq0 = w * 16;

    // Load Q tile (plain vectorized; done once)
    {
#pragma unroll
        for (int i = 0; i < 8; ++i) {
            int linear = t + 256 * i;
            int row = linear >> 4;
            int c8 = (linear & 15) * 8;
            *(uint4*)&Qs[row * FA_STR + c8] =
                *(const uint4*)(Qh + (size_t)(b * Ss_ + q0 + row) * Dd_ + h * HD_ + c8);
        }
    }

    float oacc[16][4];
#pragma unroll
    for (int i = 0; i < 16; ++i)
#pragma unroll
        for (int j = 0; j < 4; ++j) oacc[i][j] = 0.0f;
    float mrow[2] = {-INFINITY, -INFINITY};
    float lrow[2] = {0.0f, 0.0f};

    const uint32_t sbase = smem_u32(sh);
    const uint32_t qa = sbase +
        (uint32_t)((wq0 + (lane & 15)) * (FA_STR * 2)) +
        (uint32_t)(((lane >> 4) & 1) * 16);
    const uint32_t k_rel =
        (uint32_t)(((lane & 7) + ((lane >> 4) & 1) * 8) * (FA_STR * 2)) +
        (uint32_t)(((lane >> 3) & 1) * 16);
    const uint32_t v_rel = (uint32_t)(FA_KV1 * 2) +
        (uint32_t)(((lane & 7) + ((lane >> 3) & 1) * 8) * (FA_STR * 2)) +
        (uint32_t)(((lane >> 4) & 1) * 16);

    auto load_kv = [&](int kb, int buf) {
        const int k0 = kb * FA_BK;
        const uint32_t sb = sbase + (uint32_t)(FA_QS + buf * FA_STAGE) * 2;
#pragma unroll
        for (int i = 0; i < 4; ++i) {
            int linear = t + 256 * i;
            int row = linear >> 4;
            int c8 = (linear & 15) * 8;
            uint32_t s = sb + (uint32_t)(row * FA_STR + c8) * 2;
            CPA16(s, Kh + (size_t)(b * Ss_ + k0 + row) * NKV + kvh * HD_ + c8);
            CPA16(s + FA_KV1 * 2,
                  Vsrc + (size_t)(b * Ss_ + k0 + row) * vld + kvh * HD_ + c8);
        }
    };

    const int nkb = (q0 + FA_BQ) / FA_BK;
    load_kv(0, 0);
    CP_COMMIT();

    for (int kb = 0; kb < nkb; ++kb) {
        const int buf = kb & 1;
        const int k0 = kb * FA_BK;
        if (kb + 1 < nkb) {
            load_kv(kb + 1, buf ^ 1);
            CP_COMMIT();
            CP_WAIT1();
        } else {
            CP_WAIT0();
        }
        __syncthreads();

        const uint32_t stg = sbase + (uint32_t)(FA_QS + buf * FA_STAGE) * 2;
        const uint32_t ka = stg + k_rel;
        const uint32_t va = stg + v_rel;

        if (k0 <= q0 + wq0 + 15) {
            float sacc[8][4];
#pragma unroll
            for (int i = 0; i < 8; ++i)
#pragma unroll
                for (int j = 0; j < 4; ++j) sacc[i][j] = 0.0f;

#pragma unroll
            for (int kk = 0; kk < 8; ++kk) {
                uint32_t af[4];
                ldsm_x4(af, qa + kk * 32);
#pragma unroll
                for (int np = 0; np < 4; ++np) {
                    uint32_t bf[4];
                    ldsm_x4(bf, ka + np * 16 * (FA_STR * 2) + kk * 32);
                    mma16816h(sacc[np * 2],     af, bf);
                    mma16816h(sacc[np * 2 + 1], af, bf + 2);
                }
            }

            if (k0 + FA_BK - 1 > q0 + wq0) {
                const int rbase = q0 + wq0 + (lane >> 2);
                const int cbase = k0 + (lane & 3) * 2;
#pragma unroll
                for (int nt = 0; nt < 8; ++nt)
#pragma unroll
                    for (int e = 0; e < 4; ++e) {
                        int col = cbase + nt * 8 + (e & 1);
                        int row = rbase + (e >> 1) * 8;
                        if (col > row) sacc[nt][e] = -INFINITY;
                    }
            }

#pragma unroll
            for (int r = 0; r < 2; ++r) {
                float mx = -INFINITY;
#pragma unroll
                for (int nt = 0; nt < 8; ++nt)
                    mx = fmaxf(mx, fmaxf(sacc[nt][2 * r], sacc[nt][2 * r + 1]));
                mx = fmaxf(mx, __shfl_xor_sync(0xffffffffu, mx, 1));
                mx = fmaxf(mx, __shfl_xor_sync(0xffffffffu, mx, 2));
                float mn = fmaxf(mrow[r], mx);
                float al = ex2f(mrow[r] - mn);
                mrow[r] = mn;
                float rs = 0.0f;
#pragma unroll
                for (int nt = 0; nt < 8; ++nt) {
                    float p0 = ex2f(sacc[nt][2 * r] - mn);
                    float p1 = ex2f(sacc[nt][2 * r + 1] - mn);
                    sacc[nt][2 * r] = p0;
                    sacc[nt][2 * r + 1] = p1;
                    rs += p0 + p1;
                }
                rs += __shfl_xor_sync(0xffffffffu, rs, 1);
                rs += __shfl_xor_sync(0xffffffffu, rs, 2);
                lrow[r] = lrow[r] * al + rs;
#pragma unroll
                for (int nt = 0; nt < 16; ++nt) {
                    oacc[nt][2 * r]     *= al;
                    oacc[nt][2 * r + 1] *= al;
                }
            }

#pragma unroll
            for (int j = 0; j < 4; ++j) {
                uint32_t a[4];
                a[0] = packh2(sacc[2 * j][0],     sacc[2 * j][1]);
                a[1] = packh2(sacc[2 * j][2],     sacc[2 * j][3]);
                a[2] = packh2(sacc[2 * j + 1][0], sacc[2 * j + 1][1]);
                a[3] = packh2(sacc[2 * j + 1][2], sacc[2 * j + 1][3]);
#pragma unroll
                for (int dp = 0; dp < 8; ++dp) {
                    uint32_t bf[4];
                    ldsm_x4_t(bf, va + j * 16 * (FA_STR * 2) + dp * 32);
                    mma16816h(oacc[dp * 2],     a, bf);
                    mma16816h(oacc[dp * 2 + 1], a, bf + 2);
                }
            }
        }
        __syncthreads();
    }

#pragma unroll
    for (int r = 0; r < 2; ++r) {
        float inv = 1.0f / lrow[r];
        int row = q0 + wq0 + (lane >> 2) + r * 8;
        __half* Og = Oh + (size_t)(b * Ss_ + row) * Dd_ + h * HD_;
#pragma unroll
        for (int nt = 0; nt < 16; ++nt) {
            int col = nt * 8 + (lane & 3) * 2;
            *(uint32_t*)(Og + col) =
                packh2(oacc[nt][2 * r] * inv, oacc[nt][2 * r + 1] * inv);
        }
    }
}

// ---------------------------------------------------------------------------
// Launch
// ---------------------------------------------------------------------------
extern "C" void kernel_launch(void* const* d_in, const int* in_sizes, int n_in,
                              void* d_out, int out_size)
{
    const float* x  = (const float*)d_in[0];
    const float* Wq = (const float*)d_in[2];
    const float* Wk = (const float*)d_in[3];
    const float* Wv = (const float*)d_in[4];
    const float* Wo = (const float*)d_in[5];
    float* out = (float*)d_out;

    __half *Xhp, *Wqkvp, *QKVp, *Qhp, *Khp, *Ohp, *Wohp;
    cudaGetSymbolAddress((void**)&Xhp, g_Xh);
    cudaGetSymbolAddress((void**)&Wqkvp, g_Wqkv);
    cudaGetSymbolAddress((void**)&QKVp, g_QKV);
    cudaGetSymbolAddress((void**)&Qhp, g_Qh);
    cudaGetSymbolAddress((void**)&Khp, g_Kh);
    cudaGetSymbolAddress((void**)&Ohp, g_Oh);
    cudaGetSymbolAddress((void**)&Wohp, g_Woh);

    cudaFuncSetAttribute(gemm_f16x1<__half>,
                         cudaFuncAttributeMaxDynamicSharedMemorySize, G1_SMEM);
    cudaFuncSetAttribute(gemm_f16x1<float>,
                         cudaFuncAttributeMaxDynamicSharedMemorySize, G1_SMEM);
    cudaFuncSetAttribute(flash_tc,
                         cudaFuncAttributeMaxDynamicSharedMemorySize, FA_SMEM);

    const int nX  = MROWS * Dd_;       // 8.4M
    const int nWq = Dd_ * Dd_;         // 4.2M
    const int nWk = Dd_ * NKV;         // 0.5M

    // A side: x -> fp16
    convert_half_k<<<nX / 2048, 256>>>(x, Xhp, nX);

    // B side: [Wq | Wk | Wv] -> fp16 combined; Wo -> fp16
    convert_half_to_strided<<<nWq / 1024, 256>>>(Wq, Wqkvp, Dd_, NQKV, 0, nWq);
    convert_half_to_strided<<<nWk / 1024, 256>>>(Wk, Wqkvp, NKV, NQKV, Dd_, nWk);
    convert_half_to_strided<<<nWk / 1024, 256>>>(Wv, Wqkvp, NKV, NQKV, VOFF, nWk);
    convert_half_k<<<nWq / 2048, 256>>>(Wo, Wohp, nWq);

    // QKV = x @ [Wq|Wk|Wv]  (single-pass fp16, fp16 out)
    gemm_f16x1<__half><<<dim3(NQKV / 128, MROWS / 128), 256, G1_SMEM>>>(
        Xhp, Wqkvp, QKVp, MROWS, NQKV, Dd_);

    // RoPE (fp16 -> fp16); V used in-place from QKV buffer
    const float qmult = 1.4426950408889634f / sqrtf((float)HD_);
    {
        int totq = MROWS * Hh_ * 64;
        rope_h2h<<<(totq + 255) / 256, 256>>>(QKVp, Qhp, Hh_, NQKV, Dd_, qmult, totq);
        int totk = MROWS * HKV_ * 64;
        rope_h2h<<<(totk + 255) / 256, 256>>>(QKVp + Dd_, Khp, HKV_, NQKV, NKV, 1.0f, totk);
    }

    // Flash attention (V strided from QKV buffer), pipelined K/V
    flash_tc<<<dim3(Ss_ / FA_BQ, Hh_, Bb_), 256, FA_SMEM>>>(
        Qhp, Khp, QKVp + VOFF, NQKV, Ohp);

    // out = O @ Wo (single-pass fp16, fp32 out)
    gemm_f16x1<float><<<dim3(Dd_ / 128, MROWS / 128), 256, G1_SMEM>>>(
        Ohp, Wohp, out, MROWS, Dd_, Dd_);
}

// round 13
// speedup vs baseline: 2.0839x; 1.0040x over previous
#include <cuda_runtime.h>
#include <cuda_fp16.h>
#include <math.h>
#include <stdint.h>

// Problem constants
#define Bb_ 2
#define Ss_ 2048
#define Dd_ 2048
#define Hh_ 16
#define HKV_ 2
#define HD_ 128
#define MROWS (Bb_ * Ss_)          // 4096
#define NKV (HKV_ * HD_)           // 256
#define NQKV 2560                  // Q(2048) | K(256) | V(256)
#define VOFF 2304                  // V column offset in QKV buffer

// Scratch (allocation-free: __device__ globals)
__device__ __half g_Xh[(size_t)MROWS * Dd_];        // x as fp16 (A side)
__device__ __half g_Wqkv[(size_t)Dd_ * NQKV];       // [Wq|Wk|Wv] fp16
__device__ __half g_QKV[(size_t)MROWS * NQKV];      // pre-rope QKV (fp16)
__device__ __half g_Kh[(size_t)MROWS * NKV];        // post-rope K
__device__ __half g_Oh[(size_t)MROWS * Dd_];        // attn out (A of Wo gemm)
__device__ __half g_Woh[(size_t)Dd_ * Dd_];         // Wo fp16

struct RopeTab { float v[64]; };                    // inv_freq (host, double-acc)

// ---------------------------------------------------------------------------
// Helpers
// ---------------------------------------------------------------------------
static __device__ __forceinline__ uint32_t smem_u32(const void* p) {
    uint32_t r;
    asm("{ .reg .u64 t; cvta.to.shared.u64 t, %1; cvt.u32.u64 %0, t; }"
        : "=r"(r) : "l"(p));
    return r;
}

static __device__ __forceinline__ void mma16816h(float* c, const uint32_t* a,
                                                 const uint32_t* b) {
    asm volatile(
        "mma.sync.aligned.m16n8k16.row.col.f32.f16.f16.f32 "
        "{%0,%1,%2,%3}, {%4,%5,%6,%7}, {%8,%9}, {%0,%1,%2,%3};"
        : "+f"(c[0]), "+f"(c[1]), "+f"(c[2]), "+f"(c[3])
        : "r"(a[0]), "r"(a[1]), "r"(a[2]), "r"(a[3]), "r"(b[0]), "r"(b[1]));
}

static __device__ __forceinline__ void ldsm_x4(uint32_t* r, uint32_t addr) {
    asm volatile("ldmatrix.sync.aligned.m8n8.x4.shared.b16 {%0,%1,%2,%3}, [%4];"
                 : "=r"(r[0]), "=r"(r[1]), "=r"(r[2]), "=r"(r[3]) : "r"(addr));
}

static __device__ __forceinline__ void ldsm_x4_t(uint32_t* r, uint32_t addr) {
    asm volatile("ldmatrix.sync.aligned.m8n8.x4.trans.shared.b16 {%0,%1,%2,%3}, [%4];"
                 : "=r"(r[0]), "=r"(r[1]), "=r"(r[2]), "=r"(r[3]) : "r"(addr));
}

static __device__ __forceinline__ void ldsm_x2_t(uint32_t* r, uint32_t addr) {
    asm volatile("ldmatrix.sync.aligned.m8n8.x2.trans.shared.b16 {%0,%1}, [%2];"
                 : "=r"(r[0]), "=r"(r[1]) : "r"(addr));
}

static __device__ __forceinline__ float ex2f(float x) {
    float y;
    asm("ex2.approx.f32 %0, %1;" : "=f"(y) : "f"(x));
    return y;
}

static __device__ __forceinline__ uint32_t packh2(float a, float b) {
    __half2 h = __floats2half2_rn(a, b);
    return *reinterpret_cast<uint32_t*>(&h);
}

#define CPA16(dst, src) \
    asm volatile("cp.async.cg.shared.global [%0], [%1], 16;" :: "r"(dst), "l"(src))
#define CP_COMMIT() asm volatile("cp.async.commit_group;" ::: "memory")
#define CP_WAIT1() asm volatile("cp.async.wait_group 1;" ::: "memory")
#define CP_WAIT0() asm volatile("cp.async.wait_group 0;" ::: "memory")

// fp32 -> fp16 (contiguous)
__global__ void convert_half_k(const float* __restrict__ in,
                               __half* __restrict__ out, int n)
{
    int i = (blockIdx.x * blockDim.x + threadIdx.x) * 8;
    if (i >= n) return;
    float4 a = *(const float4*)(in + i);
    float4 b = *(const float4*)(in + i + 4);
    uint4 o;
    o.x = packh2(a.x, a.y);
    o.y = packh2(a.z, a.w);
    o.z = packh2(b.x, b.y);
    o.w = packh2(b.z, b.w);
    *(uint4*)(out + i) = o;
}

// fp32 dense [r][cols] -> fp16 at [r][coloff + c] with row stride ldout
__global__ void convert_half_to_strided(const float* __restrict__ in,
                                        __half* __restrict__ out,
                                        int cols, int ldout, int coloff, int n)
{
    int i = (blockIdx.x * blockDim.x + threadIdx.x) * 4;
    if (i >= n) return;
    int r = i / cols, c = i % cols;
    float4 v = *(const float4*)(in + i);
    uint2 o;
    o.x = packh2(v.x, v.y);
    o.y = packh2(v.z, v.w);
    *(uint2*)(out + (size_t)r * ldout + coloff + c) = o;
}

// RoPE fp16 -> fp16 (math in fp32), strided in/out (K only)
__global__ void rope_h2h(const __half* __restrict__ in, __half* __restrict__ out,
                         int nh, int ld_in, int ld_out, RopeTab rt, int total)
{
    int idx = blockIdx.x * blockDim.x + threadIdx.x;
    if (idx >= total) return;
    int i    = idx & 63;
    int hh   = (idx >> 6) % nh;
    int srow = idx / (64 * nh);
    int pos  = srow & (Ss_ - 1);

    float ang = (float)pos * rt.v[i];
    float sn, cs;
    sincosf(ang, &sn, &cs);

    size_t bi = (size_t)srow * ld_in + (size_t)hh * HD_ + i;
    size_t bo = (size_t)srow * ld_out + (size_t)hh * HD_ + i;
    float x1 = __half2float(in[bi]);
    float x2 = __half2float(in[bi + 64]);
    out[bo]      = __float2half(x1 * cs - x2 * sn);
    out[bo + 64] = __float2half(x2 * cs + x1 * sn);
}

// ---------------------------------------------------------------------------
// Single-pass fp16 GEMM (templated output type), cp.async 2-stage. (validated)
// ---------------------------------------------------------------------------
#define SA_STRIDE 72
#define SB_STRIDE 136
#define SA_SZ (128 * SA_STRIDE)
#define SB_SZ (64 * SB_STRIDE)
#define STG1_BYTES ((SA_SZ + SB_SZ) * 2)      // 35840
#define G1_SMEM (2 * STG1_BYTES)              // 71680

template <typename TO>
__global__ __launch_bounds__(256, 2) void gemm_f16x1(const __half* __restrict__ Ah,
                                                     const __half* __restrict__ Bh,
                                                     TO* __restrict__ C,
                                                     int M, int N, int K)
{
    extern __shared__ __half smh[];
    const uint32_t sbase = smem_u32(smh);

    const int t    = threadIdx.x;
    const int lane = t & 31;
    const int wid  = t >> 5;
    const int wm   = wid & 1;
    const int wn   = wid >> 1;
    const int n0   = blockIdx.x * 128;
    const int m0   = blockIdx.y * 128;

    float acc[4][4][4];
#pragma unroll
    for (int i = 0; i < 4; ++i)
#pragma unroll
        for (int j = 0; j < 4; ++j)
#pragma unroll
            for (int k = 0; k < 4; ++k) acc[i][j][k] = 0.0f;

    auto load_stage = [&](int c, int buf) {
        const int k0 = c << 6;
        const uint32_t sb = sbase + (uint32_t)buf * STG1_BYTES;
#pragma unroll
        for (int i = 0; i < 4; ++i) {
            int li = t + 256 * i;
            int row = li >> 3, v = li & 7;
            const size_t g = (size_t)(m0 + row) * K + k0 + v * 8;
            CPA16(sb + (uint32_t)(row * SA_STRIDE + v * 8) * 2, Ah + g);
        }
#pragma unroll
        for (int i = 0; i < 4; ++i) {
            int li = t + 256 * i;
            int row = li >> 4, v = li & 15;
            const size_t g = (size_t)(k0 + row) * N + n0 + v * 8;
            CPA16(sb + (uint32_t)(SA_SZ + row * SB_STRIDE + v * 8) * 2, Bh + g);
        }
    };

    const uint32_t a_rel =
        (uint32_t)(((lane & 7) + ((lane >> 3) & 1) * 8 + wm * 64) * (SA_STRIDE * 2)) +
        (uint32_t)(((lane >> 4) & 1) * 16);
    const uint32_t b_rel = (uint32_t)(SA_SZ * 2) +
        (uint32_t)(((lane & 7) + ((lane >> 3) & 1) * 8) * (SB_STRIDE * 2)) +
        (uint32_t)(wn * 64);

    const int nch = K >> 6;
    load_stage(0, 0);
    CP_COMMIT();

    for (int c = 0; c < nch; ++c) {
        const int buf = c & 1;
        if (c + 1 < nch) {
            load_stage(c + 1, (c + 1) & 1);
            CP_COMMIT();
            CP_WAIT1();
        } else {
            CP_WAIT0();
        }
        __syncthreads();

        const uint32_t stg = sbase + (uint32_t)buf * STG1_BYTES;
        const uint32_t a_addr = stg + a_rel;
        const uint32_t b_addr = stg + b_rel;

#pragma unroll
        for (int k16 = 0; k16 < 4; ++k16) {
            uint32_t bh[4][2], af[4][4];
            const uint32_t bko = (uint32_t)(k16 * 16 * SB_STRIDE * 2);
#pragma unroll
            for (int nt = 0; nt < 4; ++nt)
                ldsm_x2_t(bh[nt], b_addr + nt * 16 + bko);
            const uint32_t ako = (uint32_t)(k16 * 32);
#pragma unroll
            for (int mt = 0; mt < 4; ++mt)
                ldsm_x4(af[mt], a_addr + mt * (16 * SA_STRIDE * 2) + ako);
#pragma unroll
            for (int mt = 0; mt < 4; ++mt)
#pragma unroll
                for (int nt = 0; nt < 4; ++nt)
                    mma16816h(acc[mt][nt], af[mt], bh[nt]);
        }
        __syncthreads();
    }

    const int g   = lane >> 2;
    const int tid = lane & 3;
#pragma unroll
    for (int mt = 0; mt < 4; ++mt) {
        const int row = m0 + wm * 64 + mt * 16 + g;
#pragma unroll
        for (int nt = 0; nt < 4; ++nt) {
            const int col = n0 + wn * 32 + nt * 8 + tid * 2;
            if (sizeof(TO) == 4) {
                *(float2*)((float*)C + (size_t)row * N + col) =
                    make_float2(acc[mt][nt][0], acc[mt][nt][1]);
                *(float2*)((float*)C + (size_t)(row + 8) * N + col) =
                    make_float2(acc[mt][nt][2], acc[mt][nt][3]);
            } else {
                *(uint32_t*)((__half*)C + (size_t)row * N + col) =
                    packh2(acc[mt][nt][0], acc[mt][nt][1]);
                *(uint32_t*)((__half*)C + (size_t)(row + 8) * N + col) =
                    packh2(acc[mt][nt][2], acc[mt][nt][3]);
            }
        }
    }
}

// ---------------------------------------------------------------------------
// Flash attention: Q-RoPE fused into the Q-tile load; 2 CTAs/SM target;
// cp.async double-buffered K/V; reversed qb order.
// ---------------------------------------------------------------------------
#define FA_BQ 128
#define FA_BK 64
#define FA_STR 136
#define FA_QS (FA_BQ * FA_STR)
#define FA_KV1 (FA_BK * FA_STR)
#define FA_STAGE (2 * FA_KV1)
#define FA_SMEM ((FA_QS + 2 * FA_STAGE) * 2)    // 104448 bytes

__global__ __launch_bounds__(256, 2) void flash_tc(const __half* __restrict__ Qsrc,
                                                   const __half* __restrict__ Kh,
                                                   const __half* __restrict__ Vsrc,
                                                   __half* __restrict__ Oh,
                                                   RopeTab rt, float qmult)
{
    extern __shared__ __half sh[];
    __half* Qs = sh;

    const int qb = gridDim.x - 1 - blockIdx.x;   // long CTAs first
    const int h = blockIdx.y, b = blockIdx.z;
    const int kvh = h % HKV_;
    const int t = threadIdx.x, lane = t & 31, w = t >> 5;
    const int q0 = qb * FA_BQ;
    const int wq0 = w * 16;

    // Load Q tile from pre-rope QKV buffer, apply RoPE + scale on the fly.
    {
#pragma unroll
        for (int i = 0; i < 8; ++i) {
            int linear = t + 256 * i;
            int row = linear >> 4;
            int c8 = (linear & 15) * 8;       // d base within head (0..120)
            const __half* base = Qsrc + (size_t)(b * Ss_ + q0 + row) * NQKV + h * HD_;
            uint4 own = *(const uint4*)(base + c8);
            uint4 par = *(const uint4*)(base + (c8 ^ 64));
            const __half2* o2 = (const __half2*)&own;
            const __half2* p2 = (const __half2*)&par;
            float sgn = (c8 < 64) ? -1.0f : 1.0f;
            int pos = q0 + row;
            uint4 res;
            uint32_t* r32 = (uint32_t*)&res;
#pragma unroll
            for (int e = 0; e < 4; ++e) {
                int d0 = (c8 + 2 * e) & 63;
                float sa, ca, sb_, cb;
                sincosf((float)pos * rt.v[d0], &sa, &ca);
                sincosf((float)pos * rt.v[d0 + 1], &sb_, &cb);
                float xa = __half2float(o2[e].x), xb = __half2float(o2[e].y);
                float ya = __half2float(p2[e].x), yb = __half2float(p2[e].y);
                r32[e] = packh2((xa * ca + sgn * ya * sa) * qmult,
                                (xb * cb + sgn * yb * sb_) * qmult);
            }
            *(uint4*)&Qs[row * FA_STR + c8] = res;
        }
    }

    float oacc[16][4];
#pragma unroll
    for (int i = 0; i < 16; ++i)
#pragma unroll
        for (int j = 0; j < 4; ++j) oacc[i][j] = 0.0f;
    float mrow[2] = {-INFINITY, -INFINITY};
    float lrow[2] = {0.0f, 0.0f};

    const uint32_t sbase = smem_u32(sh);
    const uint32_t qa = sbase +
        (uint32_t)((wq0 + (lane & 15)) * (FA_STR * 2)) +
        (uint32_t)(((lane >> 4) & 1) * 16);
    const uint32_t k_rel =
        (uint32_t)(((lane & 7) + ((lane >> 4) & 1) * 8) * (FA_STR * 2)) +
        (uint32_t)(((lane >> 3) & 1) * 16);
    const uint32_t v_rel = (uint32_t)(FA_KV1 * 2) +
        (uint32_t)(((lane & 7) + ((lane >> 3) & 1) * 8) * (FA_STR * 2)) +
        (uint32_t)(((lane >> 4) & 1) * 16);

    auto load_kv = [&](int kb, int buf) {
        const int k0 = kb * FA_BK;
        const uint32_t sb = sbase + (uint32_t)(FA_QS + buf * FA_STAGE) * 2;
#pragma unroll
        for (int i = 0; i < 4; ++i) {
            int linear = t + 256 * i;
            int row = linear >> 4;
            int c8 = (linear & 15) * 8;
            uint32_t s = sb + (uint32_t)(row * FA_STR + c8) * 2;
            CPA16(s, Kh + (size_t)(b * Ss_ + k0 + row) * NKV + kvh * HD_ + c8);
            CPA16(s + FA_KV1 * 2,
                  Vsrc + (size_t)(b * Ss_ + k0 + row) * NQKV + kvh * HD_ + c8);
        }
    };

    const int nkb = (q0 + FA_BQ) / FA_BK;
    load_kv(0, 0);
    CP_COMMIT();

    for (int kb = 0; kb < nkb; ++kb) {
        const int buf = kb & 1;
        const int k0 = kb * FA_BK;
        if (kb + 1 < nkb) {
            load_kv(kb + 1, buf ^ 1);
            CP_COMMIT();
            CP_WAIT1();
        } else {
            CP_WAIT0();
        }
        __syncthreads();

        const uint32_t stg = sbase + (uint32_t)(FA_QS + buf * FA_STAGE) * 2;
        const uint32_t ka = stg + k_rel;
        const uint32_t va = stg + v_rel;

        if (k0 <= q0 + wq0 + 15) {
            float sacc[8][4];
#pragma unroll
            for (int i = 0; i < 8; ++i)
#pragma unroll
                for (int j = 0; j < 4; ++j) sacc[i][j] = 0.0f;

#pragma unroll
            for (int kk = 0; kk < 8; ++kk) {
                uint32_t af[4];
                ldsm_x4(af, qa + kk * 32);
#pragma unroll
                for (int np = 0; np < 4; ++np) {
                    uint32_t bf[4];
                    ldsm_x4(bf, ka + np * 16 * (FA_STR * 2) + kk * 32);
                    mma16816h(sacc[np * 2],     af, bf);
                    mma16816h(sacc[np * 2 + 1], af, bf + 2);
                }
            }

            if (k0 + FA_BK - 1 > q0 + wq0) {
                const int rbase = q0 + wq0 + (lane >> 2);
                const int cbase = k0 + (lane & 3) * 2;
#pragma unroll
                for (int nt = 0; nt < 8; ++nt)
#pragma unroll
                    for (int e = 0; e < 4; ++e) {
                        int col = cbase + nt * 8 + (e & 1);
                        int row = rbase + (e >> 1) * 8;
                        if (col > row) sacc[nt][e] = -INFINITY;
                    }
            }

#pragma unroll
            for (int r = 0; r < 2; ++r) {
                float mx = -INFINITY;
#pragma unroll
                for (int nt = 0; nt < 8; ++nt)
                    mx = fmaxf(mx, fmaxf(sacc[nt][2 * r], sacc[nt][2 * r + 1]));
                mx = fmaxf(mx, __shfl_xor_sync(0xffffffffu, mx, 1));
                mx = fmaxf(mx, __shfl_xor_sync(0xffffffffu, mx, 2));
                float mn = fmaxf(mrow[r], mx);
                float al = ex2f(mrow[r] - mn);
                mrow[r] = mn;
                float rs = 0.0f;
#pragma unroll
                for (int nt = 0; nt < 8; ++nt) {
                    float p0 = ex2f(sacc[nt][2 * r] - mn);
                    float p1 = ex2f(sacc[nt][2 * r + 1] - mn);
                    sacc[nt][2 * r] = p0;
                    sacc[nt][2 * r + 1] = p1;
                    rs += p0 + p1;
                }
                rs += __shfl_xor_sync(0xffffffffu, rs, 1);
                rs += __shfl_xor_sync(0xffffffffu, rs, 2);
                lrow[r] = lrow[r] * al + rs;
#pragma unroll
                for (int nt = 0; nt < 16; ++nt) {
                    oacc[nt][2 * r]     *= al;
                    oacc[nt][2 * r + 1] *= al;
                }
            }

#pragma unroll
            for (int j = 0; j < 4; ++j) {
                uint32_t a[4];
                a[0] = packh2(sacc[2 * j][0],     sacc[2 * j][1]);
                a[1] = packh2(sacc[2 * j][2],     sacc[2 * j][3]);
                a[2] = packh2(sacc[2 * j + 1][0], sacc[2 * j + 1][1]);
                a[3] = packh2(sacc[2 * j + 1][2], sacc[2 * j + 1][3]);
#pragma unroll
                for (int dp = 0; dp < 8; ++dp) {
                    uint32_t bf[4];
                    ldsm_x4_t(bf, va + j * 16 * (FA_STR * 2) + dp * 32);
                    mma16816h(oacc[dp * 2],     a, bf);
                    mma16816h(oacc[dp * 2 + 1], a, bf + 2);
                }
            }
        }
        __syncthreads();
    }

#pragma unroll
    for (int r = 0; r < 2; ++r) {
        float inv = 1.0f / lrow[r];
        int row = q0 + wq0 + (lane >> 2) + r * 8;
        __half* Og = Oh + (size_t)(b * Ss_ + row) * Dd_ + h * HD_;
#pragma unroll
        for (int nt = 0; nt < 16; ++nt) {
            int col = nt * 8 + (lane & 3) * 2;
            *(uint32_t*)(Og + col) =
                packh2(oacc[nt][2 * r] * inv, oacc[nt][2 * r + 1] * inv);
        }
    }
}

// ---------------------------------------------------------------------------
// Launch
// ---------------------------------------------------------------------------
extern "C" void kernel_launch(void* const* d_in, const int* in_sizes, int n_in,
                              void* d_out, int out_size)
{
    const float* x  = (const float*)d_in[0];
    const float* Wq = (const float*)d_in[2];
    const float* Wk = (const float*)d_in[3];
    const float* Wv = (const float*)d_in[4];
    const float* Wo = (const float*)d_in[5];
    float* out = (float*)d_out;

    __half *Xhp, *Wqkvp, *QKVp, *Khp, *Ohp, *Wohp;
    cudaGetSymbolAddress((void**)&Xhp, g_Xh);
    cudaGetSymbolAddress((void**)&Wqkvp, g_Wqkv);
    cudaGetSymbolAddress((void**)&QKVp, g_QKV);
    cudaGetSymbolAddress((void**)&Khp, g_Kh);
    cudaGetSymbolAddress((void**)&Ohp, g_Oh);
    cudaGetSymbolAddress((void**)&Wohp, g_Woh);

    cudaFuncSetAttribute(gemm_f16x1<__half>,
                         cudaFuncAttributeMaxDynamicSharedMemorySize, G1_SMEM);
    cudaFuncSetAttribute(gemm_f16x1<float>,
                         cudaFuncAttributeMaxDynamicSharedMemorySize, G1_SMEM);
    cudaFuncSetAttribute(flash_tc,
                         cudaFuncAttributeMaxDynamicSharedMemorySize, FA_SMEM);

    const int nX  = MROWS * Dd_;       // 8.4M
    const int nWq = Dd_ * Dd_;         // 4.2M
    const int nWk = Dd_ * NKV;         // 0.5M

    // Host-accurate inv_freq table (double precision)
    RopeTab rt;
    for (int i = 0; i < 64; ++i)
        rt.v[i] = (float)exp(-(double)i * (log(10000.0) / 64.0));
    const float qmult = 1.4426950408889634f / sqrtf((float)HD_);

    // A side: x -> fp16
    convert_half_k<<<nX / 2048, 256>>>(x, Xhp, nX);

    // B side: [Wq | Wk | Wv] -> fp16 combined; Wo -> fp16
    convert_half_to_strided<<<nWq / 1024, 256>>>(Wq, Wqkvp, Dd_, NQKV, 0, nWq);
    convert_half_to_strided<<<nWk / 1024, 256>>>(Wk, Wqkvp, NKV, NQKV, Dd_, nWk);
    convert_half_to_strided<<<nWk / 1024, 256>>>(Wv, Wqkvp, NKV, NQKV, VOFF, nWk);
    convert_half_k<<<nWq / 2048, 256>>>(Wo, Wohp, nWq);

    // QKV = x @ [Wq|Wk|Wv]  (single-pass fp16, fp16 out)
    gemm_f16x1<__half><<<dim3(NQKV / 128, MROWS / 128), 256, G1_SMEM>>>(
        Xhp, Wqkvp, QKVp, MROWS, NQKV, Dd_);

    // K RoPE (fp16 -> fp16); Q rope fused into flash; V in-place from QKV
    {
        int totk = MROWS * HKV_ * 64;
        rope_h2h<<<(totk + 255) / 256, 256>>>(QKVp + Dd_, Khp, HKV_, NQKV, NKV, rt, totk);
    }

    // Flash attention (Q pre-rope from QKV buffer; rope fused into Q load)
    flash_tc<<<dim3(Ss_ / FA_BQ, Hh_, Bb_), 256, FA_SMEM>>>(
        QKVp, Khp, QKVp + VOFF, Ohp, rt, qmult);

    // out = O @ Wo (single-pass fp16, fp32 out)
    gemm_f16x1<float><<<dim3(Dd_ / 128, MROWS / 128), 256, G1_SMEM>>>(
        Ohp, Wohp, out, MROWS, Dd_, Dd_);
}

// round 14
// speedup vs baseline: 2.1543x; 1.0338x over previous
#include <cuda_runtime.h>
#include <cuda_fp16.h>
#include <math.h>
#include <stdint.h>

// Problem constants
#define Bb_ 2
#define Ss_ 2048
#define Dd_ 2048
#define Hh_ 16
#define HKV_ 2
#define HD_ 128
#define MROWS (Bb_ * Ss_)          // 4096
#define NKV (HKV_ * HD_)           // 256
#define NQKV 2560                  // Q(2048) | K(256) | V(256)
#define VOFF 2304                  // V column offset in QKV buffer

// Scratch (allocation-free: __device__ globals)
__device__ __half g_Xh[(size_t)MROWS * Dd_];        // x as fp16 (A side)
__device__ __half g_Wqkv[(size_t)Dd_ * NQKV];       // [Wq|Wk|Wv] fp16
__device__ __half g_QKV[(size_t)MROWS * NQKV];      // pre-rope QKV (fp16)
__device__ __half g_Kh[(size_t)MROWS * NKV];        // post-rope K
__device__ __half g_Oh[(size_t)MROWS * Dd_];        // attn out (A of Wo gemm)
__device__ __half g_Woh[(size_t)Dd_ * Dd_];         // Wo fp16
__device__ float2 g_rope[(size_t)Ss_ * 64];         // (cos,sin) per (pos, d)

struct RopeTab { float v[64]; };                    // inv_freq (host, double-acc)

// ---------------------------------------------------------------------------
// Helpers
// ---------------------------------------------------------------------------
static __device__ __forceinline__ uint32_t smem_u32(const void* p) {
    uint32_t r;
    asm("{ .reg .u64 t; cvta.to.shared.u64 t, %1; cvt.u32.u64 %0, t; }"
        : "=r"(r) : "l"(p));
    return r;
}

static __device__ __forceinline__ void mma16816h(float* c, const uint32_t* a,
                                                 const uint32_t* b) {
    asm volatile(
        "mma.sync.aligned.m16n8k16.row.col.f32.f16.f16.f32 "
        "{%0,%1,%2,%3}, {%4,%5,%6,%7}, {%8,%9}, {%0,%1,%2,%3};"
        : "+f"(c[0]), "+f"(c[1]), "+f"(c[2]), "+f"(c[3])
        : "r"(a[0]), "r"(a[1]), "r"(a[2]), "r"(a[3]), "r"(b[0]), "r"(b[1]));
}

static __device__ __forceinline__ void ldsm_x4(uint32_t* r, uint32_t addr) {
    asm volatile("ldmatrix.sync.aligned.m8n8.x4.shared.b16 {%0,%1,%2,%3}, [%4];"
                 : "=r"(r[0]), "=r"(r[1]), "=r"(r[2]), "=r"(r[3]) : "r"(addr));
}

static __device__ __forceinline__ void ldsm_x4_t(uint32_t* r, uint32_t addr) {
    asm volatile("ldmatrix.sync.aligned.m8n8.x4.trans.shared.b16 {%0,%1,%2,%3}, [%4];"
                 : "=r"(r[0]), "=r"(r[1]), "=r"(r[2]), "=r"(r[3]) : "r"(addr));
}

static __device__ __forceinline__ void ldsm_x2_t(uint32_t* r, uint32_t addr) {
    asm volatile("ldmatrix.sync.aligned.m8n8.x2.trans.shared.b16 {%0,%1}, [%2];"
                 : "=r"(r[0]), "=r"(r[1]) : "r"(addr));
}

static __device__ __forceinline__ float ex2f(float x) {
    float y;
    asm("ex2.approx.f32 %0, %1;" : "=f"(y) : "f"(x));
    return y;
}

static __device__ __forceinline__ uint32_t packh2(float a, float b) {
    __half2 h = __floats2half2_rn(a, b);
    return *reinterpret_cast<uint32_t*>(&h);
}

#define CPA16(dst, src) \
    asm volatile("cp.async.cg.shared.global [%0], [%1], 16;" :: "r"(dst), "l"(src))
#define CP_COMMIT() asm volatile("cp.async.commit_group;" ::: "memory")
#define CP_WAIT1() asm volatile("cp.async.wait_group 1;" ::: "memory")
#define CP_WAIT0() asm volatile("cp.async.wait_group 0;" ::: "memory")

// Fill rope table: one thread per (pos, d); same fp32 sincosf as before
__global__ void rope_fill_k(float2* __restrict__ tab, RopeTab rt)
{
    int idx = blockIdx.x * blockDim.x + threadIdx.x;   // 0 .. Ss_*64-1
    int d = idx & 63;
    int pos = idx >> 6;
    float sn, cs;
    sincosf((float)pos * rt.v[d], &sn, &cs);
    tab[idx] = make_float2(cs, sn);
}

// fp32 -> fp16 (contiguous)
__global__ void convert_half_k(const float* __restrict__ in,
                               __half* __restrict__ out, int n)
{
    int i = (blockIdx.x * blockDim.x + threadIdx.x) * 8;
    if (i >= n) return;
    float4 a = *(const float4*)(in + i);
    float4 b = *(const float4*)(in + i + 4);
    uint4 o;
    o.x = packh2(a.x, a.y);
    o.y = packh2(a.z, a.w);
    o.z = packh2(b.x, b.y);
    o.w = packh2(b.z, b.w);
    *(uint4*)(out + i) = o;
}

// fp32 dense [r][cols] -> fp16 at [r][coloff + c] with row stride ldout
__global__ void convert_half_to_strided(const float* __restrict__ in,
                                        __half* __restrict__ out,
                                        int cols, int ldout, int coloff, int n)
{
    int i = (blockIdx.x * blockDim.x + threadIdx.x) * 4;
    if (i >= n) return;
    int r = i / cols, c = i % cols;
    float4 v = *(const float4*)(in + i);
    uint2 o;
    o.x = packh2(v.x, v.y);
    o.y = packh2(v.z, v.w);
    *(uint2*)(out + (size_t)r * ldout + coloff + c) = o;
}

// Fused Wk+Wv convert: two dense fp32 srcs -> strided fp16 dst
__global__ void convert_kv_weights(const float* __restrict__ wk,
                                   const float* __restrict__ wv,
                                   __half* __restrict__ out, int n)
{
    int i = (blockIdx.x * blockDim.x + threadIdx.x) * 4;
    if (i >= n) return;
    int r = i / NKV, c = i % NKV;
    float4 a = *(const float4*)(wk + i);
    float4 b = *(const float4*)(wv + i);
    uint2 oa, ob;
    oa.x = packh2(a.x, a.y);  oa.y = packh2(a.z, a.w);
    ob.x = packh2(b.x, b.y);  ob.y = packh2(b.z, b.w);
    *(uint2*)(out + (size_t)r * NQKV + Dd_ + c)  = oa;
    *(uint2*)(out + (size_t)r * NQKV + VOFF + c) = ob;
}

// RoPE fp16 -> fp16 via table, strided in/out (K only)
__global__ void rope_h2h(const __half* __restrict__ in, __half* __restrict__ out,
                         const float2* __restrict__ tab,
                         int nh, int ld_in, int ld_out, int total)
{
    int idx = blockIdx.x * blockDim.x + threadIdx.x;
    if (idx >= total) return;
    int i    = idx & 63;
    int hh   = (idx >> 6) % nh;
    int srow = idx / (64 * nh);
    int pos  = srow & (Ss_ - 1);

    float2 cssn = tab[pos * 64 + i];

    size_t bi = (size_t)srow * ld_in + (size_t)hh * HD_ + i;
    size_t bo = (size_t)srow * ld_out + (size_t)hh * HD_ + i;
    float x1 = __half2float(in[bi]);
    float x2 = __half2float(in[bi + 64]);
    out[bo]      = __float2half(x1 * cssn.x - x2 * cssn.y);
    out[bo + 64] = __float2half(x2 * cssn.x + x1 * cssn.y);
}

// ---------------------------------------------------------------------------
// Single-pass fp16 GEMM (templated output type), cp.async 2-stage. (validated)
// ---------------------------------------------------------------------------
#define SA_STRIDE 72
#define SB_STRIDE 136
#define SA_SZ (128 * SA_STRIDE)
#define SB_SZ (64 * SB_STRIDE)
#define STG1_BYTES ((SA_SZ + SB_SZ) * 2)      // 35840
#define G1_SMEM (2 * STG1_BYTES)              // 71680

template <typename TO>
__global__ __launch_bounds__(256, 2) void gemm_f16x1(const __half* __restrict__ Ah,
                                                     const __half* __restrict__ Bh,
                                                     TO* __restrict__ C,
                                                     int M, int N, int K)
{
    extern __shared__ __half smh[];
    const uint32_t sbase = smem_u32(smh);

    const int t    = threadIdx.x;
    const int lane = t & 31;
    const int wid  = t >> 5;
    const int wm   = wid & 1;
    const int wn   = wid >> 1;
    const int n0   = blockIdx.x * 128;
    const int m0   = blockIdx.y * 128;

    float acc[4][4][4];
#pragma unroll
    for (int i = 0; i < 4; ++i)
#pragma unroll
        for (int j = 0; j < 4; ++j)
#pragma unroll
            for (int k = 0; k < 4; ++k) acc[i][j][k] = 0.0f;

    auto load_stage = [&](int c, int buf) {
        const int k0 = c << 6;
        const uint32_t sb = sbase + (uint32_t)buf * STG1_BYTES;
#pragma unroll
        for (int i = 0; i < 4; ++i) {
            int li = t + 256 * i;
            int row = li >> 3, v = li & 7;
            const size_t g = (size_t)(m0 + row) * K + k0 + v * 8;
            CPA16(sb + (uint32_t)(row * SA_STRIDE + v * 8) * 2, Ah + g);
        }
#pragma unroll
        for (int i = 0; i < 4; ++i) {
            int li = t + 256 * i;
            int row = li >> 4, v = li & 15;
            const size_t g = (size_t)(k0 + row) * N + n0 + v * 8;
            CPA16(sb + (uint32_t)(SA_SZ + row * SB_STRIDE + v * 8) * 2, Bh + g);
        }
    };

    const uint32_t a_rel =
        (uint32_t)(((lane & 7) + ((lane >> 3) & 1) * 8 + wm * 64) * (SA_STRIDE * 2)) +
        (uint32_t)(((lane >> 4) & 1) * 16);
    const uint32_t b_rel = (uint32_t)(SA_SZ * 2) +
        (uint32_t)(((lane & 7) + ((lane >> 3) & 1) * 8) * (SB_STRIDE * 2)) +
        (uint32_t)(wn * 64);

    const int nch = K >> 6;
    load_stage(0, 0);
    CP_COMMIT();

    for (int c = 0; c < nch; ++c) {
        const int buf = c & 1;
        if (c + 1 < nch) {
            load_stage(c + 1, (c + 1) & 1);
            CP_COMMIT();
            CP_WAIT1();
        } else {
            CP_WAIT0();
        }
        __syncthreads();

        const uint32_t stg = sbase + (uint32_t)buf * STG1_BYTES;
        const uint32_t a_addr = stg + a_rel;
        const uint32_t b_addr = stg + b_rel;

#pragma unroll
        for (int k16 = 0; k16 < 4; ++k16) {
            uint32_t bh[4][2], af[4][4];
            const uint32_t bko = (uint32_t)(k16 * 16 * SB_STRIDE * 2);
#pragma unroll
            for (int nt = 0; nt < 4; ++nt)
                ldsm_x2_t(bh[nt], b_addr + nt * 16 + bko);
            const uint32_t ako = (uint32_t)(k16 * 32);
#pragma unroll
            for (int mt = 0; mt < 4; ++mt)
                ldsm_x4(af[mt], a_addr + mt * (16 * SA_STRIDE * 2) + ako);
#pragma unroll
            for (int mt = 0; mt < 4; ++mt)
#pragma unroll
                for (int nt = 0; nt < 4; ++nt)
                    mma16816h(acc[mt][nt], af[mt], bh[nt]);
        }
        __syncthreads();
    }

    const int g   = lane >> 2;
    const int tid = lane & 3;
#pragma unroll
    for (int mt = 0; mt < 4; ++mt) {
        const int row = m0 + wm * 64 + mt * 16 + g;
#pragma unroll
        for (int nt = 0; nt < 4; ++nt) {
            const int col = n0 + wn * 32 + nt * 8 + tid * 2;
            if (sizeof(TO) == 4) {
                *(float2*)((float*)C + (size_t)row * N + col) =
                    make_float2(acc[mt][nt][0], acc[mt][nt][1]);
                *(float2*)((float*)C + (size_t)(row + 8) * N + col) =
                    make_float2(acc[mt][nt][2], acc[mt][nt][3]);
            } else {
                *(uint32_t*)((__half*)C + (size_t)row * N + col) =
                    packh2(acc[mt][nt][0], acc[mt][nt][1]);
                *(uint32_t*)((__half*)C + (size_t)(row + 8) * N + col) =
                    packh2(acc[mt][nt][2], acc[mt][nt][3]);
            }
        }
    }
}

// ---------------------------------------------------------------------------
// Flash attention: Q-RoPE via precomputed table fused into Q-tile load;
// cp.async double-buffered K/V; reversed qb order.
// ---------------------------------------------------------------------------
#define FA_BQ 128
#define FA_BK 64
#define FA_STR 136
#define FA_QS (FA_BQ * FA_STR)
#define FA_KV1 (FA_BK * FA_STR)
#define FA_STAGE (2 * FA_KV1)
#define FA_SMEM ((FA_QS + 2 * FA_STAGE) * 2)    // 104448 bytes

__global__ __launch_bounds__(256, 2) void flash_tc(const __half* __restrict__ Qsrc,
                                                   const __half* __restrict__ Kh,
                                                   const __half* __restrict__ Vsrc,
                                                   __half* __restrict__ Oh,
                                                   const float2* __restrict__ rtab,
                                                   float qmult)
{
    extern __shared__ __half sh[];
    __half* Qs = sh;

    const int qb = gridDim.x - 1 - blockIdx.x;   // long CTAs first
    const int h = blockIdx.y, b = blockIdx.z;
    const int kvh = h % HKV_;
    const int t = threadIdx.x, lane = t & 31, w = t >> 5;
    const int q0 = qb * FA_BQ;
    const int wq0 = w * 16;

    // Load Q tile from pre-rope QKV buffer, apply RoPE (table) + scale.
    {
#pragma unroll
        for (int i = 0; i < 8; ++i) {
            int linear = t + 256 * i;
            int row = linear >> 4;
            int c8 = (linear & 15) * 8;       // d base within head (0..120)
            const __half* base = Qsrc + (size_t)(b * Ss_ + q0 + row) * NQKV + h * HD_;
            uint4 own = *(const uint4*)(base + c8);
            uint4 par = *(const uint4*)(base + (c8 ^ 64));
            const __half2* o2 = (const __half2*)&own;
            const __half2* p2 = (const __half2*)&par;
            float sgn = (c8 < 64) ? -1.0f : 1.0f;
            int pos = q0 + row;
            const float2* tr = rtab + pos * 64 + (c8 & 63);
            uint4 res;
            uint32_t* r32 = (uint32_t*)&res;
#pragma unroll
            for (int e = 0; e < 4; ++e) {
                float2 f0 = tr[2 * e];
                float2 f1 = tr[2 * e + 1];
                float xa = __half2float(o2[e].x), xb = __half2float(o2[e].y);
                float ya = __half2float(p2[e].x), yb = __half2float(p2[e].y);
                r32[e] = packh2((xa * f0.x + sgn * ya * f0.y) * qmult,
                                (xb * f1.x + sgn * yb * f1.y) * qmult);
            }
            *(uint4*)&Qs[row * FA_STR + c8] = res;
        }
    }

    float oacc[16][4];
#pragma unroll
    for (int i = 0; i < 16; ++i)
#pragma unroll
        for (int j = 0; j < 4; ++j) oacc[i][j] = 0.0f;
    float mrow[2] = {-INFINITY, -INFINITY};
    float lrow[2] = {0.0f, 0.0f};

    const uint32_t sbase = smem_u32(sh);
    const uint32_t qa = sbase +
        (uint32_t)((wq0 + (lane & 15)) * (FA_STR * 2)) +
        (uint32_t)(((lane >> 4) & 1) * 16);
    const uint32_t k_rel =
        (uint32_t)(((lane & 7) + ((lane >> 4) & 1) * 8) * (FA_STR * 2)) +
        (uint32_t)(((lane >> 3) & 1) * 16);
    const uint32_t v_rel = (uint32_t)(FA_KV1 * 2) +
        (uint32_t)(((lane & 7) + ((lane >> 3) & 1) * 8) * (FA_STR * 2)) +
        (uint32_t)(((lane >> 4) & 1) * 16);

    auto load_kv = [&](int kb, int buf) {
        const int k0 = kb * FA_BK;
        const uint32_t sb = sbase + (uint32_t)(FA_QS + buf * FA_STAGE) * 2;
#pragma unroll
        for (int i = 0; i < 4; ++i) {
            int linear = t + 256 * i;
            int row = linear >> 4;
            int c8 = (linear & 15) * 8;
            uint32_t s = sb + (uint32_t)(row * FA_STR + c8) * 2;
            CPA16(s, Kh + (size_t)(b * Ss_ + k0 + row) * NKV + kvh * HD_ + c8);
            CPA16(s + FA_KV1 * 2,
                  Vsrc + (size_t)(b * Ss_ + k0 + row) * NQKV + kvh * HD_ + c8);
        }
    };

    const int nkb = (q0 + FA_BQ) / FA_BK;
    load_kv(0, 0);
    CP_COMMIT();

    for (int kb = 0; kb < nkb; ++kb) {
        const int buf = kb & 1;
        const int k0 = kb * FA_BK;
        if (kb + 1 < nkb) {
            load_kv(kb + 1, buf ^ 1);
            CP_COMMIT();
            CP_WAIT1();
        } else {
            CP_WAIT0();
        }
        __syncthreads();

        const uint32_t stg = sbase + (uint32_t)(FA_QS + buf * FA_STAGE) * 2;
        const uint32_t ka = stg + k_rel;
        const uint32_t va = stg + v_rel;

        if (k0 <= q0 + wq0 + 15) {
            float sacc[8][4];
#pragma unroll
            for (int i = 0; i < 8; ++i)
#pragma unroll
                for (int j = 0; j < 4; ++j) sacc[i][j] = 0.0f;

#pragma unroll
            for (int kk = 0; kk < 8; ++kk) {
                uint32_t af[4];
                ldsm_x4(af, qa + kk * 32);
#pragma unroll
                for (int np = 0; np < 4; ++np) {
                    uint32_t bf[4];
                    ldsm_x4(bf, ka + np * 16 * (FA_STR * 2) + kk * 32);
                    mma16816h(sacc[np * 2],     af, bf);
                    mma16816h(sacc[np * 2 + 1], af, bf + 2);
                }
            }

            if (k0 + FA_BK - 1 > q0 + wq0) {
                const int rbase = q0 + wq0 + (lane >> 2);
                const int cbase = k0 + (lane & 3) * 2;
#pragma unroll
                for (int nt = 0; nt < 8; ++nt)
#pragma unroll
                    for (int e = 0; e < 4; ++e) {
                        int col = cbase + nt * 8 + (e & 1);
                        int row = rbase + (e >> 1) * 8;
                        if (col > row) sacc[nt][e] = -INFINITY;
                    }
            }

#pragma unroll
            for (int r = 0; r < 2; ++r) {
                float mx = -INFINITY;
#pragma unroll
                for (int nt = 0; nt < 8; ++nt)
                    mx = fmaxf(mx, fmaxf(sacc[nt][2 * r], sacc[nt][2 * r + 1]));
                mx = fmaxf(mx, __shfl_xor_sync(0xffffffffu, mx, 1));
                mx = fmaxf(mx, __shfl_xor_sync(0xffffffffu, mx, 2));
                float mn = fmaxf(mrow[r], mx);
                float al = ex2f(mrow[r] - mn);
                mrow[r] = mn;
                float rs = 0.0f;
#pragma unroll
                for (int nt = 0; nt < 8; ++nt) {
                    float p0 = ex2f(sacc[nt][2 * r] - mn);
                    float p1 = ex2f(sacc[nt][2 * r + 1] - mn);
                    sacc[nt][2 * r] = p0;
                    sacc[nt][2 * r + 1] = p1;
                    rs += p0 + p1;
                }
                rs += __shfl_xor_sync(0xffffffffu, rs, 1);
                rs += __shfl_xor_sync(0xffffffffu, rs, 2);
                lrow[r] = lrow[r] * al + rs;
#pragma unroll
                for (int nt = 0; nt < 16; ++nt) {
                    oacc[nt][2 * r]     *= al;
                    oacc[nt][2 * r + 1] *= al;
                }
            }

#pragma unroll
            for (int j = 0; j < 4; ++j) {
                uint32_t a[4];
                a[0] = packh2(sacc[2 * j][0],     sacc[2 * j][1]);
                a[1] = packh2(sacc[2 * j][2],     sacc[2 * j][3]);
                a[2] = packh2(sacc[2 * j + 1][0], sacc[2 * j + 1][1]);
                a[3] = packh2(sacc[2 * j + 1][2], sacc[2 * j + 1][3]);
#pragma unroll
                for (int dp = 0; dp < 8; ++dp) {
                    uint32_t bf[4];
                    ldsm_x4_t(bf, va + j * 16 * (FA_STR * 2) + dp * 32);
                    mma16816h(oacc[dp * 2],     a, bf);
                    mma16816h(oacc[dp * 2 + 1], a, bf + 2);
                }
            }
        }
        __syncthreads();
    }

#pragma unroll
    for (int r = 0; r < 2; ++r) {
        float inv = 1.0f / lrow[r];
        int row = q0 + wq0 + (lane >> 2) + r * 8;
        __half* Og = Oh + (size_t)(b * Ss_ + row) * Dd_ + h * HD_;
#pragma unroll
        for (int nt = 0; nt < 16; ++nt) {
            int col = nt * 8 + (lane & 3) * 2;
            *(uint32_t*)(Og + col) =
                packh2(oacc[nt][2 * r] * inv, oacc[nt][2 * r + 1] * inv);
        }
    }
}

// ---------------------------------------------------------------------------
// Launch
// ---------------------------------------------------------------------------
extern "C" void kernel_launch(void* const* d_in, const int* in_sizes, int n_in,
                              void* d_out, int out_size)
{
    const float* x  = (const float*)d_in[0];
    const float* Wq = (const float*)d_in[2];
    const float* Wk = (const float*)d_in[3];
    const float* Wv = (const float*)d_in[4];
    const float* Wo = (const float*)d_in[5];
    float* out = (float*)d_out;

    __half *Xhp, *Wqkvp, *QKVp, *Khp, *Ohp, *Wohp;
    float2* rtabp;
    cudaGetSymbolAddress((void**)&Xhp, g_Xh);
    cudaGetSymbolAddress((void**)&Wqkvp, g_Wqkv);
    cudaGetSymbolAddress((void**)&QKVp, g_QKV);
    cudaGetSymbolAddress((void**)&Khp, g_Kh);
    cudaGetSymbolAddress((void**)&Ohp, g_Oh);
    cudaGetSymbolAddress((void**)&Wohp, g_Woh);
    cudaGetSymbolAddress((void**)&rtabp, g_rope);

    cudaFuncSetAttribute(gemm_f16x1<__half>,
                         cudaFuncAttributeMaxDynamicSharedMemorySize, G1_SMEM);
    cudaFuncSetAttribute(gemm_f16x1<float>,
                         cudaFuncAttributeMaxDynamicSharedMemorySize, G1_SMEM);
    cudaFuncSetAttribute(flash_tc,
                         cudaFuncAttributeMaxDynamicSharedMemorySize, FA_SMEM);

    const int nX  = MROWS * Dd_;       // 8.4M
    const int nWq = Dd_ * Dd_;         // 4.2M
    const int nWk = Dd_ * NKV;         // 0.5M

    // Host-accurate inv_freq table (double precision)
    RopeTab rt;
    for (int i = 0; i < 64; ++i)
        rt.v[i] = (float)exp(-(double)i * (log(10000.0) / 64.0));
    const float qmult = 1.4426950408889634f / sqrtf((float)HD_);

    // Rope cos/sin table (131K sincosf, once)
    rope_fill_k<<<(Ss_ * 64) / 256, 256>>>(rtabp, rt);

    // A side: x -> fp16
    convert_half_k<<<nX / 2048, 256>>>(x, Xhp, nX);

    // B side: [Wq | Wk | Wv] -> fp16 combined; Wo -> fp16
    convert_half_to_strided<<<nWq / 1024, 256>>>(Wq, Wqkvp, Dd_, NQKV, 0, nWq);
    convert_kv_weights<<<nWk / 1024, 256>>>(Wk, Wv, Wqkvp, nWk);
    convert_half_k<<<nWq / 2048, 256>>>(Wo, Wohp, nWq);

    // QKV = x @ [Wq|Wk|Wv]  (single-pass fp16, fp16 out)
    gemm_f16x1<__half><<<dim3(NQKV / 128, MROWS / 128), 256, G1_SMEM>>>(
        Xhp, Wqkvp, QKVp, MROWS, NQKV, Dd_);

    // K RoPE via table; Q rope fused into flash; V in-place from QKV
    {
        int totk = MROWS * HKV_ * 64;
        rope_h2h<<<(totk + 255) / 256, 256>>>(QKVp + Dd_, Khp, rtabp,
                                              HKV_, NQKV, NKV, totk);
    }

    // Flash attention (Q pre-rope from QKV buffer; table rope in Q load)
    flash_tc<<<dim3(Ss_ / FA_BQ, Hh_, Bb_), 256, FA_SMEM>>>(
        QKVp, Khp, QKVp + VOFF, Ohp, rtabp, qmult);

    // out = O @ Wo (single-pass fp16, fp32 out)
    gemm_f16x1<float><<<dim3(Dd_ / 128, MROWS / 128), 256, G1_SMEM>>>(
        Ohp, Wohp, out, MROWS, Dd_, Dd_);
}

// round 16
// speedup vs baseline: 2.2120x; 1.0268x over previous
#include <cuda_runtime.h>
#include <cuda_fp16.h>
#include <math.h>
#include <stdint.h>

// Problem constants
#define Bb_ 2
#define Ss_ 2048
#define Dd_ 2048
#define Hh_ 16
#define HKV_ 2
#define HD_ 128
#define MROWS (Bb_ * Ss_)          // 4096
#define NKV (HKV_ * HD_)           // 256
#define NQKV 2560                  // Q(2048) | K(256) | V(256)
#define VOFF 2304                  // V column offset in QKV buffer

// Scratch (allocation-free: __device__ globals)
__device__ __half g_Xh[(size_t)MROWS * Dd_];        // x as fp16 (A side)
__device__ __half g_Wqkv[(size_t)Dd_ * NQKV];       // [Wq|Wk|Wv] fp16
__device__ __half g_QKV[(size_t)MROWS * NQKV];      // pre-rope QKV (fp16)
__device__ __half g_Kh[(size_t)MROWS * NKV];        // post-rope K
__device__ __half g_Oh[(size_t)MROWS * Dd_];        // attn out (A of Wo gemm)
__device__ __half g_Woh[(size_t)Dd_ * Dd_];         // Wo fp16
__device__ float2 g_rope[(size_t)Ss_ * 64];         // (cos,sin) per (pos, d)

struct RopeTab { float v[64]; };                    // inv_freq (host, double-acc)

// ---------------------------------------------------------------------------
// Helpers
// ---------------------------------------------------------------------------
static __device__ __forceinline__ uint32_t smem_u32(const void* p) {
    uint32_t r;
    asm("{ .reg .u64 t; cvta.to.shared.u64 t, %1; cvt.u32.u64 %0, t; }"
        : "=r"(r) : "l"(p));
    return r;
}

static __device__ __forceinline__ void mma16816h(float* c, const uint32_t* a,
                                                 const uint32_t* b) {
    asm volatile(
        "mma.sync.aligned.m16n8k16.row.col.f32.f16.f16.f32 "
        "{%0,%1,%2,%3}, {%4,%5,%6,%7}, {%8,%9}, {%0,%1,%2,%3};"
        : "+f"(c[0]), "+f"(c[1]), "+f"(c[2]), "+f"(c[3])
        : "r"(a[0]), "r"(a[1]), "r"(a[2]), "r"(a[3]), "r"(b[0]), "r"(b[1]));
}

static __device__ __forceinline__ void ldsm_x4(uint32_t* r, uint32_t addr) {
    asm volatile("ldmatrix.sync.aligned.m8n8.x4.shared.b16 {%0,%1,%2,%3}, [%4];"
                 : "=r"(r[0]), "=r"(r[1]), "=r"(r[2]), "=r"(r[3]) : "r"(addr));
}

static __device__ __forceinline__ void ldsm_x4_t(uint32_t* r, uint32_t addr) {
    asm volatile("ldmatrix.sync.aligned.m8n8.x4.trans.shared.b16 {%0,%1,%2,%3}, [%4];"
                 : "=r"(r[0]), "=r"(r[1]), "=r"(r[2]), "=r"(r[3]) : "r"(addr));
}

static __device__ __forceinline__ void ldsm_x2_t(uint32_t* r, uint32_t addr) {
    asm volatile("ldmatrix.sync.aligned.m8n8.x2.trans.shared.b16 {%0,%1}, [%2];"
                 : "=r"(r[0]), "=r"(r[1]) : "r"(addr));
}

static __device__ __forceinline__ float ex2f(float x) {
    float y;
    asm("ex2.approx.f32 %0, %1;" : "=f"(y) : "f"(x));
    return y;
}

static __device__ __forceinline__ uint32_t packh2(float a, float b) {
    __half2 h = __floats2half2_rn(a, b);
    return *reinterpret_cast<uint32_t*>(&h);
}

#define CPA16(dst, src) \
    asm volatile("cp.async.cg.shared.global [%0], [%1], 16;" :: "r"(dst), "l"(src))
#define CP_COMMIT() asm volatile("cp.async.commit_group;" ::: "memory")
#define CP_WAIT1() asm volatile("cp.async.wait_group 1;" ::: "memory")
#define CP_WAIT0() asm volatile("cp.async.wait_group 0;" ::: "memory")

// ---------------------------------------------------------------------------
// Fused prep: rope table + x->fp16 + Wq/Wk/Wv->strided fp16 + Wo->fp16.
// Region dispatch by blockIdx range (all region sizes 256-divisible).
//   R0: rope table   512 blocks   (131072 x 1 elem)
//   R1: x -> Xh     4096 blocks   (8 elems/thread)
//   R2: Wq strided  4096 blocks   (4 elems/thread)
//   R3: Wk|Wv       512 blocks    (4+4 elems/thread)
//   R4: Wo -> Woh   2048 blocks   (8 elems/thread)
// ---------------------------------------------------------------------------
#define PREP_R0 512
#define PREP_R1 (PREP_R0 + 4096)
#define PREP_R2 (PREP_R1 + 4096)
#define PREP_R3 (PREP_R2 + 512)
#define PREP_R4 (PREP_R3 + 2048)   // total 11264 blocks

__global__ void prep_all(const float* __restrict__ x,
                         const float* __restrict__ Wq,
                         const float* __restrict__ Wk,
                         const float* __restrict__ Wv,
                         const float* __restrict__ Wo,
                         __half* __restrict__ Xh,
                         __half* __restrict__ Wqkv,
                         __half* __restrict__ Woh,
                         float2* __restrict__ rtab,
                         RopeTab rt)
{
    const int blk = blockIdx.x;
    const int tid = threadIdx.x;

    if (blk < PREP_R0) {
        int idx = blk * 256 + tid;              // 0 .. 131071
        int d = idx & 63;
        int pos = idx >> 6;
        float sn, cs;
        sincosf((float)pos * rt.v[d], &sn, &cs);
        rtab[idx] = make_float2(cs, sn);
    } else if (blk < PREP_R1) {
        int i = ((blk - PREP_R0) * 256 + tid) * 8;
        float4 a = *(const float4*)(x + i);
        float4 b = *(const float4*)(x + i + 4);
        uint4 o;
        o.x = packh2(a.x, a.y);
        o.y = packh2(a.z, a.w);
        o.z = packh2(b.x, b.y);
        o.w = packh2(b.z, b.w);
        *(uint4*)(Xh + i) = o;
    } else if (blk < PREP_R2) {
        int i = ((blk - PREP_R1) * 256 + tid) * 4;
        int r = i >> 11, c = i & 2047;          // cols = Dd_ = 2048
        float4 v = *(const float4*)(Wq + i);
        uint2 o;
        o.x = packh2(v.x, v.y);
        o.y = packh2(v.z, v.w);
        *(uint2*)(Wqkv + (size_t)r * NQKV + c) = o;
    } else if (blk < PREP_R3) {
        int i = ((blk - PREP_R2) * 256 + tid) * 4;
        int r = i >> 8, c = i & 255;            // cols = NKV = 256
        float4 a = *(const float4*)(Wk + i);
        float4 b = *(const float4*)(Wv + i);
        uint2 oa, ob;
        oa.x = packh2(a.x, a.y);  oa.y = packh2(a.z, a.w);
        ob.x = packh2(b.x, b.y);  ob.y = packh2(b.z, b.w);
        *(uint2*)(Wqkv + (size_t)r * NQKV + Dd_ + c)  = oa;
        *(uint2*)(Wqkv + (size_t)r * NQKV + VOFF + c) = ob;
    } else {
        int i = ((blk - PREP_R3) * 256 + tid) * 8;
        float4 a = *(const float4*)(Wo + i);
        float4 b = *(const float4*)(Wo + i + 4);
        uint4 o;
        o.x = packh2(a.x, a.y);
        o.y = packh2(a.z, a.w);
        o.z = packh2(b.x, b.y);
        o.w = packh2(b.z, b.w);
        *(uint4*)(Woh + i) = o;
    }
}

// RoPE fp16 -> fp16 via table, strided in/out (K only)
__global__ void rope_h2h(const __half* __restrict__ in, __half* __restrict__ out,
                         const float2* __restrict__ tab,
                         int nh, int ld_in, int ld_out, int total)
{
    int idx = blockIdx.x * blockDim.x + threadIdx.x;
    if (idx >= total) return;
    int i    = idx & 63;
    int hh   = (idx >> 6) % nh;
    int srow = idx / (64 * nh);
    int pos  = srow & (Ss_ - 1);

    float2 cssn = tab[pos * 64 + i];

    size_t bi = (size_t)srow * ld_in + (size_t)hh * HD_ + i;
    size_t bo = (size_t)srow * ld_out + (size_t)hh * HD_ + i;
    float x1 = __half2float(in[bi]);
    float x2 = __half2float(in[bi + 64]);
    out[bo]      = __float2half(x1 * cssn.x - x2 * cssn.y);
    out[bo + 64] = __float2half(x2 * cssn.x + x1 * cssn.y);
}

// ---------------------------------------------------------------------------
// Single-pass fp16 GEMM (templated output type), cp.async 2-stage. (validated)
// ---------------------------------------------------------------------------
#define SA_STRIDE 72
#define SB_STRIDE 136
#define SA_SZ (128 * SA_STRIDE)
#define SB_SZ (64 * SB_STRIDE)
#define STG1_BYTES ((SA_SZ + SB_SZ) * 2)      // 35840
#define G1_SMEM (2 * STG1_BYTES)              // 71680

template <typename TO>
__global__ __launch_bounds__(256, 2) void gemm_f16x1(const __half* __restrict__ Ah,
                                                     const __half* __restrict__ Bh,
                                                     TO* __restrict__ C,
                                                     int M, int N, int K)
{
    extern __shared__ __half smh[];
    const uint32_t sbase = smem_u32(smh);

    const int t    = threadIdx.x;
    const int lane = t & 31;
    const int wid  = t >> 5;
    const int wm   = wid & 1;
    const int wn   = wid >> 1;
    const int n0   = blockIdx.x * 128;
    const int m0   = blockIdx.y * 128;

    float acc[4][4][4];
#pragma unroll
    for (int i = 0; i < 4; ++i)
#pragma unroll
        for (int j = 0; j < 4; ++j)
#pragma unroll
            for (int k = 0; k < 4; ++k) acc[i][j][k] = 0.0f;

    auto load_stage = [&](int c, int buf) {
        const int k0 = c << 6;
        const uint32_t sb = sbase + (uint32_t)buf * STG1_BYTES;
#pragma unroll
        for (int i = 0; i < 4; ++i) {
            int li = t + 256 * i;
            int row = li >> 3, v = li & 7;
            const size_t g = (size_t)(m0 + row) * K + k0 + v * 8;
            CPA16(sb + (uint32_t)(row * SA_STRIDE + v * 8) * 2, Ah + g);
        }
#pragma unroll
        for (int i = 0; i < 4; ++i) {
            int li = t + 256 * i;
            int row = li >> 4, v = li & 15;
            const size_t g = (size_t)(k0 + row) * N + n0 + v * 8;
            CPA16(sb + (uint32_t)(SA_SZ + row * SB_STRIDE + v * 8) * 2, Bh + g);
        }
    };

    const uint32_t a_rel =
        (uint32_t)(((lane & 7) + ((lane >> 3) & 1) * 8 + wm * 64) * (SA_STRIDE * 2)) +
        (uint32_t)(((lane >> 4) & 1) * 16);
    const uint32_t b_rel = (uint32_t)(SA_SZ * 2) +
        (uint32_t)(((lane & 7) + ((lane >> 3) & 1) * 8) * (SB_STRIDE * 2)) +
        (uint32_t)(wn * 64);

    const int nch = K >> 6;
    load_stage(0, 0);
    CP_COMMIT();

    for (int c = 0; c < nch; ++c) {
        const int buf = c & 1;
        if (c + 1 < nch) {
            load_stage(c + 1, (c + 1) & 1);
            CP_COMMIT();
            CP_WAIT1();
        } else {
            CP_WAIT0();
        }
        __syncthreads();

        const uint32_t stg = sbase + (uint32_t)buf * STG1_BYTES;
        const uint32_t a_addr = stg + a_rel;
        const uint32_t b_addr = stg + b_rel;

#pragma unroll
        for (int k16 = 0; k16 < 4; ++k16) {
            uint32_t bh[4][2], af[4][4];
            const uint32_t bko = (uint32_t)(k16 * 16 * SB_STRIDE * 2);
#pragma unroll
            for (int nt = 0; nt < 4; ++nt)
                ldsm_x2_t(bh[nt], b_addr + nt * 16 + bko);
            const uint32_t ako = (uint32_t)(k16 * 32);
#pragma unroll
            for (int mt = 0; mt < 4; ++mt)
                ldsm_x4(af[mt], a_addr + mt * (16 * SA_STRIDE * 2) + ako);
#pragma unroll
            for (int mt = 0; mt < 4; ++mt)
#pragma unroll
                for (int nt = 0; nt < 4; ++nt)
                    mma16816h(acc[mt][nt], af[mt], bh[nt]);
        }
        __syncthreads();
    }

    const int g   = lane >> 2;
    const int tid = lane & 3;
#pragma unroll
    for (int mt = 0; mt < 4; ++mt) {
        const int row = m0 + wm * 64 + mt * 16 + g;
#pragma unroll
        for (int nt = 0; nt < 4; ++nt) {
            const int col = n0 + wn * 32 + nt * 8 + tid * 2;
            if (sizeof(TO) == 4) {
                *(float2*)((float*)C + (size_t)row * N + col) =
                    make_float2(acc[mt][nt][0], acc[mt][nt][1]);
                *(float2*)((float*)C + (size_t)(row + 8) * N + col) =
                    make_float2(acc[mt][nt][2], acc[mt][nt][3]);
            } else {
                *(uint32_t*)((__half*)C + (size_t)row * N + col) =
                    packh2(acc[mt][nt][0], acc[mt][nt][1]);
                *(uint32_t*)((__half*)C + (size_t)(row + 8) * N + col) =
                    packh2(acc[mt][nt][2], acc[mt][nt][3]);
            }
        }
    }
}

// ---------------------------------------------------------------------------
// Flash attention: Q-RoPE via precomputed table fused into Q-tile load;
// cp.async double-buffered K/V; reversed qb order. (validated R14)
// ---------------------------------------------------------------------------
#define FA_BQ 128
#define FA_BK 64
#define FA_STR 136
#define FA_QS (FA_BQ * FA_STR)
#define FA_KV1 (FA_BK * FA_STR)
#define FA_STAGE (2 * FA_KV1)
#define FA_SMEM ((FA_QS + 2 * FA_STAGE) * 2)    // 104448 bytes

__global__ __launch_bounds__(256, 2) void flash_tc(const __half* __restrict__ Qsrc,
                                                   const __half* __restrict__ Kh,
                                                   const __half* __restrict__ Vsrc,
                                                   __half* __restrict__ Oh,
                                                   const float2* __restrict__ rtab,
                                                   float qmult)
{
    extern __shared__ __half sh[];
    __half* Qs = sh;

    const int qb = gridDim.x - 1 - blockIdx.x;   // long CTAs first
    const int h = blockIdx.y, b = blockIdx.z;
    const int kvh = h % HKV_;
    const int t = threadIdx.x, lane = t & 31, w = t >> 5;
    const int q0 = qb * FA_BQ;
    const int wq0 = w * 16;

    // Load Q tile from pre-rope QKV buffer, apply RoPE (table) + scale.
    {
#pragma unroll
        for (int i = 0; i < 8; ++i) {
            int linear = t + 256 * i;
            int row = linear >> 4;
            int c8 = (linear & 15) * 8;       // d base within head (0..120)
            const __half* base = Qsrc + (size_t)(b * Ss_ + q0 + row) * NQKV + h * HD_;
            uint4 own = *(const uint4*)(base + c8);
            uint4 par = *(const uint4*)(base + (c8 ^ 64));
            const __half2* o2 = (const __half2*)&own;
            const __half2* p2 = (const __half2*)&par;
            float sgn = (c8 < 64) ? -1.0f : 1.0f;
            int pos = q0 + row;
            const float2* tr = rtab + pos * 64 + (c8 & 63);
            uint4 res;
            uint32_t* r32 = (uint32_t*)&res;
#pragma unroll
            for (int e = 0; e < 4; ++e) {
                float2 f0 = tr[2 * e];
                float2 f1 = tr[2 * e + 1];
                float xa = __half2float(o2[e].x), xb = __half2float(o2[e].y);
                float ya = __half2float(p2[e].x), yb = __half2float(p2[e].y);
                r32[e] = packh2((xa * f0.x + sgn * ya * f0.y) * qmult,
                                (xb * f1.x + sgn * yb * f1.y) * qmult);
            }
            *(uint4*)&Qs[row * FA_STR + c8] = res;
        }
    }

    float oacc[16][4];
#pragma unroll
    for (int i = 0; i < 16; ++i)
#pragma unroll
        for (int j = 0; j < 4; ++j) oacc[i][j] = 0.0f;
    float mrow[2] = {-INFINITY, -INFINITY};
    float lrow[2] = {0.0f, 0.0f};

    const uint32_t sbase = smem_u32(sh);
    const uint32_t qa = sbase +
        (uint32_t)((wq0 + (lane & 15)) * (FA_STR * 2)) +
        (uint32_t)(((lane >> 4) & 1) * 16);
    const uint32_t k_rel =
        (uint32_t)(((lane & 7) + ((lane >> 4) & 1) * 8) * (FA_STR * 2)) +
        (uint32_t)(((lane >> 3) & 1) * 16);
    const uint32_t v_rel = (uint32_t)(FA_KV1 * 2) +
        (uint32_t)(((lane & 7) + ((lane >> 3) & 1) * 8) * (FA_STR * 2)) +
        (uint32_t)(((lane >> 4) & 1) * 16);

    auto load_kv = [&](int kb, int buf) {
        const int k0 = kb * FA_BK;
        const uint32_t sb = sbase + (uint32_t)(FA_QS + buf * FA_STAGE) * 2;
#pragma unroll
        for (int i = 0; i < 4; ++i) {
            int linear = t + 256 * i;
            int row = linear >> 4;
            int c8 = (linear & 15) * 8;
            uint32_t s = sb + (uint32_t)(row * FA_STR + c8) * 2;
            CPA16(s, Kh + (size_t)(b * Ss_ + k0 + row) * NKV + kvh * HD_ + c8);
            CPA16(s + FA_KV1 * 2,
                  Vsrc + (size_t)(b * Ss_ + k0 + row) * NQKV + kvh * HD_ + c8);
        }
    };

    const int nkb = (q0 + FA_BQ) / FA_BK;
    load_kv(0, 0);
    CP_COMMIT();

    for (int kb = 0; kb < nkb; ++kb) {
        const int buf = kb & 1;
        const int k0 = kb * FA_BK;
        if (kb + 1 < nkb) {
            load_kv(kb + 1, buf ^ 1);
            CP_COMMIT();
            CP_WAIT1();
        } else {
            CP_WAIT0();
        }
        __syncthreads();

        const uint32_t stg = sbase + (uint32_t)(FA_QS + buf * FA_STAGE) * 2;
        const uint32_t ka = stg + k_rel;
        const uint32_t va = stg + v_rel;

        if (k0 <= q0 + wq0 + 15) {
            float sacc[8][4];
#pragma unroll
            for (int i = 0; i < 8; ++i)
#pragma unroll
                for (int j = 0; j < 4; ++j) sacc[i][j] = 0.0f;

#pragma unroll
            for (int kk = 0; kk < 8; ++kk) {
                uint32_t af[4];
                ldsm_x4(af, qa + kk * 32);
#pragma unroll
                for (int np = 0; np < 4; ++np) {
                    uint32_t bf[4];
                    ldsm_x4(bf, ka + np * 16 * (FA_STR * 2) + kk * 32);
                    mma16816h(sacc[np * 2],     af, bf);
                    mma16816h(sacc[np * 2 + 1], af, bf + 2);
                }
            }

            if (k0 + FA_BK - 1 > q0 + wq0) {
                const int rbase = q0 + wq0 + (lane >> 2);
                const int cbase = k0 + (lane & 3) * 2;
#pragma unroll
                for (int nt = 0; nt < 8; ++nt)
#pragma unroll
                    for (int e = 0; e < 4; ++e) {
                        int col = cbase + nt * 8 + (e & 1);
                        int row = rbase + (e >> 1) * 8;
                        if (col > row) sacc[nt][e] = -INFINITY;
                    }
            }

#pragma unroll
            for (int r = 0; r < 2; ++r) {
                float mx = -INFINITY;
#pragma unroll
                for (int nt = 0; nt < 8; ++nt)
                    mx = fmaxf(mx, fmaxf(sacc[nt][2 * r], sacc[nt][2 * r + 1]));
                mx = fmaxf(mx, __shfl_xor_sync(0xffffffffu, mx, 1));
                mx = fmaxf(mx, __shfl_xor_sync(0xffffffffu, mx, 2));
                float mn = fmaxf(mrow[r], mx);
                float al = ex2f(mrow[r] - mn);
                mrow[r] = mn;
                float rs = 0.0f;
#pragma unroll
                for (int nt = 0; nt < 8; ++nt) {
                    float p0 = ex2f(sacc[nt][2 * r] - mn);
                    float p1 = ex2f(sacc[nt][2 * r + 1] - mn);
                    sacc[nt][2 * r] = p0;
                    sacc[nt][2 * r + 1] = p1;
                    rs += p0 + p1;
                }
                rs += __shfl_xor_sync(0xffffffffu, rs, 1);
                rs += __shfl_xor_sync(0xffffffffu, rs, 2);
                lrow[r] = lrow[r] * al + rs;
#pragma unroll
                for (int nt = 0; nt < 16; ++nt) {
                    oacc[nt][2 * r]     *= al;
                    oacc[nt][2 * r + 1] *= al;
                }
            }

#pragma unroll
            for (int j = 0; j < 4; ++j) {
                uint32_t a[4];
                a[0] = packh2(sacc[2 * j][0],     sacc[2 * j][1]);
                a[1] = packh2(sacc[2 * j][2],     sacc[2 * j][3]);
                a[2] = packh2(sacc[2 * j + 1][0], sacc[2 * j + 1][1]);
                a[3] = packh2(sacc[2 * j + 1][2], sacc[2 * j + 1][3]);
#pragma unroll
                for (int dp = 0; dp < 8; ++dp) {
                    uint32_t bf[4];
                    ldsm_x4_t(bf, va + j * 16 * (FA_STR * 2) + dp * 32);
                    mma16816h(oacc[dp * 2],     a, bf);
                    mma16816h(oacc[dp * 2 + 1], a, bf + 2);
                }
            }
        }
        __syncthreads();
    }

#pragma unroll
    for (int r = 0; r < 2; ++r) {
        float inv = 1.0f / lrow[r];
        int row = q0 + wq0 + (lane >> 2) + r * 8;
        __half* Og = Oh + (size_t)(b * Ss_ + row) * Dd_ + h * HD_;
#pragma unroll
        for (int nt = 0; nt < 16; ++nt) {
            int col = nt * 8 + (lane & 3) * 2;
            *(uint32_t*)(Og + col) =
                packh2(oacc[nt][2 * r] * inv, oacc[nt][2 * r + 1] * inv);
        }
    }
}

// ---------------------------------------------------------------------------
// Launch
// ---------------------------------------------------------------------------
extern "C" void kernel_launch(void* const* d_in, const int* in_sizes, int n_in,
                              void* d_out, int out_size)
{
    const float* x  = (const float*)d_in[0];
    const float* Wq = (const float*)d_in[2];
    const float* Wk = (const float*)d_in[3];
    const float* Wv = (const float*)d_in[4];
    const float* Wo = (const float*)d_in[5];
    float* out = (float*)d_out;

    __half *Xhp, *Wqkvp, *QKVp, *Khp, *Ohp, *Wohp;
    float2* rtabp;
    cudaGetSymbolAddress((void**)&Xhp, g_Xh);
    cudaGetSymbolAddress((void**)&Wqkvp, g_Wqkv);
    cudaGetSymbolAddress((void**)&QKVp, g_QKV);
    cudaGetSymbolAddress((void**)&Khp, g_Kh);
    cudaGetSymbolAddress((void**)&Ohp, g_Oh);
    cudaGetSymbolAddress((void**)&Wohp, g_Woh);
    cudaGetSymbolAddress((void**)&rtabp, g_rope);

    cudaFuncSetAttribute(gemm_f16x1<__half>,
                         cudaFuncAttributeMaxDynamicSharedMemorySize, G1_SMEM);
    cudaFuncSetAttribute(gemm_f16x1<float>,
                         cudaFuncAttributeMaxDynamicSharedMemorySize, G1_SMEM);
    cudaFuncSetAttribute(flash_tc,
                         cudaFuncAttributeMaxDynamicSharedMemorySize, FA_SMEM);

    // Host-accurate inv_freq table (double precision)
    RopeTab rt;
    for (int i = 0; i < 64; ++i)
        rt.v[i] = (float)exp(-(double)i * (log(10000.0) / 64.0));
    const float qmult = 1.4426950408889634f / sqrtf((float)HD_);

    // ONE fused prep kernel: rope table + all fp32->fp16 conversions
    prep_all<<<PREP_R4, 256>>>(x, Wq, Wk, Wv, Wo, Xhp, Wqkvp, Wohp, rtabp, rt);

    // QKV = x @ [Wq|Wk|Wv]  (single-pass fp16, fp16 out)
    gemm_f16x1<__half><<<dim3(NQKV / 128, MROWS / 128), 256, G1_SMEM>>>(
        Xhp, Wqkvp, QKVp, MROWS, NQKV, Dd_);

    // K RoPE via table; Q rope fused into flash; V in-place from QKV
    {
        int totk = MROWS * HKV_ * 64;
        rope_h2h<<<(totk + 255) / 256, 256>>>(QKVp + Dd_, Khp, rtabp,
                                              HKV_, NQKV, NKV, totk);
    }

    // Flash attention (Q pre-rope from QKV buffer; table rope in Q load)
    flash_tc<<<dim3(Ss_ / FA_BQ, Hh_, Bb_), 256, FA_SMEM>>>(
        QKVp, Khp, QKVp + VOFF, Ohp, rtabp, qmult);

    // out = O @ Wo (single-pass fp16, fp32 out)
    gemm_f16x1<float><<<dim3(Dd_ / 128, MROWS / 128), 256, G1_SMEM>>>(
        Ohp, Wohp, out, MROWS, Dd_, Dd_);
}

// round 17
// speedup vs baseline: 2.2451x; 1.0150x over previous
#include <cuda_runtime.h>
#include <cuda_fp16.h>
#include <math.h>
#include <stdint.h>

// Problem constants
#define Bb_ 2
#define Ss_ 2048
#define Dd_ 2048
#define Hh_ 16
#define HKV_ 2
#define HD_ 128
#define MROWS (Bb_ * Ss_)          // 4096
#define NKV (HKV_ * HD_)           // 256
#define NQKV 2560                  // Q(2048) | K(256) | V(256)
#define VOFF 2304                  // V column offset in QKV buffer

// Scratch (allocation-free: __device__ globals)
__device__ __half g_Xh[(size_t)MROWS * Dd_];        // x as fp16 (A side)
__device__ __half g_Wqkv[(size_t)Dd_ * NQKV];       // [Wq|Wk|Wv] fp16
__device__ __half g_QKV[(size_t)MROWS * NQKV];      // pre-rope QKV (fp16)
__device__ __half g_Kh[(size_t)MROWS * NKV];        // post-rope K
__device__ __half g_Oh[(size_t)MROWS * Dd_];        // attn out (A of Wo gemm)
__device__ __half g_Woh[(size_t)Dd_ * Dd_];         // Wo fp16
__device__ float2 g_rope[(size_t)Ss_ * 64];         // (cos,sin) per (pos, d)

struct RopeTab { float v[64]; };                    // inv_freq (host, double-acc)

// ---------------------------------------------------------------------------
// Helpers
// ---------------------------------------------------------------------------
static __device__ __forceinline__ uint32_t smem_u32(const void* p) {
    uint32_t r;
    asm("{ .reg .u64 t; cvta.to.shared.u64 t, %1; cvt.u32.u64 %0, t; }"
        : "=r"(r) : "l"(p));
    return r;
}

static __device__ __forceinline__ void mma16816h(float* c, const uint32_t* a,
                                                 const uint32_t* b) {
    asm volatile(
        "mma.sync.aligned.m16n8k16.row.col.f32.f16.f16.f32 "
        "{%0,%1,%2,%3}, {%4,%5,%6,%7}, {%8,%9}, {%0,%1,%2,%3};"
        : "+f"(c[0]), "+f"(c[1]), "+f"(c[2]), "+f"(c[3])
        : "r"(a[0]), "r"(a[1]), "r"(a[2]), "r"(a[3]), "r"(b[0]), "r"(b[1]));
}

static __device__ __forceinline__ void ldsm_x4(uint32_t* r, uint32_t addr) {
    asm volatile("ldmatrix.sync.aligned.m8n8.x4.shared.b16 {%0,%1,%2,%3}, [%4];"
                 : "=r"(r[0]), "=r"(r[1]), "=r"(r[2]), "=r"(r[3]) : "r"(addr));
}

static __device__ __forceinline__ void ldsm_x4_t(uint32_t* r, uint32_t addr) {
    asm volatile("ldmatrix.sync.aligned.m8n8.x4.trans.shared.b16 {%0,%1,%2,%3}, [%4];"
                 : "=r"(r[0]), "=r"(r[1]), "=r"(r[2]), "=r"(r[3]) : "r"(addr));
}

static __device__ __forceinline__ void ldsm_x2_t(uint32_t* r, uint32_t addr) {
    asm volatile("ldmatrix.sync.aligned.m8n8.x2.trans.shared.b16 {%0,%1}, [%2];"
                 : "=r"(r[0]), "=r"(r[1]) : "r"(addr));
}

static __device__ __forceinline__ float ex2f(float x) {
    float y;
    asm("ex2.approx.f32 %0, %1;" : "=f"(y) : "f"(x));
    return y;
}

static __device__ __forceinline__ uint32_t packh2(float a, float b) {
    __half2 h = __floats2half2_rn(a, b);
    return *reinterpret_cast<uint32_t*>(&h);
}

#define CPA16(dst, src) \
    asm volatile("cp.async.cg.shared.global [%0], [%1], 16;" :: "r"(dst), "l"(src))
#define CP_COMMIT() asm volatile("cp.async.commit_group;" ::: "memory")
#define CP_WAIT1() asm volatile("cp.async.wait_group 1;" ::: "memory")
#define CP_WAIT0() asm volatile("cp.async.wait_group 0;" ::: "memory")

// ---------------------------------------------------------------------------
// Fused prep (validated R16): rope table + all fp32->fp16 conversions
// ---------------------------------------------------------------------------
#define PREP_R0 512
#define PREP_R1 (PREP_R0 + 4096)
#define PREP_R2 (PREP_R1 + 4096)
#define PREP_R3 (PREP_R2 + 512)
#define PREP_R4 (PREP_R3 + 2048)   // total 11264 blocks

__global__ void prep_all(const float* __restrict__ x,
                         const float* __restrict__ Wq,
                         const float* __restrict__ Wk,
                         const float* __restrict__ Wv,
                         const float* __restrict__ Wo,
                         __half* __restrict__ Xh,
                         __half* __restrict__ Wqkv,
                         __half* __restrict__ Woh,
                         float2* __restrict__ rtab,
                         RopeTab rt)
{
    const int blk = blockIdx.x;
    const int tid = threadIdx.x;

    if (blk < PREP_R0) {
        int idx = blk * 256 + tid;
        int d = idx & 63;
        int pos = idx >> 6;
        float sn, cs;
        sincosf((float)pos * rt.v[d], &sn, &cs);
        rtab[idx] = make_float2(cs, sn);
    } else if (blk < PREP_R1) {
        int i = ((blk - PREP_R0) * 256 + tid) * 8;
        float4 a = *(const float4*)(x + i);
        float4 b = *(const float4*)(x + i + 4);
        uint4 o;
        o.x = packh2(a.x, a.y);
        o.y = packh2(a.z, a.w);
        o.z = packh2(b.x, b.y);
        o.w = packh2(b.z, b.w);
        *(uint4*)(Xh + i) = o;
    } else if (blk < PREP_R2) {
        int i = ((blk - PREP_R1) * 256 + tid) * 4;
        int r = i >> 11, c = i & 2047;
        float4 v = *(const float4*)(Wq + i);
        uint2 o;
        o.x = packh2(v.x, v.y);
        o.y = packh2(v.z, v.w);
        *(uint2*)(Wqkv + (size_t)r * NQKV + c) = o;
    } else if (blk < PREP_R3) {
        int i = ((blk - PREP_R2) * 256 + tid) * 4;
        int r = i >> 8, c = i & 255;
        float4 a = *(const float4*)(Wk + i);
        float4 b = *(const float4*)(Wv + i);
        uint2 oa, ob;
        oa.x = packh2(a.x, a.y);  oa.y = packh2(a.z, a.w);
        ob.x = packh2(b.x, b.y);  ob.y = packh2(b.z, b.w);
        *(uint2*)(Wqkv + (size_t)r * NQKV + Dd_ + c)  = oa;
        *(uint2*)(Wqkv + (size_t)r * NQKV + VOFF + c) = ob;
    } else {
        int i = ((blk - PREP_R3) * 256 + tid) * 8;
        float4 a = *(const float4*)(Wo + i);
        float4 b = *(const float4*)(Wo + i + 4);
        uint4 o;
        o.x = packh2(a.x, a.y);
        o.y = packh2(a.z, a.w);
        o.z = packh2(b.x, b.y);
        o.w = packh2(b.z, b.w);
        *(uint4*)(Woh + i) = o;
    }
}

// RoPE fp16 -> fp16 via table, strided in/out (K only)
__global__ void rope_h2h(const __half* __restrict__ in, __half* __restrict__ out,
                         const float2* __restrict__ tab,
                         int nh, int ld_in, int ld_out, int total)
{
    int idx = blockIdx.x * blockDim.x + threadIdx.x;
    if (idx >= total) return;
    int i    = idx & 63;
    int hh   = (idx >> 6) % nh;
    int srow = idx / (64 * nh);
    int pos  = srow & (Ss_ - 1);

    float2 cssn = tab[pos * 64 + i];

    size_t bi = (size_t)srow * ld_in + (size_t)hh * HD_ + i;
    size_t bo = (size_t)srow * ld_out + (size_t)hh * HD_ + i;
    float x1 = __half2float(in[bi]);
    float x2 = __half2float(in[bi + 64]);
    out[bo]      = __float2half(x1 * cssn.x - x2 * cssn.y);
    out[bo + 64] = __float2half(x2 * cssn.x + x1 * cssn.y);
}

// ---------------------------------------------------------------------------
// Single-pass fp16 GEMM, 128 threads / 4 warps, warp tile 64x64 (2m x 2n),
// acc 128 regs/thread. Halves per-warp smem fragment traffic vs 64x32.
// cp.async 2-stage. Same K order -> bitwise-identical output.
// ---------------------------------------------------------------------------
#define SA_STRIDE 72
#define SB_STRIDE 136
#define SA_SZ (128 * SA_STRIDE)
#define SB_SZ (64 * SB_STRIDE)
#define STG1_BYTES ((SA_SZ + SB_SZ) * 2)      // 35840
#define G1_SMEM (2 * STG1_BYTES)              // 71680

template <typename TO>
__global__ __launch_bounds__(128, 2) void gemm_f16x1(const __half* __restrict__ Ah,
                                                     const __half* __restrict__ Bh,
                                                     TO* __restrict__ C,
                                                     int M, int N, int K)
{
    extern __shared__ __half smh[];
    const uint32_t sbase = smem_u32(smh);

    const int t    = threadIdx.x;
    const int lane = t & 31;
    const int wid  = t >> 5;
    const int wm   = wid & 1;         // 0..1 -> 64-row half
    const int wn   = wid >> 1;        // 0..1 -> 64-col half
    const int n0   = blockIdx.x * 128;
    const int m0   = blockIdx.y * 128;

    float acc[4][8][4];
#pragma unroll
    for (int i = 0; i < 4; ++i)
#pragma unroll
        for (int j = 0; j < 8; ++j)
#pragma unroll
            for (int k = 0; k < 4; ++k) acc[i][j][k] = 0.0f;

    auto load_stage = [&](int c, int buf) {
        const int k0 = c << 6;
        const uint32_t sb = sbase + (uint32_t)buf * STG1_BYTES;
#pragma unroll
        for (int i = 0; i < 8; ++i) {                 // A: 1024 vec16
            int li = t + 128 * i;
            int row = li >> 3, v = li & 7;
            const size_t g = (size_t)(m0 + row) * K + k0 + v * 8;
            CPA16(sb + (uint32_t)(row * SA_STRIDE + v * 8) * 2, Ah + g);
        }
#pragma unroll
        for (int i = 0; i < 8; ++i) {                 // B: 1024 vec16
            int li = t + 128 * i;
            int row = li >> 4, v = li & 15;
            const size_t g = (size_t)(k0 + row) * N + n0 + v * 8;
            CPA16(sb + (uint32_t)(SA_SZ + row * SB_STRIDE + v * 8) * 2, Bh + g);
        }
    };

    const uint32_t a_rel =
        (uint32_t)(((lane & 7) + ((lane >> 3) & 1) * 8 + wm * 64) * (SA_STRIDE * 2)) +
        (uint32_t)(((lane >> 4) & 1) * 16);
    const uint32_t b_rel = (uint32_t)(SA_SZ * 2) +
        (uint32_t)(((lane & 7) + ((lane >> 3) & 1) * 8) * (SB_STRIDE * 2)) +
        (uint32_t)(wn * 128);                          // 64 cols = 128 bytes

    const int nch = K >> 6;
    load_stage(0, 0);
    CP_COMMIT();

    for (int c = 0; c < nch; ++c) {
        const int buf = c & 1;
        if (c + 1 < nch) {
            load_stage(c + 1, (c + 1) & 1);
            CP_COMMIT();
            CP_WAIT1();
        } else {
            CP_WAIT0();
        }
        __syncthreads();

        const uint32_t stg = sbase + (uint32_t)buf * STG1_BYTES;
        const uint32_t a_addr = stg + a_rel;
        const uint32_t b_addr = stg + b_rel;

#pragma unroll
        for (int k16 = 0; k16 < 4; ++k16) {
            uint32_t bh[8][2], af[4][4];
            const uint32_t bko = (uint32_t)(k16 * 16 * SB_STRIDE * 2);
#pragma unroll
            for (int nt = 0; nt < 8; ++nt)
                ldsm_x2_t(bh[nt], b_addr + nt * 16 + bko);
            const uint32_t ako = (uint32_t)(k16 * 32);
#pragma unroll
            for (int mt = 0; mt < 4; ++mt)
                ldsm_x4(af[mt], a_addr + mt * (16 * SA_STRIDE * 2) + ako);
#pragma unroll
            for (int mt = 0; mt < 4; ++mt)
#pragma unroll
                for (int nt = 0; nt < 8; ++nt)
                    mma16816h(acc[mt][nt], af[mt], bh[nt]);
        }
        __syncthreads();
    }

    const int g   = lane >> 2;
    const int tid = lane & 3;
#pragma unroll
    for (int mt = 0; mt < 4; ++mt) {
        const int row = m0 + wm * 64 + mt * 16 + g;
#pragma unroll
        for (int nt = 0; nt < 8; ++nt) {
            const int col = n0 + wn * 64 + nt * 8 + tid * 2;
            if (sizeof(TO) == 4) {
                *(float2*)((float*)C + (size_t)row * N + col) =
                    make_float2(acc[mt][nt][0], acc[mt][nt][1]);
                *(float2*)((float*)C + (size_t)(row + 8) * N + col) =
                    make_float2(acc[mt][nt][2], acc[mt][nt][3]);
            } else {
                *(uint32_t*)((__half*)C + (size_t)row * N + col) =
                    packh2(acc[mt][nt][0], acc[mt][nt][1]);
                *(uint32_t*)((__half*)C + (size_t)(row + 8) * N + col) =
                    packh2(acc[mt][nt][2], acc[mt][nt][3]);
            }
        }
    }
}

// ---------------------------------------------------------------------------
// Flash attention (validated R16, unchanged): table-rope fused Q load,
// cp.async double-buffered K/V, reversed qb order.
// ---------------------------------------------------------------------------
#define FA_BQ 128
#define FA_BK 64
#define FA_STR 136
#define FA_QS (FA_BQ * FA_STR)
#define FA_KV1 (FA_BK * FA_STR)
#define FA_STAGE (2 * FA_KV1)
#define FA_SMEM ((FA_QS + 2 * FA_STAGE) * 2)    // 104448 bytes

__global__ __launch_bounds__(256, 2) void flash_tc(const __half* __restrict__ Qsrc,
                                                   const __half* __restrict__ Kh,
                                                   const __half* __restrict__ Vsrc,
                                                   __half* __restrict__ Oh,
                                                   const float2* __restrict__ rtab,
                                                   float qmult)
{
    extern __shared__ __half sh[];
    __half* Qs = sh;

    const int qb = gridDim.x - 1 - blockIdx.x;   // long CTAs first
    const int h = blockIdx.y, b = blockIdx.z;
    const int kvh = h % HKV_;
    const int t = threadIdx.x, lane = t & 31, w = t >> 5;
    const int q0 = qb * FA_BQ;
    const int wq0 = w * 16;

    // Load Q tile from pre-rope QKV buffer, apply RoPE (table) + scale.
    {
#pragma unroll
        for (int i = 0; i < 8; ++i) {
            int linear = t + 256 * i;
            int row = linear >> 4;
            int c8 = (linear & 15) * 8;
            const __half* base = Qsrc + (size_t)(b * Ss_ + q0 + row) * NQKV + h * HD_;
            uint4 own = *(const uint4*)(base + c8);
            uint4 par = *(const uint4*)(base + (c8 ^ 64));
            const __half2* o2 = (const __half2*)&own;
            const __half2* p2 = (const __half2*)&par;
            float sgn = (c8 < 64) ? -1.0f : 1.0f;
            int pos = q0 + row;
            const float2* tr = rtab + pos * 64 + (c8 & 63);
            uint4 res;
            uint32_t* r32 = (uint32_t*)&res;
#pragma unroll
            for (int e = 0; e < 4; ++e) {
                float2 f0 = tr[2 * e];
                float2 f1 = tr[2 * e + 1];
                float xa = __half2float(o2[e].x), xb = __half2float(o2[e].y);
                float ya = __half2float(p2[e].x), yb = __half2float(p2[e].y);
                r32[e] = packh2((xa * f0.x + sgn * ya * f0.y) * qmult,
                                (xb * f1.x + sgn * yb * f1.y) * qmult);
            }
            *(uint4*)&Qs[row * FA_STR + c8] = res;
        }
    }

    float oacc[16][4];
#pragma unroll
    for (int i = 0; i < 16; ++i)
#pragma unroll
        for (int j = 0; j < 4; ++j) oacc[i][j] = 0.0f;
    float mrow[2] = {-INFINITY, -INFINITY};
    float lrow[2] = {0.0f, 0.0f};

    const uint32_t sbase = smem_u32(sh);
    const uint32_t qa = sbase +
        (uint32_t)((wq0 + (lane & 15)) * (FA_STR * 2)) +
        (uint32_t)(((lane >> 4) & 1) * 16);
    const uint32_t k_rel =
        (uint32_t)(((lane & 7) + ((lane >> 4) & 1) * 8) * (FA_STR * 2)) +
        (uint32_t)(((lane >> 3) & 1) * 16);
    const uint32_t v_rel = (uint32_t)(FA_KV1 * 2) +
        (uint32_t)(((lane & 7) + ((lane >> 3) & 1) * 8) * (FA_STR * 2)) +
        (uint32_t)(((lane >> 4) & 1) * 16);

    auto load_kv = [&](int kb, int buf) {
        const int k0 = kb * FA_BK;
        const uint32_t sb = sbase + (uint32_t)(FA_QS + buf * FA_STAGE) * 2;
#pragma unroll
        for (int i = 0; i < 4; ++i) {
            int linear = t + 256 * i;
            int row = linear >> 4;
            int c8 = (linear & 15) * 8;
            uint32_t s = sb + (uint32_t)(row * FA_STR + c8) * 2;
            CPA16(s, Kh + (size_t)(b * Ss_ + k0 + row) * NKV + kvh * HD_ + c8);
            CPA16(s + FA_KV1 * 2,
                  Vsrc + (size_t)(b * Ss_ + k0 + row) * NQKV + kvh * HD_ + c8);
        }
    };

    const int nkb = (q0 + FA_BQ) / FA_BK;
    load_kv(0, 0);
    CP_COMMIT();

    for (int kb = 0; kb < nkb; ++kb) {
        const int buf = kb & 1;
        const int k0 = kb * FA_BK;
        if (kb + 1 < nkb) {
            load_kv(kb + 1, buf ^ 1);
            CP_COMMIT();
            CP_WAIT1();
        } else {
            CP_WAIT0();
        }
        __syncthreads();

        const uint32_t stg = sbase + (uint32_t)(FA_QS + buf * FA_STAGE) * 2;
        const uint32_t ka = stg + k_rel;
        const uint32_t va = stg + v_rel;

        if (k0 <= q0 + wq0 + 15) {
            float sacc[8][4];
#pragma unroll
            for (int i = 0; i < 8; ++i)
#pragma unroll
                for (int j = 0; j < 4; ++j) sacc[i][j] = 0.0f;

#pragma unroll
            for (int kk = 0; kk < 8; ++kk) {
                uint32_t af[4];
                ldsm_x4(af, qa + kk * 32);
#pragma unroll
                for (int np = 0; np < 4; ++np) {
                    uint32_t bf[4];
                    ldsm_x4(bf, ka + np * 16 * (FA_STR * 2) + kk * 32);
                    mma16816h(sacc[np * 2],     af, bf);
                    mma16816h(sacc[np * 2 + 1], af, bf + 2);
                }
            }

            if (k0 + FA_BK - 1 > q0 + wq0) {
                const int rbase = q0 + wq0 + (lane >> 2);
                const int cbase = k0 + (lane & 3) * 2;
#pragma unroll
                for (int nt = 0; nt < 8; ++nt)
#pragma unroll
                    for (int e = 0; e < 4; ++e) {
                        int col = cbase + nt * 8 + (e & 1);
                        int row = rbase + (e >> 1) * 8;
                        if (col > row) sacc[nt][e] = -INFINITY;
                    }
            }

#pragma unroll
            for (int r = 0; r < 2; ++r) {
                float mx = -INFINITY;
#pragma unroll
                for (int nt = 0; nt < 8; ++nt)
                    mx = fmaxf(mx, fmaxf(sacc[nt][2 * r], sacc[nt][2 * r + 1]));
                mx = fmaxf(mx, __shfl_xor_sync(0xffffffffu, mx, 1));
                mx = fmaxf(mx, __shfl_xor_sync(0xffffffffu, mx, 2));
                float mn = fmaxf(mrow[r], mx);
                float al = ex2f(mrow[r] - mn);
                mrow[r] = mn;
                float rs = 0.0f;
#pragma unroll
                for (int nt = 0; nt < 8; ++nt) {
                    float p0 = ex2f(sacc[nt][2 * r] - mn);
                    float p1 = ex2f(sacc[nt][2 * r + 1] - mn);
                    sacc[nt][2 * r] = p0;
                    sacc[nt][2 * r + 1] = p1;
                    rs += p0 + p1;
                }
                rs += __shfl_xor_sync(0xffffffffu, rs, 1);
                rs += __shfl_xor_sync(0xffffffffu, rs, 2);
                lrow[r] = lrow[r] * al + rs;
#pragma unroll
                for (int nt = 0; nt < 16; ++nt) {
                    oacc[nt][2 * r]     *= al;
                    oacc[nt][2 * r + 1] *= al;
                }
            }

#pragma unroll
            for (int j = 0; j < 4; ++j) {
                uint32_t a[4];
                a[0] = packh2(sacc[2 * j][0],     sacc[2 * j][1]);
                a[1] = packh2(sacc[2 * j][2],     sacc[2 * j][3]);
                a[2] = packh2(sacc[2 * j + 1][0], sacc[2 * j + 1][1]);
                a[3] = packh2(sacc[2 * j + 1][2], sacc[2 * j + 1][3]);
#pragma unroll
                for (int dp = 0; dp < 8; ++dp) {
                    uint32_t bf[4];
                    ldsm_x4_t(bf, va + j * 16 * (FA_STR * 2) + dp * 32);
                    mma16816h(oacc[dp * 2],     a, bf);
                    mma16816h(oacc[dp * 2 + 1], a, bf + 2);
                }
            }
        }
        __syncthreads();
    }

#pragma unroll
    for (int r = 0; r < 2; ++r) {
        float inv = 1.0f / lrow[r];
        int row = q0 + wq0 + (lane >> 2) + r * 8;
        __half* Og = Oh + (size_t)(b * Ss_ + row) * Dd_ + h * HD_;
#pragma unroll
        for (int nt = 0; nt < 16; ++nt) {
            int col = nt * 8 + (lane & 3) * 2;
            *(uint32_t*)(Og + col) =
                packh2(oacc[nt][2 * r] * inv, oacc[nt][2 * r + 1] * inv);
        }
    }
}

// ---------------------------------------------------------------------------
// Launch
// ---------------------------------------------------------------------------
extern "C" void kernel_launch(void* const* d_in, const int* in_sizes, int n_in,
                              void* d_out, int out_size)
{
    const float* x  = (const float*)d_in[0];
    const float* Wq = (const float*)d_in[2];
    const float* Wk = (const float*)d_in[3];
    const float* Wv = (const float*)d_in[4];
    const float* Wo = (const float*)d_in[5];
    float* out = (float*)d_out;

    __half *Xhp, *Wqkvp, *QKVp, *Khp, *Ohp, *Wohp;
    float2* rtabp;
    cudaGetSymbolAddress((void**)&Xhp, g_Xh);
    cudaGetSymbolAddress((void**)&Wqkvp, g_Wqkv);
    cudaGetSymbolAddress((void**)&QKVp, g_QKV);
    cudaGetSymbolAddress((void**)&Khp, g_Kh);
    cudaGetSymbolAddress((void**)&Ohp, g_Oh);
    cudaGetSymbolAddress((void**)&Wohp, g_Woh);
    cudaGetSymbolAddress((void**)&rtabp, g_rope);

    cudaFuncSetAttribute(gemm_f16x1<__half>,
                         cudaFuncAttributeMaxDynamicSharedMemorySize, G1_SMEM);
    cudaFuncSetAttribute(gemm_f16x1<float>,
                         cudaFuncAttributeMaxDynamicSharedMemorySize, G1_SMEM);
    cudaFuncSetAttribute(flash_tc,
                         cudaFuncAttributeMaxDynamicSharedMemorySize, FA_SMEM);

    // Host-accurate inv_freq table (double precision)
    RopeTab rt;
    for (int i = 0; i < 64; ++i)
        rt.v[i] = (float)exp(-(double)i * (log(10000.0) / 64.0));
    const float qmult = 1.4426950408889634f / sqrtf((float)HD_);

    // ONE fused prep kernel: rope table + all fp32->fp16 conversions
    prep_all<<<PREP_R4, 256>>>(x, Wq, Wk, Wv, Wo, Xhp, Wqkvp, Wohp, rtabp, rt);

    // QKV = x @ [Wq|Wk|Wv]  (single-pass fp16, fp16 out, 128-thread CTAs)
    gemm_f16x1<__half><<<dim3(NQKV / 128, MROWS / 128), 128, G1_SMEM>>>(
        Xhp, Wqkvp, QKVp, MROWS, NQKV, Dd_);

    // K RoPE via table; Q rope fused into flash; V in-place from QKV
    {
        int totk = MROWS * HKV_ * 64;
        rope_h2h<<<(totk + 255) / 256, 256>>>(QKVp + Dd_, Khp, rtabp,
                                              HKV_, NQKV, NKV, totk);
    }

    // Flash attention (Q pre-rope from QKV buffer; table rope in Q load)
    flash_tc<<<dim3(Ss_ / FA_BQ, Hh_, Bb_), 256, FA_SMEM>>>(
        QKVp, Khp, QKVp + VOFF, Ohp, rtabp, qmult);

    // out = O @ Wo (single-pass fp16, fp32 out, 128-thread CTAs)
    gemm_f16x1<float><<<dim3(Dd_ / 128, MROWS / 128), 128, G1_SMEM>>>(
        Ohp, Wohp, out, MROWS, Dd_, Dd_);
}